// round 7
// baseline (speedup 1.0000x reference)
#include <cuda_runtime.h>
#include <cuda_bf16.h>
#include <math.h>
#include <stdio.h>

// ---------------- problem constants ----------------
#define Bq   4
#define Sq   512
#define Nq   256
#define Eq   42
#define Pq   256
#define Kq   3
#define Lq   4
#define HBq  768
#define DTq  20
#define DIq  20
#define Gq   256
#define NLq  2
#define Rq   97
#define NHq  4
#define D0q  808          // HB+DT+DI
#define BANKq 1576        // D0 + G*(NL+1)
#define BANK4q 6304       // 4*BANK
#define BANK5q 7880       // 5*BANK
#define DHq  394          // BANK/NH
#define Mlstm (Bq*Pq*Kq)        // 3072
#define MlstmT (Mlstm*Lq)       // 12288
#define BPq  (Bq*Pq)            // 1024

typedef __nv_bfloat16 bf16;
typedef __nv_bfloat162 bf162;

// ---------------- scratch (static device memory; no allocations allowed) ----------------
__device__ float g_enc   [Bq*Sq*D0q];
__device__ float g_feats [Bq*Nq*BANKq];
__device__ float g_tmp   [Bq*Nq*D0q];
__device__ float g_x1    [Bq*Nq*Gq];
__device__ float g_xq    [Bq*Nq*Gq];
__device__ float g_xk    [Bq*Nq*Gq];
__device__ float g_xv    [Bq*Nq*Gq];
__device__ float g_att   [Bq*Nq*Nq];
__device__ float g_ih    [(size_t)MlstmT*BANK4q];
__device__ float g_hh    [(size_t)Mlstm*BANK4q];
__device__ float g_c     [Mlstm*BANKq];
__device__ float g_hs1   [MlstmT*BANKq];
__device__ float g_hf    [BPq*BANKq];
__device__ float g_tf    [BPq*BANKq];
__device__ float g_q     [BPq*BANKq];
__device__ float g_k     [Mlstm*BANKq];
__device__ float g_v     [Mlstm*BANKq];
__device__ float g_pinfo [BPq*BANKq];
__device__ int   g_validany[BPq];
__device__ float g_hid   [BPq*BANK5q];

// bf16 split scratch
__device__ bf16 g_ah  [(size_t)MlstmT*BANKq];
__device__ bf16 g_al  [(size_t)MlstmT*BANKq];
__device__ bf16 g_sh  [(size_t)Mlstm*BANKq];
__device__ bf16 g_sl  [(size_t)Mlstm*BANKq];
__device__ bf16 g_w1h [(size_t)BANK4q*BANKq];
__device__ bf16 g_w1l [(size_t)BANK4q*BANKq];
__device__ bf16 g_w2h [(size_t)BANK4q*BANKq];
__device__ bf16 g_w2l [(size_t)BANK4q*BANKq];
__device__ bf16 g_wph [(size_t)BANK5q*BANK5q];
__device__ bf16 g_wpl [(size_t)BANK5q*BANK5q];

// ================= fp32 tiled GEMMs (for small GCN ops) =================
// 32x32-tile variant: 4x more CTAs than 64-tile -> latency hiding for tiny ops
template <bool TRANSB>
__global__ void __launch_bounds__(256)
gemm32_kernel(const float* __restrict__ A, const float* __restrict__ B,
              const float* __restrict__ bias, const float* __restrict__ resid,
              float* __restrict__ C,
              int M, int N, int K,
              int lda, int ldb, int ldc, int ldr,
              long sA, long sB, long sC, long sR,
              float alpha, int act)
{
    int bz = blockIdx.z;
    A += bz * sA; B += bz * sB; C += bz * sC;
    if (resid) resid += bz * sR;

    int row0 = blockIdx.y * 32;
    int col0 = blockIdx.x * 32;

    __shared__ float As[32][33];
    __shared__ float Bs[32][33];

    int tid = threadIdx.x;
    int tx = tid & 15, ty = tid >> 4;

    float acc[2][2] = {{0.f, 0.f}, {0.f, 0.f}};

    for (int k0 = 0; k0 < K; k0 += 32) {
#pragma unroll
        for (int l = 0; l < 4; l++) {
            int idx = tid + l * 256;
            int m = idx >> 5, kk = idx & 31;
            int gr = row0 + m, gk = k0 + kk;
            As[kk][m] = (gr < M && gk < K) ? A[(long)gr * lda + gk] : 0.f;
        }
#pragma unroll
        for (int l = 0; l < 4; l++) {
            int idx = tid + l * 256;
            if (TRANSB) {
                int n = idx >> 5, kk = idx & 31;
                int gn = col0 + n, gk = k0 + kk;
                Bs[kk][n] = (gn < N && gk < K) ? B[(long)gn * ldb + gk] : 0.f;
            } else {
                int kk = idx >> 5, n = idx & 31;
                int gn = col0 + n, gk = k0 + kk;
                Bs[kk][n] = (gn < N && gk < K) ? B[(long)gk * ldb + gn] : 0.f;
            }
        }
        __syncthreads();
#pragma unroll
        for (int kk = 0; kk < 32; kk++) {
            float a0 = As[kk][ty], a1 = As[kk][ty + 16];
            float b0 = Bs[kk][tx], b1 = Bs[kk][tx + 16];
            acc[0][0] = fmaf(a0, b0, acc[0][0]);
            acc[0][1] = fmaf(a0, b1, acc[0][1]);
            acc[1][0] = fmaf(a1, b0, acc[1][0]);
            acc[1][1] = fmaf(a1, b1, acc[1][1]);
        }
        __syncthreads();
    }

#pragma unroll
    for (int i = 0; i < 2; i++) {
        int r = row0 + ty + 16 * i;
        if (r >= M) continue;
#pragma unroll
        for (int j = 0; j < 2; j++) {
            int cc = col0 + tx + 16 * j;
            if (cc >= N) continue;
            float v = acc[i][j] * alpha;
            if (bias) v += bias[cc];
            if (act == 1) v = fmaxf(v, 0.f);
            if (resid) v += resid[(long)r * ldr + cc];
            C[(long)r * ldc + cc] = v;
        }
    }
}

static void gemm(bool transB,
                 const float* A, const float* B, const float* bias, const float* resid, float* C,
                 int M, int N, int K, int lda, int ldb, int ldc, int ldr,
                 long sA, long sB, long sC, long sR, int batch, float alpha, int act)
{
    dim3 grid((N + 31) / 32, (M + 31) / 32, batch);
    if (transB)
        gemm32_kernel<true><<<grid, 256>>>(A, B, bias, resid, C, M, N, K, lda, ldb, ldc, ldr, sA, sB, sC, sR, alpha, act);
    else
        gemm32_kernel<false><<<grid, 256>>>(A, B, bias, resid, C, M, N, K, lda, ldb, ldc, ldr, sA, sB, sC, sR, alpha, act);
}

// ================= bf16 split-precision tensor-core GEMM (pipelined, RAW-free) =================
// C(MxN) = A(MxK) @ B(NxK)^T + bias, A = Ah+Al, B = Bh+Bl.
// acc += Ah*Bh + Ah*Bl + Al*Bh  — issued as 3 passes of 16 independent MMAs so the
// same accumulator is only re-touched every 16 HMMAs (covers HMMA latency).
// Single __syncthreads per K-chunk: at iter kt we prefetch chunk kt+GSTG-1 into the
// stage consumed at iter kt-1 (freed by this iteration's sync); always-commit keeps
// exactly GSTG groups outstanding so wait_group(GSTG-1) uniformly means "chunk kt done".
#define LDSB 40                    // padded row stride in bf16 (80B -> conflict-free ldmatrix)
#define GSTG 4                     // pipeline stages
#define PLANE_E (128*LDSB)         // elems per plane
#define PLANE_B (PLANE_E*2)        // bytes per plane (10240)
#define STAGE_B (4*PLANE_B)        // bytes per stage  (40960)

#define MMA_BF16(d, a, b) asm volatile( \
    "mma.sync.aligned.m16n8k16.row.col.f32.bf16.bf16.f32 " \
    "{%0,%1,%2,%3}, {%4,%5,%6,%7}, {%8,%9}, {%0,%1,%2,%3};" \
    : "+f"((d)[0]), "+f"((d)[1]), "+f"((d)[2]), "+f"((d)[3]) \
    : "r"((a)[0]), "r"((a)[1]), "r"((a)[2]), "r"((a)[3]), "r"((b)[0]), "r"((b)[1]))

#define LDSM4(r, addr) asm volatile( \
    "ldmatrix.sync.aligned.m8n8.x4.shared.b16 {%0,%1,%2,%3}, [%4];" \
    : "=r"((r)[0]), "=r"((r)[1]), "=r"((r)[2]), "=r"((r)[3]) : "r"(addr))

__device__ __forceinline__ void cpasync16(unsigned saddr, const void* g, int srcbytes)
{
    asm volatile("cp.async.cg.shared.global [%0], [%1], 16, %2;\n"
                 :: "r"(saddr), "l"(g), "r"(srcbytes));
}

__device__ __forceinline__ void gbf_prefetch(
    const bf16* __restrict__ Ah, const bf16* __restrict__ Al,
    const bf16* __restrict__ Bh, const bf16* __restrict__ Bl,
    long row0, long col0, int M, int N, int K,
    int kt, int T, unsigned sbase, int stg, int tid)
{
    if (kt >= T) return;
    long k0 = (long)kt * 32;
    unsigned sst = sbase + (unsigned)stg * STAGE_B;
#pragma unroll
    for (int i = 0; i < 2; i++) {
        int c = tid + i * 256;          // 512 chunks of 16B per plane
        int r = c >> 2;
        int ko = (c & 3) * 8;
        long gk = k0 + ko;
        bool kok = gk < K;
        long gkc = kok ? gk : 0;
        unsigned soff = (unsigned)((r * LDSB + ko) * 2);
        {
            long gr = row0 + r;
            bool ok = kok && (gr < M);
            long grc = ok ? gr : 0;
            int nb = ok ? 16 : 0;
            cpasync16(sst + soff,            Ah + grc * K + gkc, nb);
            cpasync16(sst + PLANE_B + soff,  Al + grc * K + gkc, nb);
        }
        {
            long gn = col0 + r;
            bool ok = kok && (gn < N);
            long gnc = ok ? gn : 0;
            int nb = ok ? 16 : 0;
            cpasync16(sst + 2 * PLANE_B + soff, Bh + gnc * K + gkc, nb);
            cpasync16(sst + 3 * PLANE_B + soff, Bl + gnc * K + gkc, nb);
        }
    }
}

__global__ void __launch_bounds__(256)
gemm_bf16_kernel(const bf16* __restrict__ Ah, const bf16* __restrict__ Al,
                 const bf16* __restrict__ Bh, const bf16* __restrict__ Bl,
                 const float* __restrict__ bias, float* __restrict__ C,
                 int M, int N, int K, int act)
{
    extern __shared__ __align__(16) bf16 dsm[];
    unsigned sbase = (unsigned)__cvta_generic_to_shared(dsm);

    int tid = threadIdx.x;
    int warp = tid >> 5, lane = tid & 31;
    int wm = (warp & 1) * 64;
    int wn = (warp >> 1) * 32;
    long row0 = (long)blockIdx.y * 128;
    long col0 = (long)blockIdx.x * 128;

    float acc[4][4][4];
#pragma unroll
    for (int a = 0; a < 4; a++)
#pragma unroll
        for (int b = 0; b < 4; b++)
#pragma unroll
            for (int c = 0; c < 4; c++) acc[a][b][c] = 0.f;

    int am_r = (lane & 7) + ((lane >> 3) & 1) * 8;
    int a_c8 = ((lane >> 4) & 1) * 8;
    int b_r  = (lane & 7) + ((lane >> 4) & 1) * 8;
    int b_c8 = ((lane >> 3) & 1) * 8;

    int T = (K + 31) / 32;

    // prologue: chunks 0..GSTG-2 -> stages 0..GSTG-2 (GSTG-1 groups outstanding)
#pragma unroll
    for (int kt = 0; kt < GSTG - 1; kt++) {
        gbf_prefetch(Ah, Al, Bh, Bl, row0, col0, M, N, K, kt, T, sbase, kt, tid);
        asm volatile("cp.async.commit_group;\n");
    }

    for (int kt = 0; kt < T; kt++) {
        __syncthreads();   // all warps finished consuming stage (kt-1)%GSTG
        // prefetch chunk kt+GSTG-1 into stage (kt+GSTG-1)%GSTG == (kt-1)%GSTG
        gbf_prefetch(Ah, Al, Bh, Bl, row0, col0, M, N, K, kt + GSTG - 1, T,
                     sbase, (kt + GSTG - 1) % GSTG, tid);
        asm volatile("cp.async.commit_group;\n");   // always commit (may be empty)
        asm volatile("cp.async.wait_group %0;\n" :: "n"(GSTG - 1));  // chunk kt ready

        int stg = kt % GSTG;
        unsigned sst = sbase + (unsigned)stg * STAGE_B;
        unsigned aB = sst;
        unsigned bB = sst + 2 * PLANE_B;

#pragma unroll
        for (int ks = 0; ks < 2; ks++) {
            int kb = ks * 16;
            unsigned bh[2][4], bl[2][4];
#pragma unroll
            for (int pp = 0; pp < 2; pp++) {
                unsigned addr = bB + (unsigned)(((wn + pp * 16 + b_r) * LDSB + kb + b_c8) * 2);
                LDSM4(bh[pp], addr);
                LDSM4(bl[pp], addr + PLANE_B);
            }
            unsigned ahf[4][4], alf[4][4];
#pragma unroll
            for (int mi = 0; mi < 4; mi++) {
                unsigned addr = aB + (unsigned)(((wm + mi * 16 + am_r) * LDSB + kb + a_c8) * 2);
                LDSM4(ahf[mi], addr);
                LDSM4(alf[mi], addr + PLANE_B);
            }
            // pass 1: ah*bh — 16 independent MMAs
#pragma unroll
            for (int mi = 0; mi < 4; mi++)
#pragma unroll
                for (int ni = 0; ni < 4; ni++)
                    MMA_BF16(acc[mi][ni], ahf[mi], (&bh[ni >> 1][(ni & 1) * 2]));
            // pass 2: ah*bl
#pragma unroll
            for (int mi = 0; mi < 4; mi++)
#pragma unroll
                for (int ni = 0; ni < 4; ni++)
                    MMA_BF16(acc[mi][ni], ahf[mi], (&bl[ni >> 1][(ni & 1) * 2]));
            // pass 3: al*bh
#pragma unroll
            for (int mi = 0; mi < 4; mi++)
#pragma unroll
                for (int ni = 0; ni < 4; ni++)
                    MMA_BF16(acc[mi][ni], alf[mi], (&bh[ni >> 1][(ni & 1) * 2]));
        }
    }

    // ---- epilogue ----
#pragma unroll
    for (int mi = 0; mi < 4; mi++) {
#pragma unroll
        for (int ni = 0; ni < 4; ni++) {
            long r = row0 + wm + mi * 16 + (lane >> 2);
            long c = col0 + wn + ni * 8 + (lane & 3) * 2;
#pragma unroll
            for (int half = 0; half < 2; half++) {
                long rr = r + half * 8;
                if (rr >= M) continue;
#pragma unroll
                for (int e = 0; e < 2; e++) {
                    long cc = c + e;
                    if (cc >= N) continue;
                    float v = acc[mi][ni][half * 2 + e];
                    if (bias) v += bias[cc];
                    if (act == 1) v = fmaxf(v, 0.f);
                    C[(size_t)rr * N + cc] = v;
                }
            }
        }
    }
}

static void gemm_bf16(const bf16* Ah, const bf16* Al, const bf16* Bh, const bf16* Bl,
                      const float* bias, float* C, int M, int N, int K, int act)
{
    static int attr_done = 0;
    if (!attr_done) {
        cudaFuncSetAttribute(gemm_bf16_kernel,
                             cudaFuncAttributeMaxDynamicSharedMemorySize, GSTG * STAGE_B);
        attr_done = 1;
    }
    dim3 grid((N + 127) / 128, (M + 127) / 128);
    gemm_bf16_kernel<<<grid, 256, GSTG * STAGE_B>>>(Ah, Al, Bh, Bl, bias, C, M, N, K, act);
}

// ================= conversion kernels =================
__device__ __forceinline__ void split1(float f, bf16& h, bf16& l)
{
    h = __float2bfloat16(f);
    l = __float2bfloat16(f - __bfloat162float(h));
}

__global__ void split_kernel(const float* __restrict__ x, bf16* __restrict__ hi,
                             bf16* __restrict__ lo, size_t n4)
{
    size_t i = (size_t)blockIdx.x * blockDim.x + threadIdx.x;
    if (i >= n4) return;
    float4 f = ((const float4*)x)[i];
    bf16 h0, l0, h1, l1, h2, l2, h3, l3;
    split1(f.x, h0, l0); split1(f.y, h1, l1); split1(f.z, h2, l2); split1(f.w, h3, l3);
    bf162 vh0; vh0.x = h0; vh0.y = h1;
    bf162 vh1; vh1.x = h2; vh1.y = h3;
    bf162 vl0; vl0.x = l0; vl0.y = l1;
    bf162 vl1; vl1.x = l2; vl1.y = l3;
    ((bf162*)hi)[i * 2] = vh0; ((bf162*)hi)[i * 2 + 1] = vh1;
    ((bf162*)lo)[i * 2] = vl0; ((bf162*)lo)[i * 2 + 1] = vl1;
}

static void split(const float* x, bf16* hi, bf16* lo, size_t n)
{
    size_t n4 = n / 4;
    split_kernel<<<(unsigned)((n4 + 255) / 256), 256>>>(x, hi, lo, n4);
}

__global__ void transpose_split_kernel(const float* __restrict__ B, bf16* __restrict__ Th,
                                       bf16* __restrict__ Tl, int K, int N)
{
    __shared__ float tile[32][33];
    int k0 = blockIdx.y * 32, n0 = blockIdx.x * 32;
    int tx = threadIdx.x, ty = threadIdx.y;  // 32 x 8
#pragma unroll
    for (int i = 0; i < 32; i += 8) {
        int k = k0 + ty + i, n = n0 + tx;
        tile[ty + i][tx] = (k < K && n < N) ? B[(size_t)k * N + n] : 0.f;
    }
    __syncthreads();
#pragma unroll
    for (int i = 0; i < 32; i += 8) {
        int n = n0 + ty + i, k = k0 + tx;
        if (n < N && k < K) {
            float f = tile[tx][ty + i];
            bf16 h, l; split1(f, h, l);
            Th[(size_t)n * K + k] = h;
            Tl[(size_t)n * K + k] = l;
        }
    }
}

// ---------------- fast activations (ex2/rcp fast paths, err ~1e-6) ----------------
__device__ __forceinline__ float fsig(float x)
{
    return __fdividef(1.f, 1.f + __expf(-x));
}
__device__ __forceinline__ float ftanh(float x)
{
    x = fminf(fmaxf(x, -15.f), 15.f);
    float e = __expf(-2.f * x);
    return __fdividef(1.f - e, 1.f + e);
}

// ---------------- small custom kernels ----------------
__global__ void build_enc_kernel(const float* __restrict__ eo, const int* __restrict__ etype,
                                 const int* __restrict__ eid, const float* __restrict__ temb,
                                 const float* __restrict__ iemb, float* __restrict__ enc)
{
    int bs = blockIdx.x;
    const float* src = eo + (long)bs * HBq;
    float* dst = enc + (long)bs * D0q;
    int ty = etype[bs], idv = eid[bs];
    for (int j = threadIdx.x; j < D0q; j += blockDim.x) {
        float v;
        if (j < HBq)            v = src[j];
        else if (j < HBq + DTq) v = temb[ty * DTq + (j - HBq)];
        else                    v = iemb[idv * DIq + (j - HBq - DTq)];
        dst[j] = v;
    }
}

__global__ void softmax256_kernel(float* __restrict__ x)
{
    int row = blockIdx.x;
    int tid = threadIdx.x;
    float v = x[(long)row * 256 + tid];
    __shared__ float red[8];
    int lane = tid & 31, warp = tid >> 5;
    float m = v;
#pragma unroll
    for (int o = 16; o > 0; o >>= 1) m = fmaxf(m, __shfl_xor_sync(0xffffffffu, m, o));
    if (lane == 0) red[warp] = m;
    __syncthreads();
    if (tid == 0) {
        float mm = red[0];
        for (int w = 1; w < 8; w++) mm = fmaxf(mm, red[w]);
        red[0] = mm;
    }
    __syncthreads();
    float mx = red[0];
    float e = expf(v - mx);
    float s = e;
#pragma unroll
    for (int o = 16; o > 0; o >>= 1) s += __shfl_xor_sync(0xffffffffu, s, o);
    __shared__ float red2[8];
    if (lane == 0) red2[warp] = s;
    __syncthreads();
    if (tid == 0) {
        float ss = 0.f;
        for (int w = 0; w < 8; w++) ss += red2[w];
        red2[0] = ss;
    }
    __syncthreads();
    x[(long)row * 256 + tid] = e / red2[0];
}

__global__ void gather_pf_split_kernel(const float* __restrict__ feats, const int* __restrict__ nodes,
                                       bf16* __restrict__ hi, bf16* __restrict__ lo)
{
    int row = blockIdx.x;                 // 0..12287
    int b = row / (Pq * Kq * Lq);
    int node = nodes[row];
    const float* src = feats + ((size_t)b * Nq + node) * BANKq;
    size_t base = (size_t)row * BANKq;
    for (int j = threadIdx.x; j < BANKq; j += blockDim.x) {
        bf16 h, l; split1(src[j], h, l);
        hi[base + j] = h;
        lo[base + j] = l;
    }
}

__global__ void lstm_cell_kernel(const float* __restrict__ ih, const float* __restrict__ hh,
                                 bf16* __restrict__ h_hi, bf16* __restrict__ h_lo,
                                 bf16* __restrict__ seq_hi, bf16* __restrict__ seq_lo,
                                 float* __restrict__ c, float* __restrict__ hs, int t)
{
    int i = blockIdx.y;
    int j = blockIdx.x * blockDim.x + threadIdx.x;
    if (j >= BANKq) return;
    const float* g = ih + ((size_t)i * Lq + t) * BANK4q;
    float gi = g[j], gf = g[BANKq + j], gg = g[2 * BANKq + j], go = g[3 * BANKq + j];
    float cp = 0.f;
    if (t > 0) {
        const float* hr = hh + (size_t)i * BANK4q;
        gi += hr[j]; gf += hr[BANKq + j]; gg += hr[2 * BANKq + j]; go += hr[3 * BANKq + j];
        cp = c[(size_t)i * BANKq + j];
    }
    float cn = fsig(gf) * cp + fsig(gi) * ftanh(gg);
    float hn = fsig(go) * ftanh(cn);
    c[(size_t)i * BANKq + j] = cn;
    bf16 h, l; split1(hn, h, l);
    h_hi[(size_t)i * BANKq + j] = h;
    h_lo[(size_t)i * BANKq + j] = l;
    if (seq_hi) {
        seq_hi[((size_t)i * Lq + t) * BANKq + j] = h;
        seq_lo[((size_t)i * Lq + t) * BANKq + j] = l;
    }
    if (hs) hs[((size_t)i * Lq + t) * BANKq + j] = hn;
}

__global__ void maxpool_split_kernel(const float* __restrict__ hs, const int* __restrict__ lens,
                                     bf16* __restrict__ hi, bf16* __restrict__ lo)
{
    int i = blockIdx.y;
    int j = blockIdx.x * blockDim.x + threadIdx.x;
    if (j >= BANKq) return;
    int len = lens[i];
    float m = -1e9f;
    const float* base = hs + (size_t)i * Lq * BANKq + j;
    for (int t = 0; t < Lq; t++)
        if (t < len) m = fmaxf(m, base[(size_t)t * BANKq]);
    float r = (len > 0) ? m : 0.f;
    bf16 h, l; split1(r, h, l);
    hi[(size_t)i * BANKq + j] = h;
    lo[(size_t)i * BANKq + j] = l;
}

__global__ void gather_ht_kernel(const float* __restrict__ feats, const int* __restrict__ htp,
                                 float* __restrict__ hf, float* __restrict__ tf,
                                 bf16* __restrict__ qh, bf16* __restrict__ ql)
{
    int bp = blockIdx.x;
    int b = bp / Pq;
    int h0 = htp[bp * 2 + 0], t0 = htp[bp * 2 + 1];
    h0 = (h0 == 0) ? 0 : h0 - 1;
    t0 = (t0 == 0) ? 0 : t0 - 1;
    const float* hsrc = feats + ((size_t)b * Nq + (Nq - Eq) + h0) * BANKq;
    const float* tsrc = feats + ((size_t)b * Nq + (Nq - Eq) + t0) * BANKq;
    for (int j = threadIdx.x; j < BANKq; j += blockDim.x) {
        float hv = hsrc[j], tv = tsrc[j];
        hf[(size_t)bp * BANKq + j] = hv;
        tf[(size_t)bp * BANKq + j] = tv;
        bf16 h, l; split1(hv - tv, h, l);
        qh[(size_t)bp * BANKq + j] = h;
        ql[(size_t)bp * BANKq + j] = l;
    }
}

__global__ void mha_attn_kernel(const float* __restrict__ q, const float* __restrict__ k,
                                const float* __restrict__ v, const int* __restrict__ plens,
                                const float* __restrict__ rmask,
                                bf16* __restrict__ ctx_hi, bf16* __restrict__ ctx_lo,
                                int* __restrict__ validany)
{
    int bp = blockIdx.x;
    int tid = threadIdx.x;
    int warp = tid >> 5, lane = tid & 31;
    __shared__ float sc[NHq][Kq];
    __shared__ float aw[NHq][Kq];
    __shared__ int vm[Kq];
    if (tid < Kq) vm[tid] = (rmask[bp] > 0.f && plens[bp * Kq + tid] > 0) ? 1 : 0;
    __syncthreads();
    {
        int h = warp / Kq, kk = warp % Kq;
        const float* qh = q + (size_t)bp * BANKq + h * DHq;
        const float* kh = k + ((size_t)bp * Kq + kk) * BANKq + h * DHq;
        float s = 0.f;
        for (int d = lane; d < DHq; d += 32) s += qh[d] * kh[d];
#pragma unroll
        for (int o = 16; o > 0; o >>= 1) s += __shfl_xor_sync(0xffffffffu, s, o);
        if (lane == 0) {
            s = s / sqrtf((float)DHq);
            sc[h][kk] = vm[kk] ? s : -1e9f;
        }
    }
    __syncthreads();
    if (tid < NHq) {
        int h = tid;
        float m = fmaxf(fmaxf(sc[h][0], sc[h][1]), sc[h][2]);
        float e0 = expf(sc[h][0] - m), e1 = expf(sc[h][1] - m), e2 = expf(sc[h][2] - m);
        float s = e0 + e1 + e2;
        aw[h][0] = e0 / s; aw[h][1] = e1 / s; aw[h][2] = e2 / s;
    }
    if (tid == 0) validany[bp] = (vm[0] | vm[1] | vm[2]);
    __syncthreads();
    for (int j = tid; j < BANKq; j += blockDim.x) {
        int h = j / DHq;
        const float* vb = v + (size_t)bp * Kq * BANKq + j;
        float r = aw[h][0] * vb[0] + aw[h][1] * vb[BANKq] + aw[h][2] * vb[2 * BANKq];
        bf16 hh2, ll2; split1(r, hh2, ll2);
        ctx_hi[(size_t)bp * BANKq + j] = hh2;
        ctx_lo[(size_t)bp * BANKq + j] = ll2;
    }
}

__global__ void build_of_split_kernel(const float* __restrict__ hf, const float* __restrict__ tf,
                                      const float* __restrict__ pinfo, const int* __restrict__ validany,
                                      bf16* __restrict__ oh, bf16* __restrict__ ol)
{
    int bp = blockIdx.x;
    int va = validany[bp];
    const float* hr = hf + (size_t)bp * BANKq;
    const float* tr = tf + (size_t)bp * BANKq;
    const float* pr = pinfo + (size_t)bp * BANKq;
    size_t base = (size_t)bp * BANK5q;
    for (int j = threadIdx.x; j < BANK5q; j += blockDim.x) {
        int seg = j / BANKq, jj = j - seg * BANKq;
        float v;
        if (seg == 0)      v = hr[jj];
        else if (seg == 1) v = tr[jj];
        else if (seg == 2) v = fabsf(hr[jj] - tr[jj]);
        else if (seg == 3) v = hr[jj] * tr[jj];
        else               v = va ? pr[jj] : 0.f;
        bf16 h, l; split1(v, h, l);
        oh[base + j] = h;
        ol[base + j] = l;
    }
}

__global__ void __launch_bounds__(256)
head_kernel(const float* __restrict__ hid, const float* __restrict__ mW,
            const float* __restrict__ mb, const float* __restrict__ bW,
            const float* __restrict__ bb, float* __restrict__ out)
{
    int m = blockIdx.x;
    __shared__ float srow[BANK5q];
    __shared__ float part[2][Rq + 2];
    const float* hr = hid + (size_t)m * BANK5q;
    for (int j = threadIdx.x; j < BANK5q; j += 256) srow[j] = hr[j];
    __syncthreads();
    int t = threadIdx.x;
    const int NT = Rq + 2;  // 99
    if (t < 2 * NT) {
        int ks = t / NT, n = t - ks * NT;
        int k0 = ks * (BANK5q / 2), k1 = k0 + BANK5q / 2;
        float acc = 0.f;
        if (n < Rq) {
#pragma unroll 8
            for (int k = k0; k < k1; k++) acc += srow[k] * mW[(size_t)k * Rq + n];
        } else {
            int nb = n - Rq;
#pragma unroll 8
            for (int k = k0; k < k1; k++) acc += srow[k] * bW[(size_t)k * 2 + nb];
        }
        part[ks][n] = acc;
    }
    __syncthreads();
    if (t < NT) {
        float v = part[0][t] + part[1][t];
        if (t < Rq) out[(size_t)m * Rq + t] = v + mb[t];
        else        out[(size_t)BPq * Rq + (size_t)m * 2 + (t - Rq)] = v + bb[t - Rq];
    }
}

// ---------------- orchestration ----------------
extern "C" void kernel_launch(void* const* d_in, const int* in_sizes, int n_in,
                              void* d_out, int out_size)
{
    const float* encoder_outputs = (const float*)d_in[0];
    const int*   entity_type     = (const int*)  d_in[1];
    const int*   entity_id       = (const int*)  d_in[2];
    const float* sub2words       = (const float*)d_in[3];
    const float* adj             = (const float*)d_in[4];
    const int*   h_t_pairs       = (const int*)  d_in[5];
    const float* rel_mask        = (const float*)d_in[6];
    const int*   path_nodes      = (const int*)  d_in[7];
    const int*   path_lens       = (const int*)  d_in[8];
    const float* type_emb        = (const float*)d_in[9];
    const float* id_emb          = (const float*)d_in[10];
    const float* gcn0_W          = (const float*)d_in[11];
    const float* gcn0_b          = (const float*)d_in[12];
    const float* gcn_W           = (const float*)d_in[13];
    const float* gcn_b           = (const float*)d_in[14];
    const float* attn_Wq         = (const float*)d_in[15];
    const float* attn_Wk         = (const float*)d_in[16];
    const float* attn_Wv         = (const float*)d_in[17];
    const float* lstm_Wih        = (const float*)d_in[18];
    const float* lstm_Whh        = (const float*)d_in[19];
    const float* lstm_b          = (const float*)d_in[20];
    const float* mha_inW         = (const float*)d_in[21];
    const float* mha_inb         = (const float*)d_in[22];
    const float* mha_outW        = (const float*)d_in[23];
    const float* mha_outb        = (const float*)d_in[24];
    const float* pred_W          = (const float*)d_in[25];
    const float* pred_b          = (const float*)d_in[26];
    const float* mW              = (const float*)d_in[27];
    const float* mb              = (const float*)d_in[28];
    const float* bW              = (const float*)d_in[29];
    const float* bb              = (const float*)d_in[30];
    float* out = (float*)d_out;

    void* p;
#define SYMF(var, sym) cudaGetSymbolAddress(&p, sym); float* var = (float*)p;
#define SYMB(var, sym) cudaGetSymbolAddress(&p, sym); bf16* var = (bf16*)p;
    SYMF(enc,   g_enc);    SYMF(feats, g_feats);  SYMF(tmp,   g_tmp);
    SYMF(x1,    g_x1);     SYMF(xq,    g_xq);     SYMF(xk,    g_xk);
    SYMF(xv,    g_xv);     SYMF(att,   g_att);
    SYMF(ih,    g_ih);     SYMF(hh,    g_hh);
    SYMF(cbuf,  g_c);      SYMF(hs1,   g_hs1);
    SYMF(hf,    g_hf);     SYMF(tf,    g_tf);
    SYMF(qb,    g_q);      SYMF(kb,    g_k);      SYMF(vb,    g_v);
    SYMF(pinfo, g_pinfo);  SYMF(hid,   g_hid);
    SYMB(ah,  g_ah);  SYMB(al,  g_al);
    SYMB(sh,  g_sh);  SYMB(sl,  g_sl);
    SYMB(w1h, g_w1h); SYMB(w1l, g_w1l);
    SYMB(w2h, g_w2h); SYMB(w2l, g_w2l);
    SYMB(wph, g_wph); SYMB(wpl, g_wpl);
    cudaGetSymbolAddress(&p, g_validany); int* validany = (int*)p;
#undef SYMF
#undef SYMB

    // 1) enc = concat(encoder_outputs, type_emb[...], id_emb[...])
    build_enc_kernel<<<Bq * Sq, 256>>>(encoder_outputs, entity_type, entity_id, type_emb, id_emb, enc);

    // 2) x0 = sub2words @ enc -> feats[:, :, 0:808]
    gemm(false, sub2words, enc, nullptr, nullptr, feats,
         Nq, D0q, Sq, Sq, D0q, BANKq, 0,
         (long)Nq * Sq, (long)Sq * D0q, (long)Nq * BANKq, 0, Bq, 1.f, 0);

    // 3) tmp = adj @ x0
    gemm(false, adj, feats, nullptr, nullptr, tmp,
         Nq, D0q, Nq, Nq, BANKq, D0q, 0,
         (long)Nq * Nq, (long)Nq * BANKq, (long)Nq * D0q, 0, Bq, 1.f, 0);

    // 4) xg0 = tmp @ gcn0_W + gcn0_b -> feats[:, :, 808:1064]
    gemm(false, tmp, gcn0_W, gcn0_b, nullptr, feats + 808,
         Nq, Gq, D0q, D0q, Gq, BANKq, 0,
         (long)Nq * D0q, 0, (long)Nq * BANKq, 0, Bq, 1.f, 0);

    // 5) GCN + graph-attention layers
    int xoff[NLq]   = {808, 1064};
    int outoff[NLq] = {1064, 1320};
    for (int l = 0; l < NLq; l++) {
        const float* x = feats + xoff[l];
        gemm(false, adj, x, nullptr, nullptr, tmp,
             Nq, Gq, Nq, Nq, BANKq, Gq, 0,
             (long)Nq * Nq, (long)Nq * BANKq, (long)Nq * Gq, 0, Bq, 1.f, 0);
        gemm(false, tmp, gcn_W + (long)l * Gq * Gq, gcn_b + l * Gq, nullptr, x1,
             Nq, Gq, Gq, Gq, Gq, Gq, 0,
             (long)Nq * Gq, 0, (long)Nq * Gq, 0, Bq, 1.f, 1);
        gemm(false, x, attn_Wq + (long)l * Gq * Gq, nullptr, nullptr, xq,
             Nq, Gq, Gq, BANKq, Gq, Gq, 0,
             (long)Nq * BANKq, 0, (long)Nq * Gq, 0, Bq, 1.f, 0);
        gemm(false, x1, attn_Wk + (long)l * Gq * Gq, nullptr, nullptr, xk,
             Nq, Gq, Gq, Gq, Gq, Gq, 0,
             (long)Nq * Gq, 0, (long)Nq * Gq, 0, Bq, 1.f, 0);
        gemm(false, x1, attn_Wv + (long)l * Gq * Gq, nullptr, nullptr, xv,
             Nq, Gq, Gq, Gq, Gq, Gq, 0,
             (long)Nq * Gq, 0, (long)Nq * Gq, 0, Bq, 1.f, 0);
        gemm(true, xq, xk, nullptr, nullptr, att,
             Nq, Nq, Gq, Gq, Gq, Nq, 0,
             (long)Nq * Gq, (long)Nq * Gq, (long)Nq * Nq, 0, Bq, 0.0625f, 0);
        softmax256_kernel<<<Bq * Nq, 256>>>(att);
        gemm(false, att, xv, nullptr, x1, feats + outoff[l],
             Nq, Gq, Nq, Nq, Gq, BANKq, Gq,
             (long)Nq * Nq, (long)Nq * Gq, (long)Nq * BANKq, (long)Nq * Gq, Bq, 1.f, 1);
    }

    // pred weight transpose-split (independent)
    {
        dim3 grid((BANK5q + 31) / 32, (BANK5q + 31) / 32);
        transpose_split_kernel<<<grid, dim3(32, 8)>>>(pred_W, wph, wpl, BANK5q, BANK5q);
    }

    // 6) gather paths -> split bf16
    gather_pf_split_kernel<<<MlstmT, 256>>>(feats, path_nodes, ah, al);

    // 7) two LSTM layers
    for (int layer = 0; layer < 2; layer++) {
        const float* Wih = lstm_Wih + (size_t)layer * BANK4q * BANKq;
        const float* Whh = lstm_Whh + (size_t)layer * BANK4q * BANKq;
        const float* bL  = lstm_b + (size_t)layer * BANK4q;
        split(Wih, w1h, w1l, (size_t)BANK4q * BANKq);
        split(Whh, w2h, w2l, (size_t)BANK4q * BANKq);
        gemm_bf16(ah, al, w1h, w1l, bL, ih, MlstmT, BANK4q, BANKq, 0);
        for (int t = 0; t < Lq; t++) {
            if (t > 0)
                gemm_bf16(sh, sl, w2h, w2l, nullptr, hh, Mlstm, BANK4q, BANKq, 0);
            dim3 grid((BANKq + 255) / 256, Mlstm);
            lstm_cell_kernel<<<grid, 256>>>(ih, hh, sh, sl,
                                            layer == 0 ? ah : nullptr,
                                            layer == 0 ? al : nullptr,
                                            cbuf,
                                            layer == 1 ? hs1 : nullptr, t);
        }
    }

    // 8) masked max-pool over time -> split bf16 (ah/al reused)
    {
        dim3 grid((BANKq + 255) / 256, Mlstm);
        maxpool_split_kernel<<<grid, 256>>>(hs1, path_lens, ah, al);
    }

    // 9) h_f, t_f, query (split)
    gather_ht_kernel<<<BPq, 256>>>(feats, h_t_pairs, hf, tf, sh, sl);

    // 10-11) q/k/v projections
    split(mha_inW, w1h, w1l, (size_t)3 * BANKq * BANKq);
    gemm_bf16(sh, sl, w1h, w1l, mha_inb, qb, BPq, BANKq, BANKq, 0);
    gemm_bf16(ah, al, w1h + (size_t)BANKq * BANKq, w1l + (size_t)BANKq * BANKq,
              mha_inb + BANKq, kb, Mlstm, BANKq, BANKq, 0);
    gemm_bf16(ah, al, w1h + 2 * (size_t)BANKq * BANKq, w1l + 2 * (size_t)BANKq * BANKq,
              mha_inb + 2 * BANKq, vb, Mlstm, BANKq, BANKq, 0);

    // 12) tiny attention over K=3 paths (ctx split into sh/sl)
    mha_attn_kernel<<<BPq, 384>>>(qb, kb, vb, path_lens, rel_mask, sh, sl, validany);

    // 13) pinfo = ctx @ mha_outW^T + mha_outb
    split(mha_outW, w2h, w2l, (size_t)BANKq * BANKq);
    gemm_bf16(sh, sl, w2h, w2l, mha_outb, pinfo, BPq, BANKq, BANKq, 0);

    // 14) of (split into ah/al)
    build_of_split_kernel<<<BPq, 256>>>(hf, tf, pinfo, validany, ah, al);

    // 15) hid = relu(of @ pred_W + pred_b)
    gemm_bf16(ah, al, wph, wpl, pred_b, hid, BPq, BANK5q, BANK5q, 1);

    // 16) fused output heads
    head_kernel<<<BPq, 256>>>(hid, mW, mb, bW, bb, out);
}

// round 8
// speedup vs baseline: 1.4620x; 1.4620x over previous
#include <cuda_runtime.h>
#include <cuda_bf16.h>
#include <math.h>
#include <stdio.h>

// ---------------- problem constants ----------------
#define Bq   4
#define Sq   512
#define Nq   256
#define Eq   42
#define Pq   256
#define Kq   3
#define Lq   4
#define HBq  768
#define DTq  20
#define DIq  20
#define Gq   256
#define NLq  2
#define Rq   97
#define NHq  4
#define D0q  808          // HB+DT+DI
#define BANKq 1576        // D0 + G*(NL+1)
#define BANK4q 6304       // 4*BANK
#define BANK5q 7880       // 5*BANK
#define DHq  394          // BANK/NH
#define Mlstm (Bq*Pq*Kq)        // 3072
#define MlstmT (Mlstm*Lq)       // 12288
#define BPq  (Bq*Pq)            // 1024

typedef __nv_bfloat16 bf16;
typedef __nv_bfloat162 bf162;

// ---------------- scratch (static device memory; no allocations allowed) ----------------
__device__ float g_enc   [Bq*Sq*D0q];
__device__ float g_feats [Bq*Nq*BANKq];
__device__ float g_tmp   [Bq*Nq*D0q];
__device__ float g_x1    [Bq*Nq*Gq];
__device__ float g_xq    [Bq*Nq*Gq];
__device__ float g_xk    [Bq*Nq*Gq];
__device__ float g_xv    [Bq*Nq*Gq];
__device__ float g_att   [Bq*Nq*Nq];
__device__ float g_ih    [(size_t)MlstmT*BANK4q];
__device__ float g_hh    [(size_t)Mlstm*BANK4q];
__device__ float g_c     [Mlstm*BANKq];
__device__ float g_hs1   [MlstmT*BANKq];
__device__ float g_hf    [BPq*BANKq];
__device__ float g_tf    [BPq*BANKq];
__device__ float g_q     [BPq*BANKq];
__device__ float g_k     [Mlstm*BANKq];
__device__ float g_v     [Mlstm*BANKq];
__device__ float g_pinfo [BPq*BANKq];
__device__ int   g_validany[BPq];
__device__ float g_hid   [BPq*BANK5q];

// bf16 split scratch
__device__ bf16 g_ah  [(size_t)MlstmT*BANKq];
__device__ bf16 g_al  [(size_t)MlstmT*BANKq];
__device__ bf16 g_sh  [(size_t)Mlstm*BANKq];
__device__ bf16 g_sl  [(size_t)Mlstm*BANKq];
__device__ bf16 g_w1h [(size_t)BANK4q*BANKq];
__device__ bf16 g_w1l [(size_t)BANK4q*BANKq];
__device__ bf16 g_w2h [(size_t)BANK4q*BANKq];
__device__ bf16 g_w2l [(size_t)BANK4q*BANKq];
__device__ bf16 g_wph [(size_t)BANK5q*BANK5q];
__device__ bf16 g_wpl [(size_t)BANK5q*BANK5q];

// ================= fp32 tiled GEMM (small GCN ops) =================
// 32x32 tiles: many CTAs -> latency hiding for tiny ops (verified faster in R7 ncu)
template <bool TRANSB>
__global__ void __launch_bounds__(256)
gemm32_kernel(const float* __restrict__ A, const float* __restrict__ B,
              const float* __restrict__ bias, const float* __restrict__ resid,
              float* __restrict__ C,
              int M, int N, int K,
              int lda, int ldb, int ldc, int ldr,
              long sA, long sB, long sC, long sR,
              float alpha, int act)
{
    int bz = blockIdx.z;
    A += bz * sA; B += bz * sB; C += bz * sC;
    if (resid) resid += bz * sR;

    int row0 = blockIdx.y * 32;
    int col0 = blockIdx.x * 32;

    __shared__ float As[32][33];
    __shared__ float Bs[32][33];

    int tid = threadIdx.x;
    int tx = tid & 15, ty = tid >> 4;

    float acc[2][2] = {{0.f, 0.f}, {0.f, 0.f}};

    for (int k0 = 0; k0 < K; k0 += 32) {
#pragma unroll
        for (int l = 0; l < 4; l++) {
            int idx = tid + l * 256;
            int m = idx >> 5, kk = idx & 31;
            int gr = row0 + m, gk = k0 + kk;
            As[kk][m] = (gr < M && gk < K) ? A[(long)gr * lda + gk] : 0.f;
        }
#pragma unroll
        for (int l = 0; l < 4; l++) {
            int idx = tid + l * 256;
            if (TRANSB) {
                int n = idx >> 5, kk = idx & 31;
                int gn = col0 + n, gk = k0 + kk;
                Bs[kk][n] = (gn < N && gk < K) ? B[(long)gn * ldb + gk] : 0.f;
            } else {
                int kk = idx >> 5, n = idx & 31;
                int gn = col0 + n, gk = k0 + kk;
                Bs[kk][n] = (gn < N && gk < K) ? B[(long)gk * ldb + gn] : 0.f;
            }
        }
        __syncthreads();
#pragma unroll
        for (int kk = 0; kk < 32; kk++) {
            float a0 = As[kk][ty], a1 = As[kk][ty + 16];
            float b0 = Bs[kk][tx], b1 = Bs[kk][tx + 16];
            acc[0][0] = fmaf(a0, b0, acc[0][0]);
            acc[0][1] = fmaf(a0, b1, acc[0][1]);
            acc[1][0] = fmaf(a1, b0, acc[1][0]);
            acc[1][1] = fmaf(a1, b1, acc[1][1]);
        }
        __syncthreads();
    }

#pragma unroll
    for (int i = 0; i < 2; i++) {
        int r = row0 + ty + 16 * i;
        if (r >= M) continue;
#pragma unroll
        for (int j = 0; j < 2; j++) {
            int cc = col0 + tx + 16 * j;
            if (cc >= N) continue;
            float v = acc[i][j] * alpha;
            if (bias) v += bias[cc];
            if (act == 1) v = fmaxf(v, 0.f);
            if (resid) v += resid[(long)r * ldr + cc];
            C[(long)r * ldc + cc] = v;
        }
    }
}

static void gemm(bool transB,
                 const float* A, const float* B, const float* bias, const float* resid, float* C,
                 int M, int N, int K, int lda, int ldb, int ldc, int ldr,
                 long sA, long sB, long sC, long sR, int batch, float alpha, int act)
{
    dim3 grid((N + 31) / 32, (M + 31) / 32, batch);
    if (transB)
        gemm32_kernel<true><<<grid, 256>>>(A, B, bias, resid, C, M, N, K, lda, ldb, ldc, ldr, sA, sB, sC, sR, alpha, act);
    else
        gemm32_kernel<false><<<grid, 256>>>(A, B, bias, resid, C, M, N, K, lda, ldb, ldc, ldr, sA, sB, sC, sR, alpha, act);
}

// ================= bf16 split-precision tensor-core GEMM (R6 loop, verified) =================
// C(MxN) = A(MxK) @ B(NxK)^T + bias, A = Ah+Al, B = Bh+Bl.
// acc += Ah*Bh + Ah*Bl + Al*Bh — 3 passes of 16 independent MMAs (RAW-free).
#define LDSB 40                    // padded row stride in bf16 (80B -> conflict-free ldmatrix)
#define GSTG 3                     // pipeline stages
#define PLANE_E (128*LDSB)         // elems per plane
#define PLANE_B (PLANE_E*2)        // bytes per plane (10240)
#define STAGE_B (4*PLANE_B)        // bytes per stage  (40960)

#define MMA_BF16(d, a, b) asm volatile( \
    "mma.sync.aligned.m16n8k16.row.col.f32.bf16.bf16.f32 " \
    "{%0,%1,%2,%3}, {%4,%5,%6,%7}, {%8,%9}, {%0,%1,%2,%3};" \
    : "+f"((d)[0]), "+f"((d)[1]), "+f"((d)[2]), "+f"((d)[3]) \
    : "r"((a)[0]), "r"((a)[1]), "r"((a)[2]), "r"((a)[3]), "r"((b)[0]), "r"((b)[1]))

#define LDSM4(r, addr) asm volatile( \
    "ldmatrix.sync.aligned.m8n8.x4.shared.b16 {%0,%1,%2,%3}, [%4];" \
    : "=r"((r)[0]), "=r"((r)[1]), "=r"((r)[2]), "=r"((r)[3]) : "r"(addr))

__device__ __forceinline__ void cpasync16(unsigned saddr, const void* g, int srcbytes)
{
    asm volatile("cp.async.cg.shared.global [%0], [%1], 16, %2;\n"
                 :: "r"(saddr), "l"(g), "r"(srcbytes));
}

__device__ __forceinline__ void gbf_prefetch(
    const bf16* __restrict__ Ah, const bf16* __restrict__ Al,
    const bf16* __restrict__ Bh, const bf16* __restrict__ Bl,
    long row0, long col0, int M, int N, int K,
    int kt, int T, unsigned sbase, int stg, int tid)
{
    if (kt >= T) return;
    long k0 = (long)kt * 32;
    unsigned sst = sbase + (unsigned)stg * STAGE_B;
#pragma unroll
    for (int i = 0; i < 2; i++) {
        int c = tid + i * 256;          // 512 chunks of 16B per plane
        int r = c >> 2;
        int ko = (c & 3) * 8;
        long gk = k0 + ko;
        bool kok = gk < K;
        long gkc = kok ? gk : 0;
        unsigned soff = (unsigned)((r * LDSB + ko) * 2);
        {
            long gr = row0 + r;
            bool ok = kok && (gr < M);
            long grc = ok ? gr : 0;
            int nb = ok ? 16 : 0;
            cpasync16(sst + soff,            Ah + grc * K + gkc, nb);
            cpasync16(sst + PLANE_B + soff,  Al + grc * K + gkc, nb);
        }
        {
            long gn = col0 + r;
            bool ok = kok && (gn < N);
            long gnc = ok ? gn : 0;
            int nb = ok ? 16 : 0;
            cpasync16(sst + 2 * PLANE_B + soff, Bh + gnc * K + gkc, nb);
            cpasync16(sst + 3 * PLANE_B + soff, Bl + gnc * K + gkc, nb);
        }
    }
}

__global__ void __launch_bounds__(256)
gemm_bf16_kernel(const bf16* __restrict__ Ah, const bf16* __restrict__ Al,
                 const bf16* __restrict__ Bh, const bf16* __restrict__ Bl,
                 const float* __restrict__ bias, float* __restrict__ C,
                 int M, int N, int K, int act)
{
    extern __shared__ __align__(16) bf16 dsm[];
    unsigned sbase = (unsigned)__cvta_generic_to_shared(dsm);

    int tid = threadIdx.x;
    int warp = tid >> 5, lane = tid & 31;
    int wm = (warp & 1) * 64;
    int wn = (warp >> 1) * 32;
    long row0 = (long)blockIdx.y * 128;
    long col0 = (long)blockIdx.x * 128;

    float acc[4][4][4];
#pragma unroll
    for (int a = 0; a < 4; a++)
#pragma unroll
        for (int b = 0; b < 4; b++)
#pragma unroll
            for (int c = 0; c < 4; c++) acc[a][b][c] = 0.f;

    int am_r = (lane & 7) + ((lane >> 3) & 1) * 8;
    int a_c8 = ((lane >> 4) & 1) * 8;
    int b_r  = (lane & 7) + ((lane >> 4) & 1) * 8;
    int b_c8 = ((lane >> 3) & 1) * 8;

    int T = (K + 31) / 32;

    // prologue: fill the pipeline
#pragma unroll
    for (int kt = 0; kt < GSTG; kt++) {
        gbf_prefetch(Ah, Al, Bh, Bl, row0, col0, M, N, K, kt, T, sbase, kt, tid);
        asm volatile("cp.async.commit_group;\n");
    }

    for (int kt = 0; kt < T; kt++) {
        asm volatile("cp.async.wait_group %0;\n" :: "n"(GSTG - 1));
        __syncthreads();

        int stg = kt % GSTG;
        unsigned sst = sbase + (unsigned)stg * STAGE_B;
        unsigned aB = sst;
        unsigned bB = sst + 2 * PLANE_B;

#pragma unroll
        for (int ks = 0; ks < 2; ks++) {
            int kb = ks * 16;
            unsigned bh[2][4], bl[2][4];
#pragma unroll
            for (int pp = 0; pp < 2; pp++) {
                unsigned addr = bB + (unsigned)(((wn + pp * 16 + b_r) * LDSB + kb + b_c8) * 2);
                LDSM4(bh[pp], addr);
                LDSM4(bl[pp], addr + PLANE_B);
            }
            unsigned ahf[4][4], alf[4][4];
#pragma unroll
            for (int mi = 0; mi < 4; mi++) {
                unsigned addr = aB + (unsigned)(((wm + mi * 16 + am_r) * LDSB + kb + a_c8) * 2);
                LDSM4(ahf[mi], addr);
                LDSM4(alf[mi], addr + PLANE_B);
            }
            // pass 1: ah*bh — 16 independent MMAs
#pragma unroll
            for (int mi = 0; mi < 4; mi++)
#pragma unroll
                for (int ni = 0; ni < 4; ni++)
                    MMA_BF16(acc[mi][ni], ahf[mi], (&bh[ni >> 1][(ni & 1) * 2]));
            // pass 2: ah*bl
#pragma unroll
            for (int mi = 0; mi < 4; mi++)
#pragma unroll
                for (int ni = 0; ni < 4; ni++)
                    MMA_BF16(acc[mi][ni], ahf[mi], (&bl[ni >> 1][(ni & 1) * 2]));
            // pass 3: al*bh
#pragma unroll
            for (int mi = 0; mi < 4; mi++)
#pragma unroll
                for (int ni = 0; ni < 4; ni++)
                    MMA_BF16(acc[mi][ni], alf[mi], (&bh[ni >> 1][(ni & 1) * 2]));
        }
        __syncthreads();
        gbf_prefetch(Ah, Al, Bh, Bl, row0, col0, M, N, K, kt + GSTG, T, sbase, stg, tid);
        asm volatile("cp.async.commit_group;\n");
    }

    // ---- epilogue ----
#pragma unroll
    for (int mi = 0; mi < 4; mi++) {
#pragma unroll
        for (int ni = 0; ni < 4; ni++) {
            long r = row0 + wm + mi * 16 + (lane >> 2);
            long c = col0 + wn + ni * 8 + (lane & 3) * 2;
#pragma unroll
            for (int half = 0; half < 2; half++) {
                long rr = r + half * 8;
                if (rr >= M) continue;
#pragma unroll
                for (int e = 0; e < 2; e++) {
                    long cc = c + e;
                    if (cc >= N) continue;
                    float v = acc[mi][ni][half * 2 + e];
                    if (bias) v += bias[cc];
                    if (act == 1) v = fmaxf(v, 0.f);
                    C[(size_t)rr * N + cc] = v;
                }
            }
        }
    }
}

static void gemm_bf16(const bf16* Ah, const bf16* Al, const bf16* Bh, const bf16* Bl,
                      const float* bias, float* C, int M, int N, int K, int act)
{
    static int attr_done = 0;
    if (!attr_done) {
        cudaFuncSetAttribute(gemm_bf16_kernel,
                             cudaFuncAttributeMaxDynamicSharedMemorySize, GSTG * STAGE_B);
        attr_done = 1;
    }
    dim3 grid((N + 127) / 128, (M + 127) / 128);
    gemm_bf16_kernel<<<grid, 256, GSTG * STAGE_B>>>(Ah, Al, Bh, Bl, bias, C, M, N, K, act);
}

// ================= conversion kernels =================
__device__ __forceinline__ void split1(float f, bf16& h, bf16& l)
{
    h = __float2bfloat16(f);
    l = __float2bfloat16(f - __bfloat162float(h));
}

__global__ void split_kernel(const float* __restrict__ x, bf16* __restrict__ hi,
                             bf16* __restrict__ lo, size_t n4)
{
    size_t i = (size_t)blockIdx.x * blockDim.x + threadIdx.x;
    if (i >= n4) return;
    float4 f = ((const float4*)x)[i];
    bf16 h0, l0, h1, l1, h2, l2, h3, l3;
    split1(f.x, h0, l0); split1(f.y, h1, l1); split1(f.z, h2, l2); split1(f.w, h3, l3);
    bf162 vh0; vh0.x = h0; vh0.y = h1;
    bf162 vh1; vh1.x = h2; vh1.y = h3;
    bf162 vl0; vl0.x = l0; vl0.y = l1;
    bf162 vl1; vl1.x = l2; vl1.y = l3;
    ((bf162*)hi)[i * 2] = vh0; ((bf162*)hi)[i * 2 + 1] = vh1;
    ((bf162*)lo)[i * 2] = vl0; ((bf162*)lo)[i * 2 + 1] = vl1;
}

static void split(const float* x, bf16* hi, bf16* lo, size_t n)
{
    size_t n4 = n / 4;
    split_kernel<<<(unsigned)((n4 + 255) / 256), 256>>>(x, hi, lo, n4);
}

__global__ void transpose_split_kernel(const float* __restrict__ B, bf16* __restrict__ Th,
                                       bf16* __restrict__ Tl, int K, int N)
{
    __shared__ float tile[32][33];
    int k0 = blockIdx.y * 32, n0 = blockIdx.x * 32;
    int tx = threadIdx.x, ty = threadIdx.y;  // 32 x 8
#pragma unroll
    for (int i = 0; i < 32; i += 8) {
        int k = k0 + ty + i, n = n0 + tx;
        tile[ty + i][tx] = (k < K && n < N) ? B[(size_t)k * N + n] : 0.f;
    }
    __syncthreads();
#pragma unroll
    for (int i = 0; i < 32; i += 8) {
        int n = n0 + ty + i, k = k0 + tx;
        if (n < N && k < K) {
            float f = tile[tx][ty + i];
            bf16 h, l; split1(f, h, l);
            Th[(size_t)n * K + k] = h;
            Tl[(size_t)n * K + k] = l;
        }
    }
}

// ---------------- fast activations (ex2/rcp fast paths, err ~1e-6) ----------------
__device__ __forceinline__ float fsig(float x)
{
    return __fdividef(1.f, 1.f + __expf(-x));
}
__device__ __forceinline__ float ftanh(float x)
{
    x = fminf(fmaxf(x, -15.f), 15.f);
    float e = __expf(-2.f * x);
    return __fdividef(1.f - e, 1.f + e);
}

// ---------------- small custom kernels ----------------
__global__ void build_enc_kernel(const float* __restrict__ eo, const int* __restrict__ etype,
                                 const int* __restrict__ eid, const float* __restrict__ temb,
                                 const float* __restrict__ iemb, float* __restrict__ enc)
{
    int bs = blockIdx.x;
    const float* src = eo + (long)bs * HBq;
    float* dst = enc + (long)bs * D0q;
    int ty = etype[bs], idv = eid[bs];
    for (int j = threadIdx.x; j < D0q; j += blockDim.x) {
        float v;
        if (j < HBq)            v = src[j];
        else if (j < HBq + DTq) v = temb[ty * DTq + (j - HBq)];
        else                    v = iemb[idv * DIq + (j - HBq - DTq)];
        dst[j] = v;
    }
}

__global__ void softmax256_kernel(float* __restrict__ x)
{
    int row = blockIdx.x;
    int tid = threadIdx.x;
    float v = x[(long)row * 256 + tid];
    __shared__ float red[8];
    int lane = tid & 31, warp = tid >> 5;
    float m = v;
#pragma unroll
    for (int o = 16; o > 0; o >>= 1) m = fmaxf(m, __shfl_xor_sync(0xffffffffu, m, o));
    if (lane == 0) red[warp] = m;
    __syncthreads();
    if (tid == 0) {
        float mm = red[0];
        for (int w = 1; w < 8; w++) mm = fmaxf(mm, red[w]);
        red[0] = mm;
    }
    __syncthreads();
    float mx = red[0];
    float e = expf(v - mx);
    float s = e;
#pragma unroll
    for (int o = 16; o > 0; o >>= 1) s += __shfl_xor_sync(0xffffffffu, s, o);
    __shared__ float red2[8];
    if (lane == 0) red2[warp] = s;
    __syncthreads();
    if (tid == 0) {
        float ss = 0.f;
        for (int w = 0; w < 8; w++) ss += red2[w];
        red2[0] = ss;
    }
    __syncthreads();
    x[(long)row * 256 + tid] = e / red2[0];
}

__global__ void gather_pf_split_kernel(const float* __restrict__ feats, const int* __restrict__ nodes,
                                       bf16* __restrict__ hi, bf16* __restrict__ lo)
{
    int row = blockIdx.x;                 // 0..12287
    int b = row / (Pq * Kq * Lq);
    int node = nodes[row];
    const float* src = feats + ((size_t)b * Nq + node) * BANKq;
    size_t base = (size_t)row * BANKq;
    for (int j = threadIdx.x; j < BANKq; j += blockDim.x) {
        bf16 h, l; split1(src[j], h, l);
        hi[base + j] = h;
        lo[base + j] = l;
    }
}

__global__ void lstm_cell_kernel(const float* __restrict__ ih, const float* __restrict__ hh,
                                 bf16* __restrict__ h_hi, bf16* __restrict__ h_lo,
                                 bf16* __restrict__ seq_hi, bf16* __restrict__ seq_lo,
                                 float* __restrict__ c, float* __restrict__ hs, int t)
{
    int i = blockIdx.y;
    int j = blockIdx.x * blockDim.x + threadIdx.x;
    if (j >= BANKq) return;
    const float* g = ih + ((size_t)i * Lq + t) * BANK4q;
    float gi = g[j], gf = g[BANKq + j], gg = g[2 * BANKq + j], go = g[3 * BANKq + j];
    float cp = 0.f;
    if (t > 0) {
        const float* hr = hh + (size_t)i * BANK4q;
        gi += hr[j]; gf += hr[BANKq + j]; gg += hr[2 * BANKq + j]; go += hr[3 * BANKq + j];
        cp = c[(size_t)i * BANKq + j];
    }
    float cn = fsig(gf) * cp + fsig(gi) * ftanh(gg);
    float hn = fsig(go) * ftanh(cn);
    c[(size_t)i * BANKq + j] = cn;
    bf16 h, l; split1(hn, h, l);
    h_hi[(size_t)i * BANKq + j] = h;
    h_lo[(size_t)i * BANKq + j] = l;
    if (seq_hi) {
        seq_hi[((size_t)i * Lq + t) * BANKq + j] = h;
        seq_lo[((size_t)i * Lq + t) * BANKq + j] = l;
    }
    if (hs) hs[((size_t)i * Lq + t) * BANKq + j] = hn;
}

__global__ void maxpool_split_kernel(const float* __restrict__ hs, const int* __restrict__ lens,
                                     bf16* __restrict__ hi, bf16* __restrict__ lo)
{
    int i = blockIdx.y;
    int j = blockIdx.x * blockDim.x + threadIdx.x;
    if (j >= BANKq) return;
    int len = lens[i];
    float m = -1e9f;
    const float* base = hs + (size_t)i * Lq * BANKq + j;
    for (int t = 0; t < Lq; t++)
        if (t < len) m = fmaxf(m, base[(size_t)t * BANKq]);
    float r = (len > 0) ? m : 0.f;
    bf16 h, l; split1(r, h, l);
    hi[(size_t)i * BANKq + j] = h;
    lo[(size_t)i * BANKq + j] = l;
}

__global__ void gather_ht_kernel(const float* __restrict__ feats, const int* __restrict__ htp,
                                 float* __restrict__ hf, float* __restrict__ tf,
                                 bf16* __restrict__ qh, bf16* __restrict__ ql)
{
    int bp = blockIdx.x;
    int b = bp / Pq;
    int h0 = htp[bp * 2 + 0], t0 = htp[bp * 2 + 1];
    h0 = (h0 == 0) ? 0 : h0 - 1;
    t0 = (t0 == 0) ? 0 : t0 - 1;
    const float* hsrc = feats + ((size_t)b * Nq + (Nq - Eq) + h0) * BANKq;
    const float* tsrc = feats + ((size_t)b * Nq + (Nq - Eq) + t0) * BANKq;
    for (int j = threadIdx.x; j < BANKq; j += blockDim.x) {
        float hv = hsrc[j], tv = tsrc[j];
        hf[(size_t)bp * BANKq + j] = hv;
        tf[(size_t)bp * BANKq + j] = tv;
        bf16 h, l; split1(hv - tv, h, l);
        qh[(size_t)bp * BANKq + j] = h;
        ql[(size_t)bp * BANKq + j] = l;
    }
}

__global__ void mha_attn_kernel(const float* __restrict__ q, const float* __restrict__ k,
                                const float* __restrict__ v, const int* __restrict__ plens,
                                const float* __restrict__ rmask,
                                bf16* __restrict__ ctx_hi, bf16* __restrict__ ctx_lo,
                                int* __restrict__ validany)
{
    int bp = blockIdx.x;
    int tid = threadIdx.x;
    int warp = tid >> 5, lane = tid & 31;
    __shared__ float sc[NHq][Kq];
    __shared__ float aw[NHq][Kq];
    __shared__ int vm[Kq];
    if (tid < Kq) vm[tid] = (rmask[bp] > 0.f && plens[bp * Kq + tid] > 0) ? 1 : 0;
    __syncthreads();
    {
        int h = warp / Kq, kk = warp % Kq;
        const float* qh = q + (size_t)bp * BANKq + h * DHq;
        const float* kh = k + ((size_t)bp * Kq + kk) * BANKq + h * DHq;
        float s = 0.f;
        for (int d = lane; d < DHq; d += 32) s += qh[d] * kh[d];
#pragma unroll
        for (int o = 16; o > 0; o >>= 1) s += __shfl_xor_sync(0xffffffffu, s, o);
        if (lane == 0) {
            s = s / sqrtf((float)DHq);
            sc[h][kk] = vm[kk] ? s : -1e9f;
        }
    }
    __syncthreads();
    if (tid < NHq) {
        int h = tid;
        float m = fmaxf(fmaxf(sc[h][0], sc[h][1]), sc[h][2]);
        float e0 = expf(sc[h][0] - m), e1 = expf(sc[h][1] - m), e2 = expf(sc[h][2] - m);
        float s = e0 + e1 + e2;
        aw[h][0] = e0 / s; aw[h][1] = e1 / s; aw[h][2] = e2 / s;
    }
    if (tid == 0) validany[bp] = (vm[0] | vm[1] | vm[2]);
    __syncthreads();
    for (int j = tid; j < BANKq; j += blockDim.x) {
        int h = j / DHq;
        const float* vb = v + (size_t)bp * Kq * BANKq + j;
        float r = aw[h][0] * vb[0] + aw[h][1] * vb[BANKq] + aw[h][2] * vb[2 * BANKq];
        bf16 hh2, ll2; split1(r, hh2, ll2);
        ctx_hi[(size_t)bp * BANKq + j] = hh2;
        ctx_lo[(size_t)bp * BANKq + j] = ll2;
    }
}

__global__ void build_of_split_kernel(const float* __restrict__ hf, const float* __restrict__ tf,
                                      const float* __restrict__ pinfo, const int* __restrict__ validany,
                                      bf16* __restrict__ oh, bf16* __restrict__ ol)
{
    int bp = blockIdx.x;
    int va = validany[bp];
    const float* hr = hf + (size_t)bp * BANKq;
    const float* tr = tf + (size_t)bp * BANKq;
    const float* pr = pinfo + (size_t)bp * BANKq;
    size_t base = (size_t)bp * BANK5q;
    for (int j = threadIdx.x; j < BANK5q; j += blockDim.x) {
        int seg = j / BANKq, jj = j - seg * BANKq;
        float v;
        if (seg == 0)      v = hr[jj];
        else if (seg == 1) v = tr[jj];
        else if (seg == 2) v = fabsf(hr[jj] - tr[jj]);
        else if (seg == 3) v = hr[jj] * tr[jj];
        else               v = va ? pr[jj] : 0.f;
        bf16 h, l; split1(v, h, l);
        oh[base + j] = h;
        ol[base + j] = l;
    }
}

__global__ void __launch_bounds__(256)
head_kernel(const float* __restrict__ hid, const float* __restrict__ mW,
            const float* __restrict__ mb, const float* __restrict__ bW,
            const float* __restrict__ bb, float* __restrict__ out)
{
    int m = blockIdx.x;
    __shared__ float srow[BANK5q];
    __shared__ float part[2][Rq + 2];
    const float* hr = hid + (size_t)m * BANK5q;
    for (int j = threadIdx.x; j < BANK5q; j += 256) srow[j] = hr[j];
    __syncthreads();
    int t = threadIdx.x;
    const int NT = Rq + 2;  // 99
    if (t < 2 * NT) {
        int ks = t / NT, n = t - ks * NT;
        int k0 = ks * (BANK5q / 2), k1 = k0 + BANK5q / 2;
        float acc = 0.f;
        if (n < Rq) {
#pragma unroll 8
            for (int k = k0; k < k1; k++) acc += srow[k] * mW[(size_t)k * Rq + n];
        } else {
            int nb = n - Rq;
#pragma unroll 8
            for (int k = k0; k < k1; k++) acc += srow[k] * bW[(size_t)k * 2 + nb];
        }
        part[ks][n] = acc;
    }
    __syncthreads();
    if (t < NT) {
        float v = part[0][t] + part[1][t];
        if (t < Rq) out[(size_t)m * Rq + t] = v + mb[t];
        else        out[(size_t)BPq * Rq + (size_t)m * 2 + (t - Rq)] = v + bb[t - Rq];
    }
}

// ---------------- orchestration ----------------
extern "C" void kernel_launch(void* const* d_in, const int* in_sizes, int n_in,
                              void* d_out, int out_size)
{
    const float* encoder_outputs = (const float*)d_in[0];
    const int*   entity_type     = (const int*)  d_in[1];
    const int*   entity_id       = (const int*)  d_in[2];
    const float* sub2words       = (const float*)d_in[3];
    const float* adj             = (const float*)d_in[4];
    const int*   h_t_pairs       = (const int*)  d_in[5];
    const float* rel_mask        = (const float*)d_in[6];
    const int*   path_nodes      = (const int*)  d_in[7];
    const int*   path_lens       = (const int*)  d_in[8];
    const float* type_emb        = (const float*)d_in[9];
    const float* id_emb          = (const float*)d_in[10];
    const float* gcn0_W          = (const float*)d_in[11];
    const float* gcn0_b          = (const float*)d_in[12];
    const float* gcn_W           = (const float*)d_in[13];
    const float* gcn_b           = (const float*)d_in[14];
    const float* attn_Wq         = (const float*)d_in[15];
    const float* attn_Wk         = (const float*)d_in[16];
    const float* attn_Wv         = (const float*)d_in[17];
    const float* lstm_Wih        = (const float*)d_in[18];
    const float* lstm_Whh        = (const float*)d_in[19];
    const float* lstm_b          = (const float*)d_in[20];
    const float* mha_inW         = (const float*)d_in[21];
    const float* mha_inb         = (const float*)d_in[22];
    const float* mha_outW        = (const float*)d_in[23];
    const float* mha_outb        = (const float*)d_in[24];
    const float* pred_W          = (const float*)d_in[25];
    const float* pred_b          = (const float*)d_in[26];
    const float* mW              = (const float*)d_in[27];
    const float* mb              = (const float*)d_in[28];
    const float* bW              = (const float*)d_in[29];
    const float* bb              = (const float*)d_in[30];
    float* out = (float*)d_out;

    void* p;
#define SYMF(var, sym) cudaGetSymbolAddress(&p, sym); float* var = (float*)p;
#define SYMB(var, sym) cudaGetSymbolAddress(&p, sym); bf16* var = (bf16*)p;
    SYMF(enc,   g_enc);    SYMF(feats, g_feats);  SYMF(tmp,   g_tmp);
    SYMF(x1,    g_x1);     SYMF(xq,    g_xq);     SYMF(xk,    g_xk);
    SYMF(xv,    g_xv);     SYMF(att,   g_att);
    SYMF(ih,    g_ih);     SYMF(hh,    g_hh);
    SYMF(cbuf,  g_c);      SYMF(hs1,   g_hs1);
    SYMF(hf,    g_hf);     SYMF(tf,    g_tf);
    SYMF(qb,    g_q);      SYMF(kb,    g_k);      SYMF(vb,    g_v);
    SYMF(pinfo, g_pinfo);  SYMF(hid,   g_hid);
    SYMB(ah,  g_ah);  SYMB(al,  g_al);
    SYMB(sh,  g_sh);  SYMB(sl,  g_sl);
    SYMB(w1h, g_w1h); SYMB(w1l, g_w1l);
    SYMB(w2h, g_w2h); SYMB(w2l, g_w2l);
    SYMB(wph, g_wph); SYMB(wpl, g_wpl);
    cudaGetSymbolAddress(&p, g_validany); int* validany = (int*)p;
#undef SYMF
#undef SYMB

    // 1) enc = concat(encoder_outputs, type_emb[...], id_emb[...])
    build_enc_kernel<<<Bq * Sq, 256>>>(encoder_outputs, entity_type, entity_id, type_emb, id_emb, enc);

    // 2) x0 = sub2words @ enc -> feats[:, :, 0:808]
    gemm(false, sub2words, enc, nullptr, nullptr, feats,
         Nq, D0q, Sq, Sq, D0q, BANKq, 0,
         (long)Nq * Sq, (long)Sq * D0q, (long)Nq * BANKq, 0, Bq, 1.f, 0);

    // 3) tmp = adj @ x0
    gemm(false, adj, feats, nullptr, nullptr, tmp,
         Nq, D0q, Nq, Nq, BANKq, D0q, 0,
         (long)Nq * Nq, (long)Nq * BANKq, (long)Nq * D0q, 0, Bq, 1.f, 0);

    // 4) xg0 = tmp @ gcn0_W + gcn0_b -> feats[:, :, 808:1064]
    gemm(false, tmp, gcn0_W, gcn0_b, nullptr, feats + 808,
         Nq, Gq, D0q, D0q, Gq, BANKq, 0,
         (long)Nq * D0q, 0, (long)Nq * BANKq, 0, Bq, 1.f, 0);

    // 5) GCN + graph-attention layers
    int xoff[NLq]   = {808, 1064};
    int outoff[NLq] = {1064, 1320};
    for (int l = 0; l < NLq; l++) {
        const float* x = feats + xoff[l];
        gemm(false, adj, x, nullptr, nullptr, tmp,
             Nq, Gq, Nq, Nq, BANKq, Gq, 0,
             (long)Nq * Nq, (long)Nq * BANKq, (long)Nq * Gq, 0, Bq, 1.f, 0);
        gemm(false, tmp, gcn_W + (long)l * Gq * Gq, gcn_b + l * Gq, nullptr, x1,
             Nq, Gq, Gq, Gq, Gq, Gq, 0,
             (long)Nq * Gq, 0, (long)Nq * Gq, 0, Bq, 1.f, 1);
        gemm(false, x, attn_Wq + (long)l * Gq * Gq, nullptr, nullptr, xq,
             Nq, Gq, Gq, BANKq, Gq, Gq, 0,
             (long)Nq * BANKq, 0, (long)Nq * Gq, 0, Bq, 1.f, 0);
        gemm(false, x1, attn_Wk + (long)l * Gq * Gq, nullptr, nullptr, xk,
             Nq, Gq, Gq, Gq, Gq, Gq, 0,
             (long)Nq * Gq, 0, (long)Nq * Gq, 0, Bq, 1.f, 0);
        gemm(false, x1, attn_Wv + (long)l * Gq * Gq, nullptr, nullptr, xv,
             Nq, Gq, Gq, Gq, Gq, Gq, 0,
             (long)Nq * Gq, 0, (long)Nq * Gq, 0, Bq, 1.f, 0);
        gemm(true, xq, xk, nullptr, nullptr, att,
             Nq, Nq, Gq, Gq, Gq, Nq, 0,
             (long)Nq * Gq, (long)Nq * Gq, (long)Nq * Nq, 0, Bq, 0.0625f, 0);
        softmax256_kernel<<<Bq * Nq, 256>>>(att);
        gemm(false, att, xv, nullptr, x1, feats + outoff[l],
             Nq, Gq, Nq, Nq, Gq, BANKq, Gq,
             (long)Nq * Nq, (long)Nq * Gq, (long)Nq * BANKq, (long)Nq * Gq, Bq, 1.f, 1);
    }

    // pred weight transpose-split (independent)
    {
        dim3 grid((BANK5q + 31) / 32, (BANK5q + 31) / 32);
        transpose_split_kernel<<<grid, dim3(32, 8)>>>(pred_W, wph, wpl, BANK5q, BANK5q);
    }

    // 6) gather paths -> split bf16
    gather_pf_split_kernel<<<MlstmT, 256>>>(feats, path_nodes, ah, al);

    // 7) two LSTM layers
    for (int layer = 0; layer < 2; layer++) {
        const float* Wih = lstm_Wih + (size_t)layer * BANK4q * BANKq;
        const float* Whh = lstm_Whh + (size_t)layer * BANK4q * BANKq;
        const float* bL  = lstm_b + (size_t)layer * BANK4q;
        split(Wih, w1h, w1l, (size_t)BANK4q * BANKq);
        split(Whh, w2h, w2l, (size_t)BANK4q * BANKq);
        gemm_bf16(ah, al, w1h, w1l, bL, ih, MlstmT, BANK4q, BANKq, 0);
        for (int t = 0; t < Lq; t++) {
            if (t > 0)
                gemm_bf16(sh, sl, w2h, w2l, nullptr, hh, Mlstm, BANK4q, BANKq, 0);
            dim3 grid((BANKq + 255) / 256, Mlstm);
            lstm_cell_kernel<<<grid, 256>>>(ih, hh, sh, sl,
                                            layer == 0 ? ah : nullptr,
                                            layer == 0 ? al : nullptr,
                                            cbuf,
                                            layer == 1 ? hs1 : nullptr, t);
        }
    }

    // 8) masked max-pool over time -> split bf16 (ah/al reused)
    {
        dim3 grid((BANKq + 255) / 256, Mlstm);
        maxpool_split_kernel<<<grid, 256>>>(hs1, path_lens, ah, al);
    }

    // 9) h_f, t_f, query (split)
    gather_ht_kernel<<<BPq, 256>>>(feats, h_t_pairs, hf, tf, sh, sl);

    // 10-11) q/k/v projections
    split(mha_inW, w1h, w1l, (size_t)3 * BANKq * BANKq);
    gemm_bf16(sh, sl, w1h, w1l, mha_inb, qb, BPq, BANKq, BANKq, 0);
    gemm_bf16(ah, al, w1h + (size_t)BANKq * BANKq, w1l + (size_t)BANKq * BANKq,
              mha_inb + BANKq, kb, Mlstm, BANKq, BANKq, 0);
    gemm_bf16(ah, al, w1h + 2 * (size_t)BANKq * BANKq, w1l + 2 * (size_t)BANKq * BANKq,
              mha_inb + 2 * BANKq, vb, Mlstm, BANKq, BANKq, 0);

    // 12) tiny attention over K=3 paths (ctx split into sh/sl)
    mha_attn_kernel<<<BPq, 384>>>(qb, kb, vb, path_lens, rel_mask, sh, sl, validany);

    // 13) pinfo = ctx @ mha_outW^T + mha_outb
    split(mha_outW, w2h, w2l, (size_t)BANKq * BANKq);
    gemm_bf16(sh, sl, w2h, w2l, mha_outb, pinfo, BPq, BANKq, BANKq, 0);

    // 14) of (split into ah/al)
    build_of_split_kernel<<<BPq, 256>>>(hf, tf, pinfo, validany, ah, al);

    // 15) hid = relu(of @ pred_W + pred_b)
    gemm_bf16(ah, al, wph, wpl, pred_b, hid, BPq, BANK5q, BANK5q, 1);

    // 16) fused output heads
    head_kernel<<<BPq, 256>>>(hid, mW, mb, bW, bb, out);
}

// round 9
// speedup vs baseline: 1.7883x; 1.2232x over previous
#include <cuda_runtime.h>
#include <cuda_bf16.h>
#include <math.h>
#include <stdio.h>

// ---------------- problem constants ----------------
#define Bq   4
#define Sq   512
#define Nq   256
#define Eq   42
#define Pq   256
#define Kq   3
#define Lq   4
#define HBq  768
#define DTq  20
#define DIq  20
#define Gq   256
#define NLq  2
#define Rq   97
#define NHq  4
#define D0q  808          // HB+DT+DI
#define BANKq 1576        // D0 + G*(NL+1)
#define BANK4q 6304       // 4*BANK
#define BANK5q 7880       // 5*BANK
#define DHq  394          // BANK/NH
#define Mlstm (Bq*Pq*Kq)        // 3072
#define MlstmT (Mlstm*Lq)       // 12288
#define BPq  (Bq*Pq)            // 1024

typedef __nv_bfloat16 bf16;
typedef __nv_bfloat162 bf162;

// ---------------- scratch (static device memory; no allocations allowed) ----------------
__device__ float g_enc   [Bq*Sq*D0q];
__device__ float g_feats [Bq*Nq*BANKq];
__device__ float g_tmp   [Bq*Nq*D0q];
__device__ float g_x1    [Bq*Nq*Gq];
__device__ float g_xq    [Bq*Nq*Gq];
__device__ float g_xk    [Bq*Nq*Gq];
__device__ float g_xv    [Bq*Nq*Gq];
__device__ float g_att   [Bq*Nq*Nq];
__device__ float g_ih    [(size_t)MlstmT*BANK4q];
__device__ float g_hh    [(size_t)Mlstm*BANK4q];
__device__ float g_c     [Mlstm*BANKq];
__device__ float g_hs1   [MlstmT*BANKq];
__device__ float g_hf    [BPq*BANKq];
__device__ float g_tf    [BPq*BANKq];
__device__ float g_q     [BPq*BANKq];
__device__ float g_k     [Mlstm*BANKq];
__device__ float g_v     [Mlstm*BANKq];
__device__ float g_pinfo [BPq*BANKq];
__device__ int   g_validany[BPq];
__device__ float g_hid   [BPq*BANK5q];

// bf16 split scratch
__device__ bf16 g_ah  [(size_t)MlstmT*BANKq];
__device__ bf16 g_al  [(size_t)MlstmT*BANKq];
__device__ bf16 g_sh  [(size_t)Mlstm*BANKq];
__device__ bf16 g_sl  [(size_t)Mlstm*BANKq];
__device__ bf16 g_w1h [(size_t)BANK4q*BANKq];
__device__ bf16 g_w1l [(size_t)BANK4q*BANKq];
__device__ bf16 g_w2h [(size_t)BANK4q*BANKq];
__device__ bf16 g_w2l [(size_t)BANK4q*BANKq];
__device__ bf16 g_wph [(size_t)BANK5q*BANK5q];
__device__ bf16 g_wpl [(size_t)BANK5q*BANK5q];

// ================= fp32 tiled GEMM (small GCN ops) =================
template <bool TRANSB>
__global__ void __launch_bounds__(256)
gemm32_kernel(const float* __restrict__ A, const float* __restrict__ B,
              const float* __restrict__ bias, const float* __restrict__ resid,
              float* __restrict__ C,
              int M, int N, int K,
              int lda, int ldb, int ldc, int ldr,
              long sA, long sB, long sC, long sR,
              float alpha, int act)
{
    int bz = blockIdx.z;
    A += bz * sA; B += bz * sB; C += bz * sC;
    if (resid) resid += bz * sR;

    int row0 = blockIdx.y * 32;
    int col0 = blockIdx.x * 32;

    __shared__ float As[32][33];
    __shared__ float Bs[32][33];

    int tid = threadIdx.x;
    int tx = tid & 15, ty = tid >> 4;

    float acc[2][2] = {{0.f, 0.f}, {0.f, 0.f}};

    for (int k0 = 0; k0 < K; k0 += 32) {
#pragma unroll
        for (int l = 0; l < 4; l++) {
            int idx = tid + l * 256;
            int m = idx >> 5, kk = idx & 31;
            int gr = row0 + m, gk = k0 + kk;
            As[kk][m] = (gr < M && gk < K) ? A[(long)gr * lda + gk] : 0.f;
        }
#pragma unroll
        for (int l = 0; l < 4; l++) {
            int idx = tid + l * 256;
            if (TRANSB) {
                int n = idx >> 5, kk = idx & 31;
                int gn = col0 + n, gk = k0 + kk;
                Bs[kk][n] = (gn < N && gk < K) ? B[(long)gn * ldb + gk] : 0.f;
            } else {
                int kk = idx >> 5, n = idx & 31;
                int gn = col0 + n, gk = k0 + kk;
                Bs[kk][n] = (gn < N && gk < K) ? B[(long)gk * ldb + gn] : 0.f;
            }
        }
        __syncthreads();
#pragma unroll
        for (int kk = 0; kk < 32; kk++) {
            float a0 = As[kk][ty], a1 = As[kk][ty + 16];
            float b0 = Bs[kk][tx], b1 = Bs[kk][tx + 16];
            acc[0][0] = fmaf(a0, b0, acc[0][0]);
            acc[0][1] = fmaf(a0, b1, acc[0][1]);
            acc[1][0] = fmaf(a1, b0, acc[1][0]);
            acc[1][1] = fmaf(a1, b1, acc[1][1]);
        }
        __syncthreads();
    }

#pragma unroll
    for (int i = 0; i < 2; i++) {
        int r = row0 + ty + 16 * i;
        if (r >= M) continue;
#pragma unroll
        for (int j = 0; j < 2; j++) {
            int cc = col0 + tx + 16 * j;
            if (cc >= N) continue;
            float v = acc[i][j] * alpha;
            if (bias) v += bias[cc];
            if (act == 1) v = fmaxf(v, 0.f);
            if (resid) v += resid[(long)r * ldr + cc];
            C[(long)r * ldc + cc] = v;
        }
    }
}

static void gemm(bool transB,
                 const float* A, const float* B, const float* bias, const float* resid, float* C,
                 int M, int N, int K, int lda, int ldb, int ldc, int ldr,
                 long sA, long sB, long sC, long sR, int batch, float alpha, int act)
{
    dim3 grid((N + 31) / 32, (M + 31) / 32, batch);
    if (transB)
        gemm32_kernel<true><<<grid, 256>>>(A, B, bias, resid, C, M, N, K, lda, ldb, ldc, ldr, sA, sB, sC, sR, alpha, act);
    else
        gemm32_kernel<false><<<grid, 256>>>(A, B, bias, resid, C, M, N, K, lda, ldb, ldc, ldr, sA, sB, sC, sR, alpha, act);
}

// ================= bf16 split-precision tensor-core GEMM (R6 loop, verified) =================
#define LDSB 40                    // padded row stride in bf16 (80B -> conflict-free ldmatrix)
#define GSTG 3                     // pipeline stages
#define PLANE_E (128*LDSB)         // elems per plane
#define PLANE_B (PLANE_E*2)        // bytes per plane (10240)
#define STAGE_B (4*PLANE_B)        // bytes per stage  (40960)

#define MMA_BF16(d, a, b) asm volatile( \
    "mma.sync.aligned.m16n8k16.row.col.f32.bf16.bf16.f32 " \
    "{%0,%1,%2,%3}, {%4,%5,%6,%7}, {%8,%9}, {%0,%1,%2,%3};" \
    : "+f"((d)[0]), "+f"((d)[1]), "+f"((d)[2]), "+f"((d)[3]) \
    : "r"((a)[0]), "r"((a)[1]), "r"((a)[2]), "r"((a)[3]), "r"((b)[0]), "r"((b)[1]))

#define LDSM4(r, addr) asm volatile( \
    "ldmatrix.sync.aligned.m8n8.x4.shared.b16 {%0,%1,%2,%3}, [%4];" \
    : "=r"((r)[0]), "=r"((r)[1]), "=r"((r)[2]), "=r"((r)[3]) : "r"(addr))

__device__ __forceinline__ void cpasync16(unsigned saddr, const void* g, int srcbytes)
{
    asm volatile("cp.async.cg.shared.global [%0], [%1], 16, %2;\n"
                 :: "r"(saddr), "l"(g), "r"(srcbytes));
}

__device__ __forceinline__ void gbf_prefetch(
    const bf16* __restrict__ Ah, const bf16* __restrict__ Al,
    const bf16* __restrict__ Bh, const bf16* __restrict__ Bl,
    long row0, long col0, int M, int N, int K,
    int kt, int T, unsigned sbase, int stg, int tid)
{
    if (kt >= T) return;
    long k0 = (long)kt * 32;
    unsigned sst = sbase + (unsigned)stg * STAGE_B;
#pragma unroll
    for (int i = 0; i < 2; i++) {
        int c = tid + i * 256;          // 512 chunks of 16B per plane
        int r = c >> 2;
        int ko = (c & 3) * 8;
        long gk = k0 + ko;
        bool kok = gk < K;
        long gkc = kok ? gk : 0;
        unsigned soff = (unsigned)((r * LDSB + ko) * 2);
        {
            long gr = row0 + r;
            bool ok = kok && (gr < M);
            long grc = ok ? gr : 0;
            int nb = ok ? 16 : 0;
            cpasync16(sst + soff,            Ah + grc * K + gkc, nb);
            cpasync16(sst + PLANE_B + soff,  Al + grc * K + gkc, nb);
        }
        {
            long gn = col0 + r;
            bool ok = kok && (gn < N);
            long gnc = ok ? gn : 0;
            int nb = ok ? 16 : 0;
            cpasync16(sst + 2 * PLANE_B + soff, Bh + gnc * K + gkc, nb);
            cpasync16(sst + 3 * PLANE_B + soff, Bl + gnc * K + gkc, nb);
        }
    }
}

__global__ void __launch_bounds__(256)
gemm_bf16_kernel(const bf16* __restrict__ Ah, const bf16* __restrict__ Al,
                 const bf16* __restrict__ Bh, const bf16* __restrict__ Bl,
                 const float* __restrict__ bias, float* __restrict__ C,
                 int M, int N, int K, int act)
{
    extern __shared__ __align__(16) bf16 dsm[];
    unsigned sbase = (unsigned)__cvta_generic_to_shared(dsm);

    int tid = threadIdx.x;
    int warp = tid >> 5, lane = tid & 31;
    int wm = (warp & 1) * 64;
    int wn = (warp >> 1) * 32;
    long row0 = (long)blockIdx.y * 128;
    long col0 = (long)blockIdx.x * 128;

    float acc[4][4][4];
#pragma unroll
    for (int a = 0; a < 4; a++)
#pragma unroll
        for (int b = 0; b < 4; b++)
#pragma unroll
            for (int c = 0; c < 4; c++) acc[a][b][c] = 0.f;

    int am_r = (lane & 7) + ((lane >> 3) & 1) * 8;
    int a_c8 = ((lane >> 4) & 1) * 8;
    int b_r  = (lane & 7) + ((lane >> 4) & 1) * 8;
    int b_c8 = ((lane >> 3) & 1) * 8;

    int T = (K + 31) / 32;

    // prologue: fill the pipeline
#pragma unroll
    for (int kt = 0; kt < GSTG; kt++) {
        gbf_prefetch(Ah, Al, Bh, Bl, row0, col0, M, N, K, kt, T, sbase, kt, tid);
        asm volatile("cp.async.commit_group;\n");
    }

    for (int kt = 0; kt < T; kt++) {
        asm volatile("cp.async.wait_group %0;\n" :: "n"(GSTG - 1));
        __syncthreads();

        int stg = kt % GSTG;
        unsigned sst = sbase + (unsigned)stg * STAGE_B;
        unsigned aB = sst;
        unsigned bB = sst + 2 * PLANE_B;

#pragma unroll
        for (int ks = 0; ks < 2; ks++) {
            int kb = ks * 16;
            unsigned bh[2][4], bl[2][4];
#pragma unroll
            for (int pp = 0; pp < 2; pp++) {
                unsigned addr = bB + (unsigned)(((wn + pp * 16 + b_r) * LDSB + kb + b_c8) * 2);
                LDSM4(bh[pp], addr);
                LDSM4(bl[pp], addr + PLANE_B);
            }
            unsigned ahf[4][4], alf[4][4];
#pragma unroll
            for (int mi = 0; mi < 4; mi++) {
                unsigned addr = aB + (unsigned)(((wm + mi * 16 + am_r) * LDSB + kb + a_c8) * 2);
                LDSM4(ahf[mi], addr);
                LDSM4(alf[mi], addr + PLANE_B);
            }
            // pass 1: ah*bh — 16 independent MMAs
#pragma unroll
            for (int mi = 0; mi < 4; mi++)
#pragma unroll
                for (int ni = 0; ni < 4; ni++)
                    MMA_BF16(acc[mi][ni], ahf[mi], (&bh[ni >> 1][(ni & 1) * 2]));
            // pass 2: ah*bl
#pragma unroll
            for (int mi = 0; mi < 4; mi++)
#pragma unroll
                for (int ni = 0; ni < 4; ni++)
                    MMA_BF16(acc[mi][ni], ahf[mi], (&bl[ni >> 1][(ni & 1) * 2]));
            // pass 3: al*bh
#pragma unroll
            for (int mi = 0; mi < 4; mi++)
#pragma unroll
                for (int ni = 0; ni < 4; ni++)
                    MMA_BF16(acc[mi][ni], alf[mi], (&bh[ni >> 1][(ni & 1) * 2]));
        }
        __syncthreads();
        gbf_prefetch(Ah, Al, Bh, Bl, row0, col0, M, N, K, kt + GSTG, T, sbase, stg, tid);
        asm volatile("cp.async.commit_group;\n");
    }

    // ---- epilogue ----
#pragma unroll
    for (int mi = 0; mi < 4; mi++) {
#pragma unroll
        for (int ni = 0; ni < 4; ni++) {
            long r = row0 + wm + mi * 16 + (lane >> 2);
            long c = col0 + wn + ni * 8 + (lane & 3) * 2;
#pragma unroll
            for (int half = 0; half < 2; half++) {
                long rr = r + half * 8;
                if (rr >= M) continue;
#pragma unroll
                for (int e = 0; e < 2; e++) {
                    long cc = c + e;
                    if (cc >= N) continue;
                    float v = acc[mi][ni][half * 2 + e];
                    if (bias) v += bias[cc];
                    if (act == 1) v = fmaxf(v, 0.f);
                    C[(size_t)rr * N + cc] = v;
                }
            }
        }
    }
}

static void gemm_bf16(const bf16* Ah, const bf16* Al, const bf16* Bh, const bf16* Bl,
                      const float* bias, float* C, int M, int N, int K, int act)
{
    static int attr_done = 0;
    if (!attr_done) {
        cudaFuncSetAttribute(gemm_bf16_kernel,
                             cudaFuncAttributeMaxDynamicSharedMemorySize, GSTG * STAGE_B);
        attr_done = 1;
    }
    dim3 grid((N + 127) / 128, (M + 127) / 128);
    gemm_bf16_kernel<<<grid, 256, GSTG * STAGE_B>>>(Ah, Al, Bh, Bl, bias, C, M, N, K, act);
}

// ================= conversion kernels =================
__device__ __forceinline__ void split1(float f, bf16& h, bf16& l)
{
    h = __float2bfloat16(f);
    l = __float2bfloat16(f - __bfloat162float(h));
}

__global__ void split_kernel(const float* __restrict__ x, bf16* __restrict__ hi,
                             bf16* __restrict__ lo, size_t n4)
{
    size_t i = (size_t)blockIdx.x * blockDim.x + threadIdx.x;
    if (i >= n4) return;
    float4 f = ((const float4*)x)[i];
    bf16 h0, l0, h1, l1, h2, l2, h3, l3;
    split1(f.x, h0, l0); split1(f.y, h1, l1); split1(f.z, h2, l2); split1(f.w, h3, l3);
    bf162 vh0; vh0.x = h0; vh0.y = h1;
    bf162 vh1; vh1.x = h2; vh1.y = h3;
    bf162 vl0; vl0.x = l0; vl0.y = l1;
    bf162 vl1; vl1.x = l2; vl1.y = l3;
    ((bf162*)hi)[i * 2] = vh0; ((bf162*)hi)[i * 2 + 1] = vh1;
    ((bf162*)lo)[i * 2] = vl0; ((bf162*)lo)[i * 2 + 1] = vl1;
}

static void split(const float* x, bf16* hi, bf16* lo, size_t n)
{
    size_t n4 = n / 4;
    split_kernel<<<(unsigned)((n4 + 255) / 256), 256>>>(x, hi, lo, n4);
}

__global__ void transpose_split_kernel(const float* __restrict__ B, bf16* __restrict__ Th,
                                       bf16* __restrict__ Tl, int K, int N)
{
    __shared__ float tile[32][33];
    int k0 = blockIdx.y * 32, n0 = blockIdx.x * 32;
    int tx = threadIdx.x, ty = threadIdx.y;  // 32 x 8
#pragma unroll
    for (int i = 0; i < 32; i += 8) {
        int k = k0 + ty + i, n = n0 + tx;
        tile[ty + i][tx] = (k < K && n < N) ? B[(size_t)k * N + n] : 0.f;
    }
    __syncthreads();
#pragma unroll
    for (int i = 0; i < 32; i += 8) {
        int n = n0 + ty + i, k = k0 + tx;
        if (n < N && k < K) {
            float f = tile[tx][ty + i];
            bf16 h, l; split1(f, h, l);
            Th[(size_t)n * K + k] = h;
            Tl[(size_t)n * K + k] = l;
        }
    }
}

// ---------------- fast activations (ex2/rcp fast paths, err ~1e-6) ----------------
__device__ __forceinline__ float fsig(float x)
{
    return __fdividef(1.f, 1.f + __expf(-x));
}
__device__ __forceinline__ float ftanh(float x)
{
    x = fminf(fmaxf(x, -15.f), 15.f);
    float e = __expf(-2.f * x);
    return __fdividef(1.f - e, 1.f + e);
}

// ---------------- small custom kernels ----------------
__global__ void build_enc_kernel(const float* __restrict__ eo, const int* __restrict__ etype,
                                 const int* __restrict__ eid, const float* __restrict__ temb,
                                 const float* __restrict__ iemb, float* __restrict__ enc)
{
    int bs = blockIdx.x;
    const float* src = eo + (long)bs * HBq;
    float* dst = enc + (long)bs * D0q;
    int ty = etype[bs], idv = eid[bs];
    for (int j = threadIdx.x; j < D0q; j += blockDim.x) {
        float v;
        if (j < HBq)            v = src[j];
        else if (j < HBq + DTq) v = temb[ty * DTq + (j - HBq)];
        else                    v = iemb[idv * DIq + (j - HBq - DTq)];
        dst[j] = v;
    }
}

__global__ void softmax256_kernel(float* __restrict__ x)
{
    int row = blockIdx.x;
    int tid = threadIdx.x;
    float v = x[(long)row * 256 + tid];
    __shared__ float red[8];
    int lane = tid & 31, warp = tid >> 5;
    float m = v;
#pragma unroll
    for (int o = 16; o > 0; o >>= 1) m = fmaxf(m, __shfl_xor_sync(0xffffffffu, m, o));
    if (lane == 0) red[warp] = m;
    __syncthreads();
    if (tid == 0) {
        float mm = red[0];
        for (int w = 1; w < 8; w++) mm = fmaxf(mm, red[w]);
        red[0] = mm;
    }
    __syncthreads();
    float mx = red[0];
    float e = expf(v - mx);
    float s = e;
#pragma unroll
    for (int o = 16; o > 0; o >>= 1) s += __shfl_xor_sync(0xffffffffu, s, o);
    __shared__ float red2[8];
    if (lane == 0) red2[warp] = s;
    __syncthreads();
    if (tid == 0) {
        float ss = 0.f;
        for (int w = 0; w < 8; w++) ss += red2[w];
        red2[0] = ss;
    }
    __syncthreads();
    x[(long)row * 256 + tid] = e / red2[0];
}

// gather projected rows: ih[r] = proj[b*Nq + path_nodes[r]]  (pure fp32 copy)
__global__ void gather_ih_kernel(const float* __restrict__ proj, const int* __restrict__ nodes,
                                 float* __restrict__ ih)
{
    int row = blockIdx.x;                 // 0..12287
    int b = row / (Pq * Kq * Lq);
    int node = nodes[row];
    const float4* src = (const float4*)(proj + ((size_t)(b * Nq + node)) * BANK4q);
    float4* dst = (float4*)(ih + (size_t)row * BANK4q);
    for (int j = threadIdx.x; j < BANK4q / 4; j += blockDim.x) dst[j] = src[j];
}

__global__ void lstm_cell_kernel(const float* __restrict__ ih, const float* __restrict__ hh,
                                 bf16* __restrict__ h_hi, bf16* __restrict__ h_lo,
                                 bf16* __restrict__ seq_hi, bf16* __restrict__ seq_lo,
                                 float* __restrict__ c, float* __restrict__ hs, int t)
{
    int i = blockIdx.y;
    int j = blockIdx.x * blockDim.x + threadIdx.x;
    if (j >= BANKq) return;
    const float* g = ih + ((size_t)i * Lq + t) * BANK4q;
    float gi = g[j], gf = g[BANKq + j], gg = g[2 * BANKq + j], go = g[3 * BANKq + j];
    float cp = 0.f;
    if (t > 0) {
        const float* hr = hh + (size_t)i * BANK4q;
        gi += hr[j]; gf += hr[BANKq + j]; gg += hr[2 * BANKq + j]; go += hr[3 * BANKq + j];
        cp = c[(size_t)i * BANKq + j];
    }
    float cn = fsig(gf) * cp + fsig(gi) * ftanh(gg);
    float hn = fsig(go) * ftanh(cn);
    c[(size_t)i * BANKq + j] = cn;
    bf16 h, l; split1(hn, h, l);
    h_hi[(size_t)i * BANKq + j] = h;
    h_lo[(size_t)i * BANKq + j] = l;
    if (seq_hi) {
        seq_hi[((size_t)i * Lq + t) * BANKq + j] = h;
        seq_lo[((size_t)i * Lq + t) * BANKq + j] = l;
    }
    if (hs) hs[((size_t)i * Lq + t) * BANKq + j] = hn;
}

__global__ void maxpool_split_kernel(const float* __restrict__ hs, const int* __restrict__ lens,
                                     bf16* __restrict__ hi, bf16* __restrict__ lo)
{
    int i = blockIdx.y;
    int j = blockIdx.x * blockDim.x + threadIdx.x;
    if (j >= BANKq) return;
    int len = lens[i];
    float m = -1e9f;
    const float* base = hs + (size_t)i * Lq * BANKq + j;
    for (int t = 0; t < Lq; t++)
        if (t < len) m = fmaxf(m, base[(size_t)t * BANKq]);
    float r = (len > 0) ? m : 0.f;
    bf16 h, l; split1(r, h, l);
    hi[(size_t)i * BANKq + j] = h;
    lo[(size_t)i * BANKq + j] = l;
}

__global__ void gather_ht_kernel(const float* __restrict__ feats, const int* __restrict__ htp,
                                 float* __restrict__ hf, float* __restrict__ tf,
                                 bf16* __restrict__ qh, bf16* __restrict__ ql)
{
    int bp = blockIdx.x;
    int b = bp / Pq;
    int h0 = htp[bp * 2 + 0], t0 = htp[bp * 2 + 1];
    h0 = (h0 == 0) ? 0 : h0 - 1;
    t0 = (t0 == 0) ? 0 : t0 - 1;
    const float* hsrc = feats + ((size_t)b * Nq + (Nq - Eq) + h0) * BANKq;
    const float* tsrc = feats + ((size_t)b * Nq + (Nq - Eq) + t0) * BANKq;
    for (int j = threadIdx.x; j < BANKq; j += blockDim.x) {
        float hv = hsrc[j], tv = tsrc[j];
        hf[(size_t)bp * BANKq + j] = hv;
        tf[(size_t)bp * BANKq + j] = tv;
        bf16 h, l; split1(hv - tv, h, l);
        qh[(size_t)bp * BANKq + j] = h;
        ql[(size_t)bp * BANKq + j] = l;
    }
}

__global__ void mha_attn_kernel(const float* __restrict__ q, const float* __restrict__ k,
                                const float* __restrict__ v, const int* __restrict__ plens,
                                const float* __restrict__ rmask,
                                bf16* __restrict__ ctx_hi, bf16* __restrict__ ctx_lo,
                                int* __restrict__ validany)
{
    int bp = blockIdx.x;
    int tid = threadIdx.x;
    int warp = tid >> 5, lane = tid & 31;
    __shared__ float sc[NHq][Kq];
    __shared__ float aw[NHq][Kq];
    __shared__ int vm[Kq];
    if (tid < Kq) vm[tid] = (rmask[bp] > 0.f && plens[bp * Kq + tid] > 0) ? 1 : 0;
    __syncthreads();
    {
        int h = warp / Kq, kk = warp % Kq;
        const float* qh = q + (size_t)bp * BANKq + h * DHq;
        const float* kh = k + ((size_t)bp * Kq + kk) * BANKq + h * DHq;
        float s = 0.f;
        for (int d = lane; d < DHq; d += 32) s += qh[d] * kh[d];
#pragma unroll
        for (int o = 16; o > 0; o >>= 1) s += __shfl_xor_sync(0xffffffffu, s, o);
        if (lane == 0) {
            s = s / sqrtf((float)DHq);
            sc[h][kk] = vm[kk] ? s : -1e9f;
        }
    }
    __syncthreads();
    if (tid < NHq) {
        int h = tid;
        float m = fmaxf(fmaxf(sc[h][0], sc[h][1]), sc[h][2]);
        float e0 = expf(sc[h][0] - m), e1 = expf(sc[h][1] - m), e2 = expf(sc[h][2] - m);
        float s = e0 + e1 + e2;
        aw[h][0] = e0 / s; aw[h][1] = e1 / s; aw[h][2] = e2 / s;
    }
    if (tid == 0) validany[bp] = (vm[0] | vm[1] | vm[2]);
    __syncthreads();
    for (int j = tid; j < BANKq; j += blockDim.x) {
        int h = j / DHq;
        const float* vb = v + (size_t)bp * Kq * BANKq + j;
        float r = aw[h][0] * vb[0] + aw[h][1] * vb[BANKq] + aw[h][2] * vb[2 * BANKq];
        bf16 hh2, ll2; split1(r, hh2, ll2);
        ctx_hi[(size_t)bp * BANKq + j] = hh2;
        ctx_lo[(size_t)bp * BANKq + j] = ll2;
    }
}

__global__ void build_of_split_kernel(const float* __restrict__ hf, const float* __restrict__ tf,
                                      const float* __restrict__ pinfo, const int* __restrict__ validany,
                                      bf16* __restrict__ oh, bf16* __restrict__ ol)
{
    int bp = blockIdx.x;
    int va = validany[bp];
    const float* hr = hf + (size_t)bp * BANKq;
    const float* tr = tf + (size_t)bp * BANKq;
    const float* pr = pinfo + (size_t)bp * BANKq;
    size_t base = (size_t)bp * BANK5q;
    for (int j = threadIdx.x; j < BANK5q; j += blockDim.x) {
        int seg = j / BANKq, jj = j - seg * BANKq;
        float v;
        if (seg == 0)      v = hr[jj];
        else if (seg == 1) v = tr[jj];
        else if (seg == 2) v = fabsf(hr[jj] - tr[jj]);
        else if (seg == 3) v = hr[jj] * tr[jj];
        else               v = va ? pr[jj] : 0.f;
        bf16 h, l; split1(v, h, l);
        oh[base + j] = h;
        ol[base + j] = l;
    }
}

__global__ void __launch_bounds__(256)
head_kernel(const float* __restrict__ hid, const float* __restrict__ mW,
            const float* __restrict__ mb, const float* __restrict__ bW,
            const float* __restrict__ bb, float* __restrict__ out)
{
    int m = blockIdx.x;
    __shared__ float srow[BANK5q];
    __shared__ float part[2][Rq + 2];
    const float* hr = hid + (size_t)m * BANK5q;
    for (int j = threadIdx.x; j < BANK5q; j += 256) srow[j] = hr[j];
    __syncthreads();
    int t = threadIdx.x;
    const int NT = Rq + 2;  // 99
    if (t < 2 * NT) {
        int ks = t / NT, n = t - ks * NT;
        int k0 = ks * (BANK5q / 2), k1 = k0 + BANK5q / 2;
        float acc = 0.f;
        if (n < Rq) {
#pragma unroll 8
            for (int k = k0; k < k1; k++) acc += srow[k] * mW[(size_t)k * Rq + n];
        } else {
            int nb = n - Rq;
#pragma unroll 8
            for (int k = k0; k < k1; k++) acc += srow[k] * bW[(size_t)k * 2 + nb];
        }
        part[ks][n] = acc;
    }
    __syncthreads();
    if (t < NT) {
        float v = part[0][t] + part[1][t];
        if (t < Rq) out[(size_t)m * Rq + t] = v + mb[t];
        else        out[(size_t)BPq * Rq + (size_t)m * 2 + (t - Rq)] = v + bb[t - Rq];
    }
}

// ---------------- orchestration ----------------
extern "C" void kernel_launch(void* const* d_in, const int* in_sizes, int n_in,
                              void* d_out, int out_size)
{
    const float* encoder_outputs = (const float*)d_in[0];
    const int*   entity_type     = (const int*)  d_in[1];
    const int*   entity_id       = (const int*)  d_in[2];
    const float* sub2words       = (const float*)d_in[3];
    const float* adj             = (const float*)d_in[4];
    const int*   h_t_pairs       = (const int*)  d_in[5];
    const float* rel_mask        = (const float*)d_in[6];
    const int*   path_nodes      = (const int*)  d_in[7];
    const int*   path_lens       = (const int*)  d_in[8];
    const float* type_emb        = (const float*)d_in[9];
    const float* id_emb          = (const float*)d_in[10];
    const float* gcn0_W          = (const float*)d_in[11];
    const float* gcn0_b          = (const float*)d_in[12];
    const float* gcn_W           = (const float*)d_in[13];
    const float* gcn_b           = (const float*)d_in[14];
    const float* attn_Wq         = (const float*)d_in[15];
    const float* attn_Wk         = (const float*)d_in[16];
    const float* attn_Wv         = (const float*)d_in[17];
    const float* lstm_Wih        = (const float*)d_in[18];
    const float* lstm_Whh        = (const float*)d_in[19];
    const float* lstm_b          = (const float*)d_in[20];
    const float* mha_inW         = (const float*)d_in[21];
    const float* mha_inb         = (const float*)d_in[22];
    const float* mha_outW        = (const float*)d_in[23];
    const float* mha_outb        = (const float*)d_in[24];
    const float* pred_W          = (const float*)d_in[25];
    const float* pred_b          = (const float*)d_in[26];
    const float* mW              = (const float*)d_in[27];
    const float* mb              = (const float*)d_in[28];
    const float* bW              = (const float*)d_in[29];
    const float* bb              = (const float*)d_in[30];
    float* out = (float*)d_out;

    void* p;
#define SYMF(var, sym) cudaGetSymbolAddress(&p, sym); float* var = (float*)p;
#define SYMB(var, sym) cudaGetSymbolAddress(&p, sym); bf16* var = (bf16*)p;
    SYMF(enc,   g_enc);    SYMF(feats, g_feats);  SYMF(tmp,   g_tmp);
    SYMF(x1,    g_x1);     SYMF(xq,    g_xq);     SYMF(xk,    g_xk);
    SYMF(xv,    g_xv);     SYMF(att,   g_att);
    SYMF(ih,    g_ih);     SYMF(hh,    g_hh);
    SYMF(cbuf,  g_c);      SYMF(hs1,   g_hs1);
    SYMF(hf,    g_hf);     SYMF(tf,    g_tf);
    SYMF(qb,    g_q);      SYMF(kb,    g_k);      SYMF(vb,    g_v);
    SYMF(pinfo, g_pinfo);  SYMF(hid,   g_hid);
    SYMB(ah,  g_ah);  SYMB(al,  g_al);
    SYMB(sh,  g_sh);  SYMB(sl,  g_sl);
    SYMB(w1h, g_w1h); SYMB(w1l, g_w1l);
    SYMB(w2h, g_w2h); SYMB(w2l, g_w2l);
    SYMB(wph, g_wph); SYMB(wpl, g_wpl);
    cudaGetSymbolAddress(&p, g_validany); int* validany = (int*)p;
#undef SYMF
#undef SYMB

    // 1) enc = concat(encoder_outputs, type_emb[...], id_emb[...])
    build_enc_kernel<<<Bq * Sq, 256>>>(encoder_outputs, entity_type, entity_id, type_emb, id_emb, enc);

    // 2) x0 = sub2words @ enc -> feats[:, :, 0:808]
    gemm(false, sub2words, enc, nullptr, nullptr, feats,
         Nq, D0q, Sq, Sq, D0q, BANKq, 0,
         (long)Nq * Sq, (long)Sq * D0q, (long)Nq * BANKq, 0, Bq, 1.f, 0);

    // 3) tmp = adj @ x0
    gemm(false, adj, feats, nullptr, nullptr, tmp,
         Nq, D0q, Nq, Nq, BANKq, D0q, 0,
         (long)Nq * Nq, (long)Nq * BANKq, (long)Nq * D0q, 0, Bq, 1.f, 0);

    // 4) xg0 = tmp @ gcn0_W + gcn0_b -> feats[:, :, 808:1064]
    gemm(false, tmp, gcn0_W, gcn0_b, nullptr, feats + 808,
         Nq, Gq, D0q, D0q, Gq, BANKq, 0,
         (long)Nq * D0q, 0, (long)Nq * BANKq, 0, Bq, 1.f, 0);

    // 5) GCN + graph-attention layers
    int xoff[NLq]   = {808, 1064};
    int outoff[NLq] = {1064, 1320};
    for (int l = 0; l < NLq; l++) {
        const float* x = feats + xoff[l];
        gemm(false, adj, x, nullptr, nullptr, tmp,
             Nq, Gq, Nq, Nq, BANKq, Gq, 0,
             (long)Nq * Nq, (long)Nq * BANKq, (long)Nq * Gq, 0, Bq, 1.f, 0);
        gemm(false, tmp, gcn_W + (long)l * Gq * Gq, gcn_b + l * Gq, nullptr, x1,
             Nq, Gq, Gq, Gq, Gq, Gq, 0,
             (long)Nq * Gq, 0, (long)Nq * Gq, 0, Bq, 1.f, 1);
        gemm(false, x, attn_Wq + (long)l * Gq * Gq, nullptr, nullptr, xq,
             Nq, Gq, Gq, BANKq, Gq, Gq, 0,
             (long)Nq * BANKq, 0, (long)Nq * Gq, 0, Bq, 1.f, 0);
        gemm(false, x1, attn_Wk + (long)l * Gq * Gq, nullptr, nullptr, xk,
             Nq, Gq, Gq, Gq, Gq, Gq, 0,
             (long)Nq * Gq, 0, (long)Nq * Gq, 0, Bq, 1.f, 0);
        gemm(false, x1, attn_Wv + (long)l * Gq * Gq, nullptr, nullptr, xv,
             Nq, Gq, Gq, Gq, Gq, Gq, 0,
             (long)Nq * Gq, 0, (long)Nq * Gq, 0, Bq, 1.f, 0);
        gemm(true, xq, xk, nullptr, nullptr, att,
             Nq, Nq, Gq, Gq, Gq, Nq, 0,
             (long)Nq * Gq, (long)Nq * Gq, (long)Nq * Nq, 0, Bq, 0.0625f, 0);
        softmax256_kernel<<<Bq * Nq, 256>>>(att);
        gemm(false, att, xv, nullptr, x1, feats + outoff[l],
             Nq, Gq, Nq, Nq, Gq, BANKq, Gq,
             (long)Nq * Nq, (long)Nq * Gq, (long)Nq * BANKq, (long)Nq * Gq, Bq, 1.f, 1);
    }

    // pred weight transpose-split (independent)
    {
        dim3 grid((BANK5q + 31) / 32, (BANK5q + 31) / 32);
        transpose_split_kernel<<<grid, dim3(32, 8)>>>(pred_W, wph, wpl, BANK5q, BANK5q);
    }

    // 6-7) two LSTM layers.
    // Layer 0 ih uses the gather trick: pf = gather(feats) and gather(X)@W = gather(X@W),
    // so project the 1024 distinct node rows once (12x fewer MMA MACs), then fp32-gather.
    {
        // layer 0
        const float* Wih0 = lstm_Wih;
        const float* Whh0 = lstm_Whh;
        const float* b0   = lstm_b;
        split(feats, sh, sl, (size_t)Bq * Nq * BANKq);          // 1024 node rows -> bf16 split
        split(Wih0, w1h, w1l, (size_t)BANK4q * BANKq);
        split(Whh0, w2h, w2l, (size_t)BANK4q * BANKq);
        // proj = feats @ Wih0^T + b0  (1024 x 6304), stored in hh (free until t=1)
        gemm_bf16(sh, sl, w1h, w1l, b0, hh, Bq * Nq, BANK4q, BANKq, 0);
        // ih[r] = proj[node(r)]  (pure fp32 gather, 12288 rows)
        gather_ih_kernel<<<MlstmT, 256>>>(hh, path_nodes, ih);
        for (int t = 0; t < Lq; t++) {
            if (t > 0)
                gemm_bf16(sh, sl, w2h, w2l, nullptr, hh, Mlstm, BANK4q, BANKq, 0);
            dim3 grid((BANKq + 255) / 256, Mlstm);
            lstm_cell_kernel<<<grid, 256>>>(ih, hh, sh, sl, ah, al, cbuf, nullptr, t);
        }
        // layer 1 (inputs are distinct hidden states; standard path)
        const float* Wih1 = lstm_Wih + (size_t)BANK4q * BANKq;
        const float* Whh1 = lstm_Whh + (size_t)BANK4q * BANKq;
        const float* b1   = lstm_b + BANK4q;
        split(Wih1, w1h, w1l, (size_t)BANK4q * BANKq);
        split(Whh1, w2h, w2l, (size_t)BANK4q * BANKq);
        gemm_bf16(ah, al, w1h, w1l, b1, ih, MlstmT, BANK4q, BANKq, 0);
        for (int t = 0; t < Lq; t++) {
            if (t > 0)
                gemm_bf16(sh, sl, w2h, w2l, nullptr, hh, Mlstm, BANK4q, BANKq, 0);
            dim3 grid((BANKq + 255) / 256, Mlstm);
            lstm_cell_kernel<<<grid, 256>>>(ih, hh, sh, sl, nullptr, nullptr, cbuf, hs1, t);
        }
    }

    // 8) masked max-pool over time -> split bf16 (ah/al reused)
    {
        dim3 grid((BANKq + 255) / 256, Mlstm);
        maxpool_split_kernel<<<grid, 256>>>(hs1, path_lens, ah, al);
    }

    // 9) h_f, t_f, query (split)
    gather_ht_kernel<<<BPq, 256>>>(feats, h_t_pairs, hf, tf, sh, sl);

    // 10-11) q/k/v projections
    split(mha_inW, w1h, w1l, (size_t)3 * BANKq * BANKq);
    gemm_bf16(sh, sl, w1h, w1l, mha_inb, qb, BPq, BANKq, BANKq, 0);
    gemm_bf16(ah, al, w1h + (size_t)BANKq * BANKq, w1l + (size_t)BANKq * BANKq,
              mha_inb + BANKq, kb, Mlstm, BANKq, BANKq, 0);
    gemm_bf16(ah, al, w1h + 2 * (size_t)BANKq * BANKq, w1l + 2 * (size_t)BANKq * BANKq,
              mha_inb + 2 * BANKq, vb, Mlstm, BANKq, BANKq, 0);

    // 12) tiny attention over K=3 paths (ctx split into sh/sl)
    mha_attn_kernel<<<BPq, 384>>>(qb, kb, vb, path_lens, rel_mask, sh, sl, validany);

    // 13) pinfo = ctx @ mha_outW^T + mha_outb
    split(mha_outW, w2h, w2l, (size_t)BANKq * BANKq);
    gemm_bf16(sh, sl, w2h, w2l, mha_outb, pinfo, BPq, BANKq, BANKq, 0);

    // 14) of (split into ah/al)
    build_of_split_kernel<<<BPq, 256>>>(hf, tf, pinfo, validany, ah, al);

    // 15) hid = relu(of @ pred_W + pred_b)
    gemm_bf16(ah, al, wph, wpl, pred_b, hid, BPq, BANK5q, BANK5q, 1);

    // 16) fused output heads
    head_kernel<<<BPq, 256>>>(hid, mW, mb, bW, bb, out);
}

// round 10
// speedup vs baseline: 2.0187x; 1.1288x over previous
#include <cuda_runtime.h>
#include <cuda_bf16.h>
#include <math.h>
#include <stdio.h>

// ---------------- problem constants ----------------
#define Bq   4
#define Sq   512
#define Nq   256
#define Eq   42
#define Pq   256
#define Kq   3
#define Lq   4
#define HBq  768
#define DTq  20
#define DIq  20
#define Gq   256
#define NLq  2
#define Rq   97
#define NHq  4
#define D0q  808          // HB+DT+DI
#define BANKq 1576        // D0 + G*(NL+1)
#define BANK4q 6304       // 4*BANK
#define BANK5q 7880       // 5*BANK
#define DHq  394          // BANK/NH
#define Mlstm (Bq*Pq*Kq)        // 3072
#define MlstmT (Mlstm*Lq)       // 12288
#define BPq  (Bq*Pq)            // 1024

typedef __nv_bfloat16 bf16;
typedef __nv_bfloat162 bf162;

// ---------------- scratch (static device memory; no allocations allowed) ----------------
__device__ float g_enc   [Bq*Sq*D0q];
__device__ float g_feats [Bq*Nq*BANKq];
__device__ float g_tmp   [Bq*Nq*D0q];
__device__ float g_x1    [Bq*Nq*Gq];
__device__ float g_xq    [Bq*Nq*Gq];
__device__ float g_xk    [Bq*Nq*Gq];
__device__ float g_xv    [Bq*Nq*Gq];
__device__ float g_att   [Bq*Nq*Nq];
__device__ float g_ih    [(size_t)MlstmT*BANK4q];
__device__ float g_hh    [(size_t)Mlstm*BANK4q];
__device__ float g_c     [Mlstm*BANKq];
__device__ float g_hs1   [MlstmT*BANKq];          // t-major: row t*Mlstm+i
__device__ float g_hf    [BPq*BANKq];
__device__ float g_tf    [BPq*BANKq];
__device__ float g_q     [BPq*BANKq];             // qb; doubles as ccand during LSTM
__device__ float g_k     [Mlstm*BANKq];
__device__ float g_v     [Mlstm*BANKq];
__device__ float g_pinfo [BPq*BANKq];
__device__ int   g_validany[BPq];
__device__ float g_hid   [BPq*BANK5q];            // also hhproj/ihproj0 scratch

// bf16 split scratch
__device__ bf16 g_ah  [(size_t)MlstmT*BANKq];     // layer-0 h sequence, t-major
__device__ bf16 g_al  [(size_t)MlstmT*BANKq];
__device__ bf16 g_sh  [(size_t)Mlstm*BANKq];
__device__ bf16 g_sl  [(size_t)Mlstm*BANKq];
__device__ bf16 g_hch [(size_t)BPq*BANKq];        // candidate h (1024 distinct rows)
__device__ bf16 g_hcl [(size_t)BPq*BANKq];
__device__ bf16 g_w1h [(size_t)BANK4q*BANKq];
__device__ bf16 g_w1l [(size_t)BANK4q*BANKq];
__device__ bf16 g_w2h [(size_t)BANK4q*BANKq];
__device__ bf16 g_w2l [(size_t)BANK4q*BANKq];
__device__ bf16 g_wph [(size_t)BANK5q*BANK5q];
__device__ bf16 g_wpl [(size_t)BANK5q*BANK5q];

// ================= fp32 tiled GEMM (small GCN ops) =================
template <bool TRANSB>
__global__ void __launch_bounds__(256)
gemm32_kernel(const float* __restrict__ A, const float* __restrict__ B,
              const float* __restrict__ bias, const float* __restrict__ resid,
              float* __restrict__ C,
              int M, int N, int K,
              int lda, int ldb, int ldc, int ldr,
              long sA, long sB, long sC, long sR,
              float alpha, int act)
{
    int bz = blockIdx.z;
    A += bz * sA; B += bz * sB; C += bz * sC;
    if (resid) resid += bz * sR;

    int row0 = blockIdx.y * 32;
    int col0 = blockIdx.x * 32;

    __shared__ float As[32][33];
    __shared__ float Bs[32][33];

    int tid = threadIdx.x;
    int tx = tid & 15, ty = tid >> 4;

    float acc[2][2] = {{0.f, 0.f}, {0.f, 0.f}};

    for (int k0 = 0; k0 < K; k0 += 32) {
#pragma unroll
        for (int l = 0; l < 4; l++) {
            int idx = tid + l * 256;
            int m = idx >> 5, kk = idx & 31;
            int gr = row0 + m, gk = k0 + kk;
            As[kk][m] = (gr < M && gk < K) ? A[(long)gr * lda + gk] : 0.f;
        }
#pragma unroll
        for (int l = 0; l < 4; l++) {
            int idx = tid + l * 256;
            if (TRANSB) {
                int n = idx >> 5, kk = idx & 31;
                int gn = col0 + n, gk = k0 + kk;
                Bs[kk][n] = (gn < N && gk < K) ? B[(long)gn * ldb + gk] : 0.f;
            } else {
                int kk = idx >> 5, n = idx & 31;
                int gn = col0 + n, gk = k0 + kk;
                Bs[kk][n] = (gn < N && gk < K) ? B[(long)gk * ldb + gn] : 0.f;
            }
        }
        __syncthreads();
#pragma unroll
        for (int kk = 0; kk < 32; kk++) {
            float a0 = As[kk][ty], a1 = As[kk][ty + 16];
            float b0 = Bs[kk][tx], b1 = Bs[kk][tx + 16];
            acc[0][0] = fmaf(a0, b0, acc[0][0]);
            acc[0][1] = fmaf(a0, b1, acc[0][1]);
            acc[1][0] = fmaf(a1, b0, acc[1][0]);
            acc[1][1] = fmaf(a1, b1, acc[1][1]);
        }
        __syncthreads();
    }

#pragma unroll
    for (int i = 0; i < 2; i++) {
        int r = row0 + ty + 16 * i;
        if (r >= M) continue;
#pragma unroll
        for (int j = 0; j < 2; j++) {
            int cc = col0 + tx + 16 * j;
            if (cc >= N) continue;
            float v = acc[i][j] * alpha;
            if (bias) v += bias[cc];
            if (act == 1) v = fmaxf(v, 0.f);
            if (resid) v += resid[(long)r * ldr + cc];
            C[(long)r * ldc + cc] = v;
        }
    }
}

static void gemm(bool transB,
                 const float* A, const float* B, const float* bias, const float* resid, float* C,
                 int M, int N, int K, int lda, int ldb, int ldc, int ldr,
                 long sA, long sB, long sC, long sR, int batch, float alpha, int act)
{
    dim3 grid((N + 31) / 32, (M + 31) / 32, batch);
    if (transB)
        gemm32_kernel<true><<<grid, 256>>>(A, B, bias, resid, C, M, N, K, lda, ldb, ldc, ldr, sA, sB, sC, sR, alpha, act);
    else
        gemm32_kernel<false><<<grid, 256>>>(A, B, bias, resid, C, M, N, K, lda, ldb, ldc, ldr, sA, sB, sC, sR, alpha, act);
}

// ================= bf16 split-precision tensor-core GEMM (verified R6 loop) =================
#define LDSB 40
#define GSTG 3
#define PLANE_E (128*LDSB)
#define PLANE_B (PLANE_E*2)
#define STAGE_B (4*PLANE_B)

#define MMA_BF16(d, a, b) asm volatile( \
    "mma.sync.aligned.m16n8k16.row.col.f32.bf16.bf16.f32 " \
    "{%0,%1,%2,%3}, {%4,%5,%6,%7}, {%8,%9}, {%0,%1,%2,%3};" \
    : "+f"((d)[0]), "+f"((d)[1]), "+f"((d)[2]), "+f"((d)[3]) \
    : "r"((a)[0]), "r"((a)[1]), "r"((a)[2]), "r"((a)[3]), "r"((b)[0]), "r"((b)[1]))

#define LDSM4(r, addr) asm volatile( \
    "ldmatrix.sync.aligned.m8n8.x4.shared.b16 {%0,%1,%2,%3}, [%4];" \
    : "=r"((r)[0]), "=r"((r)[1]), "=r"((r)[2]), "=r"((r)[3]) : "r"(addr))

__device__ __forceinline__ void cpasync16(unsigned saddr, const void* g, int srcbytes)
{
    asm volatile("cp.async.cg.shared.global [%0], [%1], 16, %2;\n"
                 :: "r"(saddr), "l"(g), "r"(srcbytes));
}

__device__ __forceinline__ void gbf_prefetch(
    const bf16* __restrict__ Ah, const bf16* __restrict__ Al,
    const bf16* __restrict__ Bh, const bf16* __restrict__ Bl,
    long row0, long col0, int M, int N, int K,
    int kt, int T, unsigned sbase, int stg, int tid)
{
    if (kt >= T) return;
    long k0 = (long)kt * 32;
    unsigned sst = sbase + (unsigned)stg * STAGE_B;
#pragma unroll
    for (int i = 0; i < 2; i++) {
        int c = tid + i * 256;
        int r = c >> 2;
        int ko = (c & 3) * 8;
        long gk = k0 + ko;
        bool kok = gk < K;
        long gkc = kok ? gk : 0;
        unsigned soff = (unsigned)((r * LDSB + ko) * 2);
        {
            long gr = row0 + r;
            bool ok = kok && (gr < M);
            long grc = ok ? gr : 0;
            int nb = ok ? 16 : 0;
            cpasync16(sst + soff,            Ah + grc * K + gkc, nb);
            cpasync16(sst + PLANE_B + soff,  Al + grc * K + gkc, nb);
        }
        {
            long gn = col0 + r;
            bool ok = kok && (gn < N);
            long gnc = ok ? gn : 0;
            int nb = ok ? 16 : 0;
            cpasync16(sst + 2 * PLANE_B + soff, Bh + gnc * K + gkc, nb);
            cpasync16(sst + 3 * PLANE_B + soff, Bl + gnc * K + gkc, nb);
        }
    }
}

__global__ void __launch_bounds__(256)
gemm_bf16_kernel(const bf16* __restrict__ Ah, const bf16* __restrict__ Al,
                 const bf16* __restrict__ Bh, const bf16* __restrict__ Bl,
                 const float* __restrict__ bias, float* __restrict__ C,
                 int M, int N, int K, int act)
{
    extern __shared__ __align__(16) bf16 dsm[];
    unsigned sbase = (unsigned)__cvta_generic_to_shared(dsm);

    int tid = threadIdx.x;
    int warp = tid >> 5, lane = tid & 31;
    int wm = (warp & 1) * 64;
    int wn = (warp >> 1) * 32;
    long row0 = (long)blockIdx.y * 128;
    long col0 = (long)blockIdx.x * 128;

    float acc[4][4][4];
#pragma unroll
    for (int a = 0; a < 4; a++)
#pragma unroll
        for (int b = 0; b < 4; b++)
#pragma unroll
            for (int c = 0; c < 4; c++) acc[a][b][c] = 0.f;

    int am_r = (lane & 7) + ((lane >> 3) & 1) * 8;
    int a_c8 = ((lane >> 4) & 1) * 8;
    int b_r  = (lane & 7) + ((lane >> 4) & 1) * 8;
    int b_c8 = ((lane >> 3) & 1) * 8;

    int T = (K + 31) / 32;

#pragma unroll
    for (int kt = 0; kt < GSTG; kt++) {
        gbf_prefetch(Ah, Al, Bh, Bl, row0, col0, M, N, K, kt, T, sbase, kt, tid);
        asm volatile("cp.async.commit_group;\n");
    }

    for (int kt = 0; kt < T; kt++) {
        asm volatile("cp.async.wait_group %0;\n" :: "n"(GSTG - 1));
        __syncthreads();

        int stg = kt % GSTG;
        unsigned sst = sbase + (unsigned)stg * STAGE_B;
        unsigned aB = sst;
        unsigned bB = sst + 2 * PLANE_B;

#pragma unroll
        for (int ks = 0; ks < 2; ks++) {
            int kb = ks * 16;
            unsigned bh[2][4], bl[2][4];
#pragma unroll
            for (int pp = 0; pp < 2; pp++) {
                unsigned addr = bB + (unsigned)(((wn + pp * 16 + b_r) * LDSB + kb + b_c8) * 2);
                LDSM4(bh[pp], addr);
                LDSM4(bl[pp], addr + PLANE_B);
            }
            unsigned ahf[4][4], alf[4][4];
#pragma unroll
            for (int mi = 0; mi < 4; mi++) {
                unsigned addr = aB + (unsigned)(((wm + mi * 16 + am_r) * LDSB + kb + a_c8) * 2);
                LDSM4(ahf[mi], addr);
                LDSM4(alf[mi], addr + PLANE_B);
            }
#pragma unroll
            for (int mi = 0; mi < 4; mi++)
#pragma unroll
                for (int ni = 0; ni < 4; ni++)
                    MMA_BF16(acc[mi][ni], ahf[mi], (&bh[ni >> 1][(ni & 1) * 2]));
#pragma unroll
            for (int mi = 0; mi < 4; mi++)
#pragma unroll
                for (int ni = 0; ni < 4; ni++)
                    MMA_BF16(acc[mi][ni], ahf[mi], (&bl[ni >> 1][(ni & 1) * 2]));
#pragma unroll
            for (int mi = 0; mi < 4; mi++)
#pragma unroll
                for (int ni = 0; ni < 4; ni++)
                    MMA_BF16(acc[mi][ni], alf[mi], (&bh[ni >> 1][(ni & 1) * 2]));
        }
        __syncthreads();
        gbf_prefetch(Ah, Al, Bh, Bl, row0, col0, M, N, K, kt + GSTG, T, sbase, stg, tid);
        asm volatile("cp.async.commit_group;\n");
    }

#pragma unroll
    for (int mi = 0; mi < 4; mi++) {
#pragma unroll
        for (int ni = 0; ni < 4; ni++) {
            long r = row0 + wm + mi * 16 + (lane >> 2);
            long c = col0 + wn + ni * 8 + (lane & 3) * 2;
#pragma unroll
            for (int half = 0; half < 2; half++) {
                long rr = r + half * 8;
                if (rr >= M) continue;
#pragma unroll
                for (int e = 0; e < 2; e++) {
                    long cc = c + e;
                    if (cc >= N) continue;
                    float v = acc[mi][ni][half * 2 + e];
                    if (bias) v += bias[cc];
                    if (act == 1) v = fmaxf(v, 0.f);
                    C[(size_t)rr * N + cc] = v;
                }
            }
        }
    }
}

static void gemm_bf16(const bf16* Ah, const bf16* Al, const bf16* Bh, const bf16* Bl,
                      const float* bias, float* C, int M, int N, int K, int act)
{
    static int attr_done = 0;
    if (!attr_done) {
        cudaFuncSetAttribute(gemm_bf16_kernel,
                             cudaFuncAttributeMaxDynamicSharedMemorySize, GSTG * STAGE_B);
        attr_done = 1;
    }
    dim3 grid((N + 127) / 128, (M + 127) / 128);
    gemm_bf16_kernel<<<grid, 256, GSTG * STAGE_B>>>(Ah, Al, Bh, Bl, bias, C, M, N, K, act);
}

// ================= conversion kernels =================
__device__ __forceinline__ void split1(float f, bf16& h, bf16& l)
{
    h = __float2bfloat16(f);
    l = __float2bfloat16(f - __bfloat162float(h));
}

__global__ void split_kernel(const float* __restrict__ x, bf16* __restrict__ hi,
                             bf16* __restrict__ lo, size_t n4)
{
    size_t i = (size_t)blockIdx.x * blockDim.x + threadIdx.x;
    if (i >= n4) return;
    float4 f = ((const float4*)x)[i];
    bf16 h0, l0, h1, l1, h2, l2, h3, l3;
    split1(f.x, h0, l0); split1(f.y, h1, l1); split1(f.z, h2, l2); split1(f.w, h3, l3);
    bf162 vh0; vh0.x = h0; vh0.y = h1;
    bf162 vh1; vh1.x = h2; vh1.y = h3;
    bf162 vl0; vl0.x = l0; vl0.y = l1;
    bf162 vl1; vl1.x = l2; vl1.y = l3;
    ((bf162*)hi)[i * 2] = vh0; ((bf162*)hi)[i * 2 + 1] = vh1;
    ((bf162*)lo)[i * 2] = vl0; ((bf162*)lo)[i * 2 + 1] = vl1;
}

static void split(const float* x, bf16* hi, bf16* lo, size_t n)
{
    size_t n4 = n / 4;
    split_kernel<<<(unsigned)((n4 + 255) / 256), 256>>>(x, hi, lo, n4);
}

__global__ void transpose_split_kernel(const float* __restrict__ B, bf16* __restrict__ Th,
                                       bf16* __restrict__ Tl, int K, int N)
{
    __shared__ float tile[32][33];
    int k0 = blockIdx.y * 32, n0 = blockIdx.x * 32;
    int tx = threadIdx.x, ty = threadIdx.y;  // 32 x 8
#pragma unroll
    for (int i = 0; i < 32; i += 8) {
        int k = k0 + ty + i, n = n0 + tx;
        tile[ty + i][tx] = (k < K && n < N) ? B[(size_t)k * N + n] : 0.f;
    }
    __syncthreads();
#pragma unroll
    for (int i = 0; i < 32; i += 8) {
        int n = n0 + ty + i, k = k0 + tx;
        if (n < N && k < K) {
            float f = tile[tx][ty + i];
            bf16 h, l; split1(f, h, l);
            Th[(size_t)n * K + k] = h;
            Tl[(size_t)n * K + k] = l;
        }
    }
}

// ---------------- fast activations ----------------
__device__ __forceinline__ float fsig(float x)
{
    return __fdividef(1.f, 1.f + __expf(-x));
}
__device__ __forceinline__ float ftanh(float x)
{
    x = fminf(fmaxf(x, -15.f), 15.f);
    float e = __expf(-2.f * x);
    return __fdividef(1.f - e, 1.f + e);
}

// ---------------- small custom kernels ----------------
__global__ void build_enc_kernel(const float* __restrict__ eo, const int* __restrict__ etype,
                                 const int* __restrict__ eid, const float* __restrict__ temb,
                                 const float* __restrict__ iemb, float* __restrict__ enc)
{
    int bs = blockIdx.x;
    const float* src = eo + (long)bs * HBq;
    float* dst = enc + (long)bs * D0q;
    int ty = etype[bs], idv = eid[bs];
    for (int j = threadIdx.x; j < D0q; j += blockDim.x) {
        float v;
        if (j < HBq)            v = src[j];
        else if (j < HBq + DTq) v = temb[ty * DTq + (j - HBq)];
        else                    v = iemb[idv * DIq + (j - HBq - DTq)];
        dst[j] = v;
    }
}

__global__ void softmax256_kernel(float* __restrict__ x)
{
    int row = blockIdx.x;
    int tid = threadIdx.x;
    float v = x[(long)row * 256 + tid];
    __shared__ float red[8];
    int lane = tid & 31, warp = tid >> 5;
    float m = v;
#pragma unroll
    for (int o = 16; o > 0; o >>= 1) m = fmaxf(m, __shfl_xor_sync(0xffffffffu, m, o));
    if (lane == 0) red[warp] = m;
    __syncthreads();
    if (tid == 0) {
        float mm = red[0];
        for (int w = 1; w < 8; w++) mm = fmaxf(mm, red[w]);
        red[0] = mm;
    }
    __syncthreads();
    float mx = red[0];
    float e = expf(v - mx);
    float s = e;
#pragma unroll
    for (int o = 16; o > 0; o >>= 1) s += __shfl_xor_sync(0xffffffffu, s, o);
    __shared__ float red2[8];
    if (lane == 0) red2[warp] = s;
    __syncthreads();
    if (tid == 0) {
        float ss = 0.f;
        for (int w = 0; w < 8; w++) ss += red2[w];
        red2[0] = ss;
    }
    __syncthreads();
    x[(long)row * 256 + tid] = e / red2[0];
}

// layer-0 ih gather, t-major: ih[t*Mlstm+i] = proj[b*Nq + node(i,t)]
__global__ void gather_ih_l0_kernel(const float* __restrict__ proj, const int* __restrict__ nodes,
                                    float* __restrict__ ih)
{
    int r = blockIdx.x;                   // 0..12287 (t-major)
    int t = r / Mlstm, i = r - t * Mlstm;
    int b = i / (Pq * Kq);
    int node = nodes[i * Lq + t];
    const float4* src = (const float4*)(proj + ((size_t)(b * Nq + node)) * BANK4q);
    float4* dst = (float4*)(ih + (size_t)r * BANK4q);
    for (int j = threadIdx.x; j < BANK4q / 4; j += blockDim.x) dst[j] = src[j];
}

// generic 6304-wide row gather via node0: dst[i] = src[b*Nq + node(i,0)]
__global__ void gather_w64_kernel(const float* __restrict__ src, const int* __restrict__ nodes,
                                  float* __restrict__ dst)
{
    int i = blockIdx.x;                   // 0..3071
    int b = i / (Pq * Kq);
    int node = nodes[i * Lq];
    const float4* s = (const float4*)(src + ((size_t)(b * Nq + node)) * BANK4q);
    float4* d = (float4*)(dst + (size_t)i * BANK4q);
    for (int j = threadIdx.x; j < BANK4q / 4; j += blockDim.x) d[j] = s[j];
}

// t=0 candidate cell: 1024 rows, c=0
__global__ void cand_cell_kernel(const float* __restrict__ proj, float* __restrict__ ccand,
                                 bf16* __restrict__ hch, bf16* __restrict__ hcl)
{
    int i = blockIdx.y;                   // 0..1023
    int j = blockIdx.x * blockDim.x + threadIdx.x;
    if (j >= BANKq) return;
    const float* g = proj + (size_t)i * BANK4q;
    float gi = g[j], gg = g[2 * BANKq + j], go = g[3 * BANKq + j];
    float cn = fsig(gi) * ftanh(gg);
    float hn = fsig(go) * ftanh(cn);
    ccand[(size_t)i * BANKq + j] = cn;
    bf16 h, l; split1(hn, h, l);
    hch[(size_t)i * BANKq + j] = h;
    hcl[(size_t)i * BANKq + j] = l;
}

// distribute candidates to the 3072 rows: running h/c, plus seq (bf16, layer0) or hs (float, layer1)
__global__ void gather0_kernel(const bf16* __restrict__ hch, const bf16* __restrict__ hcl,
                               const float* __restrict__ ccand, const int* __restrict__ nodes,
                               bf16* __restrict__ sh, bf16* __restrict__ sl,
                               float* __restrict__ c,
                               bf16* __restrict__ seq_hi, bf16* __restrict__ seq_lo,
                               float* __restrict__ hs)
{
    int i = blockIdx.x;                   // 0..3071
    int b = i / (Pq * Kq);
    size_t idx = ((size_t)(b * Nq + nodes[i * Lq])) * BANKq;
    size_t dst = (size_t)i * BANKq;
    for (int j = threadIdx.x; j < BANKq; j += blockDim.x) {
        bf16 h = hch[idx + j], l = hcl[idx + j];
        sh[dst + j] = h;
        sl[dst + j] = l;
        c[dst + j] = ccand[idx + j];
        if (seq_hi) { seq_hi[dst + j] = h; seq_lo[dst + j] = l; }
        if (hs) hs[dst + j] = __bfloat162float(h) + __bfloat162float(l);
    }
}

// LSTM cell for t >= 1 (t-major ih/seq/hs layouts)
__global__ void lstm_cell_kernel(const float* __restrict__ ih, const float* __restrict__ hh,
                                 bf16* __restrict__ h_hi, bf16* __restrict__ h_lo,
                                 bf16* __restrict__ seq_hi, bf16* __restrict__ seq_lo,
                                 float* __restrict__ c, float* __restrict__ hs, int t)
{
    int i = blockIdx.y;
    int j = blockIdx.x * blockDim.x + threadIdx.x;
    if (j >= BANKq) return;
    const float* g = ih + ((size_t)t * Mlstm + i) * BANK4q;
    const float* hr = hh + (size_t)i * BANK4q;
    float gi = g[j] + hr[j];
    float gf = g[BANKq + j] + hr[BANKq + j];
    float gg = g[2 * BANKq + j] + hr[2 * BANKq + j];
    float go = g[3 * BANKq + j] + hr[3 * BANKq + j];
    float cp = c[(size_t)i * BANKq + j];
    float cn = fsig(gf) * cp + fsig(gi) * ftanh(gg);
    float hn = fsig(go) * ftanh(cn);
    c[(size_t)i * BANKq + j] = cn;
    bf16 h, l; split1(hn, h, l);
    h_hi[(size_t)i * BANKq + j] = h;
    h_lo[(size_t)i * BANKq + j] = l;
    if (seq_hi) {
        seq_hi[((size_t)t * Mlstm + i) * BANKq + j] = h;
        seq_lo[((size_t)t * Mlstm + i) * BANKq + j] = l;
    }
    if (hs) hs[((size_t)t * Mlstm + i) * BANKq + j] = hn;
}

// masked max-pool over time (t-major hs)
__global__ void maxpool_split_kernel(const float* __restrict__ hs, const int* __restrict__ lens,
                                     bf16* __restrict__ hi, bf16* __restrict__ lo)
{
    int i = blockIdx.y;
    int j = blockIdx.x * blockDim.x + threadIdx.x;
    if (j >= BANKq) return;
    int len = lens[i];
    float m = -1e9f;
    const float* base = hs + (size_t)i * BANKq + j;
    for (int t = 0; t < Lq; t++)
        if (t < len) m = fmaxf(m, base[(size_t)t * Mlstm * BANKq]);
    float r = (len > 0) ? m : 0.f;
    bf16 h, l; split1(r, h, l);
    hi[(size_t)i * BANKq + j] = h;
    lo[(size_t)i * BANKq + j] = l;
}

__global__ void gather_ht_kernel(const float* __restrict__ feats, const int* __restrict__ htp,
                                 float* __restrict__ hf, float* __restrict__ tf,
                                 bf16* __restrict__ qh, bf16* __restrict__ ql)
{
    int bp = blockIdx.x;
    int b = bp / Pq;
    int h0 = htp[bp * 2 + 0], t0 = htp[bp * 2 + 1];
    h0 = (h0 == 0) ? 0 : h0 - 1;
    t0 = (t0 == 0) ? 0 : t0 - 1;
    const float* hsrc = feats + ((size_t)b * Nq + (Nq - Eq) + h0) * BANKq;
    const float* tsrc = feats + ((size_t)b * Nq + (Nq - Eq) + t0) * BANKq;
    for (int j = threadIdx.x; j < BANKq; j += blockDim.x) {
        float hv = hsrc[j], tv = tsrc[j];
        hf[(size_t)bp * BANKq + j] = hv;
        tf[(size_t)bp * BANKq + j] = tv;
        bf16 h, l; split1(hv - tv, h, l);
        qh[(size_t)bp * BANKq + j] = h;
        ql[(size_t)bp * BANKq + j] = l;
    }
}

__global__ void mha_attn_kernel(const float* __restrict__ q, const float* __restrict__ k,
                                const float* __restrict__ v, const int* __restrict__ plens,
                                const float* __restrict__ rmask,
                                bf16* __restrict__ ctx_hi, bf16* __restrict__ ctx_lo,
                                int* __restrict__ validany)
{
    int bp = blockIdx.x;
    int tid = threadIdx.x;
    int warp = tid >> 5, lane = tid & 31;
    __shared__ float sc[NHq][Kq];
    __shared__ float aw[NHq][Kq];
    __shared__ int vm[Kq];
    if (tid < Kq) vm[tid] = (rmask[bp] > 0.f && plens[bp * Kq + tid] > 0) ? 1 : 0;
    __syncthreads();
    {
        int h = warp / Kq, kk = warp % Kq;
        const float* qh = q + (size_t)bp * BANKq + h * DHq;
        const float* kh = k + ((size_t)bp * Kq + kk) * BANKq + h * DHq;
        float s = 0.f;
        for (int d = lane; d < DHq; d += 32) s += qh[d] * kh[d];
#pragma unroll
        for (int o = 16; o > 0; o >>= 1) s += __shfl_xor_sync(0xffffffffu, s, o);
        if (lane == 0) {
            s = s / sqrtf((float)DHq);
            sc[h][kk] = vm[kk] ? s : -1e9f;
        }
    }
    __syncthreads();
    if (tid < NHq) {
        int h = tid;
        float m = fmaxf(fmaxf(sc[h][0], sc[h][1]), sc[h][2]);
        float e0 = expf(sc[h][0] - m), e1 = expf(sc[h][1] - m), e2 = expf(sc[h][2] - m);
        float s = e0 + e1 + e2;
        aw[h][0] = e0 / s; aw[h][1] = e1 / s; aw[h][2] = e2 / s;
    }
    if (tid == 0) validany[bp] = (vm[0] | vm[1] | vm[2]);
    __syncthreads();
    for (int j = tid; j < BANKq; j += blockDim.x) {
        int h = j / DHq;
        const float* vb = v + (size_t)bp * Kq * BANKq + j;
        float r = aw[h][0] * vb[0] + aw[h][1] * vb[BANKq] + aw[h][2] * vb[2 * BANKq];
        bf16 hh2, ll2; split1(r, hh2, ll2);
        ctx_hi[(size_t)bp * BANKq + j] = hh2;
        ctx_lo[(size_t)bp * BANKq + j] = ll2;
    }
}

__global__ void build_of_split_kernel(const float* __restrict__ hf, const float* __restrict__ tf,
                                      const float* __restrict__ pinfo, const int* __restrict__ validany,
                                      bf16* __restrict__ oh, bf16* __restrict__ ol)
{
    int bp = blockIdx.x;
    int va = validany[bp];
    const float* hr = hf + (size_t)bp * BANKq;
    const float* tr = tf + (size_t)bp * BANKq;
    const float* pr = pinfo + (size_t)bp * BANKq;
    size_t base = (size_t)bp * BANK5q;
    for (int j = threadIdx.x; j < BANK5q; j += blockDim.x) {
        int seg = j / BANKq, jj = j - seg * BANKq;
        float v;
        if (seg == 0)      v = hr[jj];
        else if (seg == 1) v = tr[jj];
        else if (seg == 2) v = fabsf(hr[jj] - tr[jj]);
        else if (seg == 3) v = hr[jj] * tr[jj];
        else               v = va ? pr[jj] : 0.f;
        bf16 h, l; split1(v, h, l);
        oh[base + j] = h;
        ol[base + j] = l;
    }
}

__global__ void __launch_bounds__(256)
head_kernel(const float* __restrict__ hid, const float* __restrict__ mW,
            const float* __restrict__ mb, const float* __restrict__ bW,
            const float* __restrict__ bb, float* __restrict__ out)
{
    int m = blockIdx.x;
    __shared__ float srow[BANK5q];
    __shared__ float part[2][Rq + 2];
    const float* hr = hid + (size_t)m * BANK5q;
    for (int j = threadIdx.x; j < BANK5q; j += 256) srow[j] = hr[j];
    __syncthreads();
    int t = threadIdx.x;
    const int NT = Rq + 2;  // 99
    if (t < 2 * NT) {
        int ks = t / NT, n = t - ks * NT;
        int k0 = ks * (BANK5q / 2), k1 = k0 + BANK5q / 2;
        float acc = 0.f;
        if (n < Rq) {
#pragma unroll 8
            for (int k = k0; k < k1; k++) acc += srow[k] * mW[(size_t)k * Rq + n];
        } else {
            int nb = n - Rq;
#pragma unroll 8
            for (int k = k0; k < k1; k++) acc += srow[k] * bW[(size_t)k * 2 + nb];
        }
        part[ks][n] = acc;
    }
    __syncthreads();
    if (t < NT) {
        float v = part[0][t] + part[1][t];
        if (t < Rq) out[(size_t)m * Rq + t] = v + mb[t];
        else        out[(size_t)BPq * Rq + (size_t)m * 2 + (t - Rq)] = v + bb[t - Rq];
    }
}

// ---------------- orchestration ----------------
extern "C" void kernel_launch(void* const* d_in, const int* in_sizes, int n_in,
                              void* d_out, int out_size)
{
    const float* encoder_outputs = (const float*)d_in[0];
    const int*   entity_type     = (const int*)  d_in[1];
    const int*   entity_id       = (const int*)  d_in[2];
    const float* sub2words       = (const float*)d_in[3];
    const float* adj             = (const float*)d_in[4];
    const int*   h_t_pairs       = (const int*)  d_in[5];
    const float* rel_mask        = (const float*)d_in[6];
    const int*   path_nodes      = (const int*)  d_in[7];
    const int*   path_lens       = (const int*)  d_in[8];
    const float* type_emb        = (const float*)d_in[9];
    const float* id_emb          = (const float*)d_in[10];
    const float* gcn0_W          = (const float*)d_in[11];
    const float* gcn0_b          = (const float*)d_in[12];
    const float* gcn_W           = (const float*)d_in[13];
    const float* gcn_b           = (const float*)d_in[14];
    const float* attn_Wq         = (const float*)d_in[15];
    const float* attn_Wk         = (const float*)d_in[16];
    const float* attn_Wv         = (const float*)d_in[17];
    const float* lstm_Wih        = (const float*)d_in[18];
    const float* lstm_Whh        = (const float*)d_in[19];
    const float* lstm_b          = (const float*)d_in[20];
    const float* mha_inW         = (const float*)d_in[21];
    const float* mha_inb         = (const float*)d_in[22];
    const float* mha_outW        = (const float*)d_in[23];
    const float* mha_outb        = (const float*)d_in[24];
    const float* pred_W          = (const float*)d_in[25];
    const float* pred_b          = (const float*)d_in[26];
    const float* mW              = (const float*)d_in[27];
    const float* mb              = (const float*)d_in[28];
    const float* bW              = (const float*)d_in[29];
    const float* bb              = (const float*)d_in[30];
    float* out = (float*)d_out;

    void* p;
#define SYMF(var, sym) cudaGetSymbolAddress(&p, sym); float* var = (float*)p;
#define SYMB(var, sym) cudaGetSymbolAddress(&p, sym); bf16* var = (bf16*)p;
    SYMF(enc,   g_enc);    SYMF(feats, g_feats);  SYMF(tmp,   g_tmp);
    SYMF(x1,    g_x1);     SYMF(xq,    g_xq);     SYMF(xk,    g_xk);
    SYMF(xv,    g_xv);     SYMF(att,   g_att);
    SYMF(ih,    g_ih);     SYMF(hh,    g_hh);
    SYMF(cbuf,  g_c);      SYMF(hs1,   g_hs1);
    SYMF(hf,    g_hf);     SYMF(tf,    g_tf);
    SYMF(qb,    g_q);      SYMF(kb,    g_k);      SYMF(vb,    g_v);
    SYMF(pinfo, g_pinfo);  SYMF(hid,   g_hid);
    SYMB(ah,  g_ah);  SYMB(al,  g_al);
    SYMB(sh,  g_sh);  SYMB(sl,  g_sl);
    SYMB(hch, g_hch); SYMB(hcl, g_hcl);
    SYMB(w1h, g_w1h); SYMB(w1l, g_w1l);
    SYMB(w2h, g_w2h); SYMB(w2l, g_w2l);
    SYMB(wph, g_wph); SYMB(wpl, g_wpl);
    cudaGetSymbolAddress(&p, g_validany); int* validany = (int*)p;
#undef SYMF
#undef SYMB

    // 1) enc
    build_enc_kernel<<<Bq * Sq, 256>>>(encoder_outputs, entity_type, entity_id, type_emb, id_emb, enc);

    // 2) x0 = sub2words @ enc
    gemm(false, sub2words, enc, nullptr, nullptr, feats,
         Nq, D0q, Sq, Sq, D0q, BANKq, 0,
         (long)Nq * Sq, (long)Sq * D0q, (long)Nq * BANKq, 0, Bq, 1.f, 0);

    // 3) tmp = adj @ x0
    gemm(false, adj, feats, nullptr, nullptr, tmp,
         Nq, D0q, Nq, Nq, BANKq, D0q, 0,
         (long)Nq * Nq, (long)Nq * BANKq, (long)Nq * D0q, 0, Bq, 1.f, 0);

    // 4) xg0
    gemm(false, tmp, gcn0_W, gcn0_b, nullptr, feats + 808,
         Nq, Gq, D0q, D0q, Gq, BANKq, 0,
         (long)Nq * D0q, 0, (long)Nq * BANKq, 0, Bq, 1.f, 0);

    // 5) GCN + graph-attention layers
    int xoff[NLq]   = {808, 1064};
    int outoff[NLq] = {1064, 1320};
    for (int l = 0; l < NLq; l++) {
        const float* x = feats + xoff[l];
        gemm(false, adj, x, nullptr, nullptr, tmp,
             Nq, Gq, Nq, Nq, BANKq, Gq, 0,
             (long)Nq * Nq, (long)Nq * BANKq, (long)Nq * Gq, 0, Bq, 1.f, 0);
        gemm(false, tmp, gcn_W + (long)l * Gq * Gq, gcn_b + l * Gq, nullptr, x1,
             Nq, Gq, Gq, Gq, Gq, Gq, 0,
             (long)Nq * Gq, 0, (long)Nq * Gq, 0, Bq, 1.f, 1);
        gemm(false, x, attn_Wq + (long)l * Gq * Gq, nullptr, nullptr, xq,
             Nq, Gq, Gq, BANKq, Gq, Gq, 0,
             (long)Nq * BANKq, 0, (long)Nq * Gq, 0, Bq, 1.f, 0);
        gemm(false, x1, attn_Wk + (long)l * Gq * Gq, nullptr, nullptr, xk,
             Nq, Gq, Gq, Gq, Gq, Gq, 0,
             (long)Nq * Gq, 0, (long)Nq * Gq, 0, Bq, 1.f, 0);
        gemm(false, x1, attn_Wv + (long)l * Gq * Gq, nullptr, nullptr, xv,
             Nq, Gq, Gq, Gq, Gq, Gq, 0,
             (long)Nq * Gq, 0, (long)Nq * Gq, 0, Bq, 1.f, 0);
        gemm(true, xq, xk, nullptr, nullptr, att,
             Nq, Nq, Gq, Gq, Gq, Nq, 0,
             (long)Nq * Gq, (long)Nq * Gq, (long)Nq * Nq, 0, Bq, 0.0625f, 0);
        softmax256_kernel<<<Bq * Nq, 256>>>(att);
        gemm(false, att, xv, nullptr, x1, feats + outoff[l],
             Nq, Gq, Nq, Nq, Gq, BANKq, Gq,
             (long)Nq * Nq, (long)Nq * Gq, (long)Nq * BANKq, (long)Nq * Gq, Bq, 1.f, 1);
    }

    // pred weight transpose-split
    {
        dim3 grid((BANK5q + 31) / 32, (BANK5q + 31) / 32);
        transpose_split_kernel<<<grid, dim3(32, 8)>>>(pred_W, wph, wpl, BANK5q, BANK5q);
    }

    const size_t W4 = (size_t)BANK4q * BANKq;
    dim3 cg((BANKq + 255) / 256, Mlstm);
    dim3 cg1((BANKq + 255) / 256, BPq);

    // ===== LSTM layer 0 (prefix dedup at t=0/t=1) =====
    {
        const float* Wih0 = lstm_Wih;
        const float* Whh0 = lstm_Whh;
        const float* b0   = lstm_b;
        split(feats, sh, sl, (size_t)Bq * Nq * BANKq);
        split(Wih0, w1h, w1l, W4);
        split(Whh0, w2h, w2l, W4);
        // proj = feats @ Wih0^T + b0 (1024 x 6304) in hh buffer
        gemm_bf16(sh, sl, w1h, w1l, b0, hh, BPq, BANK4q, BANKq, 0);
        // ih (t-major, all t) = gather(proj)
        gather_ih_l0_kernel<<<MlstmT, 256>>>(hh, path_nodes, ih);
        // candidate t=0 states on 1024 distinct rows
        cand_cell_kernel<<<cg1, 256>>>(hh, qb /*ccand*/, hch, hcl);
        // distribute: running h/c + seq t=0 slice
        gather0_kernel<<<Mlstm, 256>>>(hch, hcl, qb, path_nodes, sh, sl, cbuf, ah, al, nullptr);
        // t=1 hh via dedup: hhproj = hcand @ Whh0^T (1024 rows), then gather
        gemm_bf16(hch, hcl, w2h, w2l, nullptr, hid, BPq, BANK4q, BANKq, 0);
        gather_w64_kernel<<<Mlstm, 256>>>(hid, path_nodes, hh);
        for (int t = 1; t < Lq; t++) {
            if (t > 1)
                gemm_bf16(sh, sl, w2h, w2l, nullptr, hh, Mlstm, BANK4q, BANKq, 0);
            lstm_cell_kernel<<<cg, 256>>>(ih, hh, sh, sl, ah, al, cbuf, nullptr, t);
        }
    }

    // ===== LSTM layer 1 (same dedup; input t=0 is gather(hcand_L0)) =====
    {
        const float* Wih1 = lstm_Wih + W4;
        const float* Whh1 = lstm_Whh + W4;
        const float* b1   = lstm_b + BANK4q;
        split(Wih1, w1h, w1l, W4);
        split(Whh1, w2h, w2l, W4);
        // ihproj0 = hcand_L0 @ Wih1^T + b1 (1024 rows) -> hid
        gemm_bf16(hch, hcl, w1h, w1l, b1, hid, BPq, BANK4q, BANKq, 0);
        // ih t=0 slice = gather(ihproj0)
        gather_w64_kernel<<<Mlstm, 256>>>(hid, path_nodes, ih);
        // ih t=1..3 = seq rows 3072.. @ Wih1^T + b1 (9216 rows)
        gemm_bf16(ah + (size_t)Mlstm * BANKq, al + (size_t)Mlstm * BANKq, w1h, w1l, b1,
                  ih + (size_t)Mlstm * BANK4q, 3 * Mlstm, BANK4q, BANKq, 0);
        // candidate layer-1 t=0 states (reads hid=ihproj0; overwrites hch/hcl/ccand)
        cand_cell_kernel<<<cg1, 256>>>(hid, qb, hch, hcl);
        // distribute: running h/c + hs1 t=0 slice (float)
        gather0_kernel<<<Mlstm, 256>>>(hch, hcl, qb, path_nodes, sh, sl, cbuf,
                                       nullptr, nullptr, hs1);
        // t=1 hh via dedup
        gemm_bf16(hch, hcl, w2h, w2l, nullptr, hid, BPq, BANK4q, BANKq, 0);
        gather_w64_kernel<<<Mlstm, 256>>>(hid, path_nodes, hh);
        for (int t = 1; t < Lq; t++) {
            if (t > 1)
                gemm_bf16(sh, sl, w2h, w2l, nullptr, hh, Mlstm, BANK4q, BANKq, 0);
            lstm_cell_kernel<<<cg, 256>>>(ih, hh, sh, sl, nullptr, nullptr, cbuf, hs1, t);
        }
    }

    // 8) masked max-pool over time (t-major) -> split bf16 (ah/al reused)
    maxpool_split_kernel<<<cg, 256>>>(hs1, path_lens, ah, al);

    // 9) h_f, t_f, query (split)
    gather_ht_kernel<<<BPq, 256>>>(feats, h_t_pairs, hf, tf, sh, sl);

    // 10-11) q/k/v projections
    split(mha_inW, w1h, w1l, (size_t)3 * BANKq * BANKq);
    gemm_bf16(sh, sl, w1h, w1l, mha_inb, qb, BPq, BANKq, BANKq, 0);
    gemm_bf16(ah, al, w1h + (size_t)BANKq * BANKq, w1l + (size_t)BANKq * BANKq,
              mha_inb + BANKq, kb, Mlstm, BANKq, BANKq, 0);
    gemm_bf16(ah, al, w1h + 2 * (size_t)BANKq * BANKq, w1l + 2 * (size_t)BANKq * BANKq,
              mha_inb + 2 * BANKq, vb, Mlstm, BANKq, BANKq, 0);

    // 12) tiny attention over K=3 paths (ctx split into sh/sl)
    mha_attn_kernel<<<BPq, 384>>>(qb, kb, vb, path_lens, rel_mask, sh, sl, validany);

    // 13) pinfo
    split(mha_outW, w2h, w2l, (size_t)BANKq * BANKq);
    gemm_bf16(sh, sl, w2h, w2l, mha_outb, pinfo, BPq, BANKq, BANKq, 0);

    // 14) of (split into ah/al)
    build_of_split_kernel<<<BPq, 256>>>(hf, tf, pinfo, validany, ah, al);

    // 15) hid = relu(of @ pred_W + pred_b)
    gemm_bf16(ah, al, wph, wpl, pred_b, hid, BPq, BANK5q, BANK5q, 1);

    // 16) fused output heads
    head_kernel<<<BPq, 256>>>(hid, mW, mb, bW, bb, out);
}

// round 11
// speedup vs baseline: 2.8979x; 1.4355x over previous
#include <cuda_runtime.h>
#include <cuda_bf16.h>
#include <math.h>
#include <stdio.h>

// ---------------- problem constants ----------------
#define Bq   4
#define Sq   512
#define Nq   256
#define Eq   42
#define Pq   256
#define Kq   3
#define Lq   4
#define HBq  768
#define DTq  20
#define DIq  20
#define Gq   256
#define NLq  2
#define Rq   97
#define NHq  4
#define D0q  808          // HB+DT+DI
#define BANKq 1576        // D0 + G*(NL+1)
#define BANK4q 6304       // 4*BANK
#define BANK5q 7880       // 5*BANK
#define DHq  394          // BANK/NH
#define Mlstm (Bq*Pq*Kq)        // 3072
#define MlstmT (Mlstm*Lq)       // 12288
#define BPq  (Bq*Pq)            // 1024

typedef __nv_bfloat16 bf16;
typedef __nv_bfloat162 bf162;

// ---------------- scratch (static device memory; no allocations allowed) ----------------
__device__ float g_enc   [Bq*Sq*D0q];
__device__ float g_feats [Bq*Nq*BANKq];
__device__ float g_tmp   [Bq*Nq*D0q];
__device__ float g_x1    [Bq*Nq*Gq];
__device__ float g_xq    [Bq*Nq*Gq];
__device__ float g_xk    [Bq*Nq*Gq];
__device__ float g_xv    [Bq*Nq*Gq];
__device__ float g_att   [Bq*Nq*Nq];
__device__ float g_ih    [(size_t)MlstmT*BANK4q];   // t-major
__device__ float g_hh    [(size_t)Mlstm*BANK4q];
__device__ float g_c     [Mlstm*BANKq];
__device__ float g_hs1   [MlstmT*BANKq];            // t-major, compacted rows
__device__ float g_hf    [BPq*BANKq];
__device__ float g_tf    [BPq*BANKq];
__device__ float g_q     [BPq*BANKq];               // qb / ccand scratch
__device__ float g_k     [Mlstm*BANKq];
__device__ float g_v     [Mlstm*BANKq];
__device__ float g_pinfo [BPq*BANKq];
__device__ int   g_validany[BPq];
__device__ float g_hid   [BPq*BANK5q];              // also proj scratch

// length-compaction state
__device__ int g_perm[Mlstm];                       // compacted slot -> orig row
__device__ int g_cnt[4];                            // cnt[t] = #rows with len > t

// bf16 split scratch
__device__ bf16 g_ah  [(size_t)MlstmT*BANKq];       // layer-0 seq, t-major compacted; later pe (orig order)
__device__ bf16 g_al  [(size_t)MlstmT*BANKq];
__device__ bf16 g_sh  [(size_t)Mlstm*BANKq];
__device__ bf16 g_sl  [(size_t)Mlstm*BANKq];
__device__ bf16 g_hch [(size_t)BPq*BANKq];          // candidate h (1024 distinct rows)
__device__ bf16 g_hcl [(size_t)BPq*BANKq];
__device__ bf16 g_w1h [(size_t)BANK4q*BANKq];
__device__ bf16 g_w1l [(size_t)BANK4q*BANKq];
__device__ bf16 g_w2h [(size_t)BANK4q*BANKq];
__device__ bf16 g_w2l [(size_t)BANK4q*BANKq];
__device__ bf16 g_wph [(size_t)BANK5q*BANK5q];
__device__ bf16 g_wpl [(size_t)BANK5q*BANK5q];

// ================= fp32 tiled GEMM (small GCN ops) =================
template <bool TRANSB>
__global__ void __launch_bounds__(256)
gemm32_kernel(const float* __restrict__ A, const float* __restrict__ B,
              const float* __restrict__ bias, const float* __restrict__ resid,
              float* __restrict__ C,
              int M, int N, int K,
              int lda, int ldb, int ldc, int ldr,
              long sA, long sB, long sC, long sR,
              float alpha, int act)
{
    int bz = blockIdx.z;
    A += bz * sA; B += bz * sB; C += bz * sC;
    if (resid) resid += bz * sR;

    int row0 = blockIdx.y * 32;
    int col0 = blockIdx.x * 32;

    __shared__ float As[32][33];
    __shared__ float Bs[32][33];

    int tid = threadIdx.x;
    int tx = tid & 15, ty = tid >> 4;

    float acc[2][2] = {{0.f, 0.f}, {0.f, 0.f}};

    for (int k0 = 0; k0 < K; k0 += 32) {
#pragma unroll
        for (int l = 0; l < 4; l++) {
            int idx = tid + l * 256;
            int m = idx >> 5, kk = idx & 31;
            int gr = row0 + m, gk = k0 + kk;
            As[kk][m] = (gr < M && gk < K) ? A[(long)gr * lda + gk] : 0.f;
        }
#pragma unroll
        for (int l = 0; l < 4; l++) {
            int idx = tid + l * 256;
            if (TRANSB) {
                int n = idx >> 5, kk = idx & 31;
                int gn = col0 + n, gk = k0 + kk;
                Bs[kk][n] = (gn < N && gk < K) ? B[(long)gn * ldb + gk] : 0.f;
            } else {
                int kk = idx >> 5, n = idx & 31;
                int gn = col0 + n, gk = k0 + kk;
                Bs[kk][n] = (gn < N && gk < K) ? B[(long)gk * ldb + gn] : 0.f;
            }
        }
        __syncthreads();
#pragma unroll
        for (int kk = 0; kk < 32; kk++) {
            float a0 = As[kk][ty], a1 = As[kk][ty + 16];
            float b0 = Bs[kk][tx], b1 = Bs[kk][tx + 16];
            acc[0][0] = fmaf(a0, b0, acc[0][0]);
            acc[0][1] = fmaf(a0, b1, acc[0][1]);
            acc[1][0] = fmaf(a1, b0, acc[1][0]);
            acc[1][1] = fmaf(a1, b1, acc[1][1]);
        }
        __syncthreads();
    }

#pragma unroll
    for (int i = 0; i < 2; i++) {
        int r = row0 + ty + 16 * i;
        if (r >= M) continue;
#pragma unroll
        for (int j = 0; j < 2; j++) {
            int cc = col0 + tx + 16 * j;
            if (cc >= N) continue;
            float v = acc[i][j] * alpha;
            if (bias) v += bias[cc];
            if (act == 1) v = fmaxf(v, 0.f);
            if (resid) v += resid[(long)r * ldr + cc];
            C[(long)r * ldc + cc] = v;
        }
    }
}

static void gemm(bool transB,
                 const float* A, const float* B, const float* bias, const float* resid, float* C,
                 int M, int N, int K, int lda, int ldb, int ldc, int ldr,
                 long sA, long sB, long sC, long sR, int batch, float alpha, int act)
{
    dim3 grid((N + 31) / 32, (M + 31) / 32, batch);
    if (transB)
        gemm32_kernel<true><<<grid, 256>>>(A, B, bias, resid, C, M, N, K, lda, ldb, ldc, ldr, sA, sB, sC, sR, alpha, act);
    else
        gemm32_kernel<false><<<grid, 256>>>(A, B, bias, resid, C, M, N, K, lda, ldb, ldc, ldr, sA, sB, sC, sR, alpha, act);
}

// ================= bf16 split-precision tensor-core GEMM (verified R6 loop + Mdev) =================
#define LDSB 40
#define GSTG 3
#define PLANE_E (128*LDSB)
#define PLANE_B (PLANE_E*2)
#define STAGE_B (4*PLANE_B)

#define MMA_BF16(d, a, b) asm volatile( \
    "mma.sync.aligned.m16n8k16.row.col.f32.bf16.bf16.f32 " \
    "{%0,%1,%2,%3}, {%4,%5,%6,%7}, {%8,%9}, {%0,%1,%2,%3};" \
    : "+f"((d)[0]), "+f"((d)[1]), "+f"((d)[2]), "+f"((d)[3]) \
    : "r"((a)[0]), "r"((a)[1]), "r"((a)[2]), "r"((a)[3]), "r"((b)[0]), "r"((b)[1]))

#define LDSM4(r, addr) asm volatile( \
    "ldmatrix.sync.aligned.m8n8.x4.shared.b16 {%0,%1,%2,%3}, [%4];" \
    : "=r"((r)[0]), "=r"((r)[1]), "=r"((r)[2]), "=r"((r)[3]) : "r"(addr))

__device__ __forceinline__ void cpasync16(unsigned saddr, const void* g, int srcbytes)
{
    asm volatile("cp.async.cg.shared.global [%0], [%1], 16, %2;\n"
                 :: "r"(saddr), "l"(g), "r"(srcbytes));
}

__device__ __forceinline__ void gbf_prefetch(
    const bf16* __restrict__ Ah, const bf16* __restrict__ Al,
    const bf16* __restrict__ Bh, const bf16* __restrict__ Bl,
    long row0, long col0, int M, int N, int K,
    int kt, int T, unsigned sbase, int stg, int tid)
{
    if (kt >= T) return;
    long k0 = (long)kt * 32;
    unsigned sst = sbase + (unsigned)stg * STAGE_B;
#pragma unroll
    for (int i = 0; i < 2; i++) {
        int c = tid + i * 256;
        int r = c >> 2;
        int ko = (c & 3) * 8;
        long gk = k0 + ko;
        bool kok = gk < K;
        long gkc = kok ? gk : 0;
        unsigned soff = (unsigned)((r * LDSB + ko) * 2);
        {
            long gr = row0 + r;
            bool ok = kok && (gr < M);
            long grc = ok ? gr : 0;
            int nb = ok ? 16 : 0;
            cpasync16(sst + soff,            Ah + grc * K + gkc, nb);
            cpasync16(sst + PLANE_B + soff,  Al + grc * K + gkc, nb);
        }
        {
            long gn = col0 + r;
            bool ok = kok && (gn < N);
            long gnc = ok ? gn : 0;
            int nb = ok ? 16 : 0;
            cpasync16(sst + 2 * PLANE_B + soff, Bh + gnc * K + gkc, nb);
            cpasync16(sst + 3 * PLANE_B + soff, Bl + gnc * K + gkc, nb);
        }
    }
}

__global__ void __launch_bounds__(256)
gemm_bf16_kernel(const bf16* __restrict__ Ah, const bf16* __restrict__ Al,
                 const bf16* __restrict__ Bh, const bf16* __restrict__ Bl,
                 const float* __restrict__ bias, float* __restrict__ C,
                 int M, int N, int K, int act, const int* __restrict__ Mdev)
{
    if (Mdev) {
        M = min(M, *Mdev);
        if ((long)blockIdx.y * 128 >= (long)M) return;   // uniform early exit
    }
    extern __shared__ __align__(16) bf16 dsm[];
    unsigned sbase = (unsigned)__cvta_generic_to_shared(dsm);

    int tid = threadIdx.x;
    int warp = tid >> 5, lane = tid & 31;
    int wm = (warp & 1) * 64;
    int wn = (warp >> 1) * 32;
    long row0 = (long)blockIdx.y * 128;
    long col0 = (long)blockIdx.x * 128;

    float acc[4][4][4];
#pragma unroll
    for (int a = 0; a < 4; a++)
#pragma unroll
        for (int b = 0; b < 4; b++)
#pragma unroll
            for (int c = 0; c < 4; c++) acc[a][b][c] = 0.f;

    int am_r = (lane & 7) + ((lane >> 3) & 1) * 8;
    int a_c8 = ((lane >> 4) & 1) * 8;
    int b_r  = (lane & 7) + ((lane >> 4) & 1) * 8;
    int b_c8 = ((lane >> 3) & 1) * 8;

    int T = (K + 31) / 32;

#pragma unroll
    for (int kt = 0; kt < GSTG; kt++) {
        gbf_prefetch(Ah, Al, Bh, Bl, row0, col0, M, N, K, kt, T, sbase, kt, tid);
        asm volatile("cp.async.commit_group;\n");
    }

    for (int kt = 0; kt < T; kt++) {
        asm volatile("cp.async.wait_group %0;\n" :: "n"(GSTG - 1));
        __syncthreads();

        int stg = kt % GSTG;
        unsigned sst = sbase + (unsigned)stg * STAGE_B;
        unsigned aB = sst;
        unsigned bB = sst + 2 * PLANE_B;

#pragma unroll
        for (int ks = 0; ks < 2; ks++) {
            int kb = ks * 16;
            unsigned bh[2][4], bl[2][4];
#pragma unroll
            for (int pp = 0; pp < 2; pp++) {
                unsigned addr = bB + (unsigned)(((wn + pp * 16 + b_r) * LDSB + kb + b_c8) * 2);
                LDSM4(bh[pp], addr);
                LDSM4(bl[pp], addr + PLANE_B);
            }
            unsigned ahf[4][4], alf[4][4];
#pragma unroll
            for (int mi = 0; mi < 4; mi++) {
                unsigned addr = aB + (unsigned)(((wm + mi * 16 + am_r) * LDSB + kb + a_c8) * 2);
                LDSM4(ahf[mi], addr);
                LDSM4(alf[mi], addr + PLANE_B);
            }
#pragma unroll
            for (int mi = 0; mi < 4; mi++)
#pragma unroll
                for (int ni = 0; ni < 4; ni++)
                    MMA_BF16(acc[mi][ni], ahf[mi], (&bh[ni >> 1][(ni & 1) * 2]));
#pragma unroll
            for (int mi = 0; mi < 4; mi++)
#pragma unroll
                for (int ni = 0; ni < 4; ni++)
                    MMA_BF16(acc[mi][ni], ahf[mi], (&bl[ni >> 1][(ni & 1) * 2]));
#pragma unroll
            for (int mi = 0; mi < 4; mi++)
#pragma unroll
                for (int ni = 0; ni < 4; ni++)
                    MMA_BF16(acc[mi][ni], alf[mi], (&bh[ni >> 1][(ni & 1) * 2]));
        }
        __syncthreads();
        gbf_prefetch(Ah, Al, Bh, Bl, row0, col0, M, N, K, kt + GSTG, T, sbase, stg, tid);
        asm volatile("cp.async.commit_group;\n");
    }

#pragma unroll
    for (int mi = 0; mi < 4; mi++) {
#pragma unroll
        for (int ni = 0; ni < 4; ni++) {
            long r = row0 + wm + mi * 16 + (lane >> 2);
            long c = col0 + wn + ni * 8 + (lane & 3) * 2;
#pragma unroll
            for (int half = 0; half < 2; half++) {
                long rr = r + half * 8;
                if (rr >= M) continue;
#pragma unroll
                for (int e = 0; e < 2; e++) {
                    long cc = c + e;
                    if (cc >= N) continue;
                    float v = acc[mi][ni][half * 2 + e];
                    if (bias) v += bias[cc];
                    if (act == 1) v = fmaxf(v, 0.f);
                    C[(size_t)rr * N + cc] = v;
                }
            }
        }
    }
}

static void gemm_bf16(const bf16* Ah, const bf16* Al, const bf16* Bh, const bf16* Bl,
                      const float* bias, float* C, int M, int N, int K, int act,
                      const int* Mdev = nullptr)
{
    static int attr_done = 0;
    if (!attr_done) {
        cudaFuncSetAttribute(gemm_bf16_kernel,
                             cudaFuncAttributeMaxDynamicSharedMemorySize, GSTG * STAGE_B);
        attr_done = 1;
    }
    dim3 grid((N + 127) / 128, (M + 127) / 128);
    gemm_bf16_kernel<<<grid, 256, GSTG * STAGE_B>>>(Ah, Al, Bh, Bl, bias, C, M, N, K, act, Mdev);
}

// ================= conversion kernels =================
__device__ __forceinline__ void split1(float f, bf16& h, bf16& l)
{
    h = __float2bfloat16(f);
    l = __float2bfloat16(f - __bfloat162float(h));
}

__global__ void split_kernel(const float* __restrict__ x, bf16* __restrict__ hi,
                             bf16* __restrict__ lo, size_t n4)
{
    size_t i = (size_t)blockIdx.x * blockDim.x + threadIdx.x;
    if (i >= n4) return;
    float4 f = ((const float4*)x)[i];
    bf16 h0, l0, h1, l1, h2, l2, h3, l3;
    split1(f.x, h0, l0); split1(f.y, h1, l1); split1(f.z, h2, l2); split1(f.w, h3, l3);
    bf162 vh0; vh0.x = h0; vh0.y = h1;
    bf162 vh1; vh1.x = h2; vh1.y = h3;
    bf162 vl0; vl0.x = l0; vl0.y = l1;
    bf162 vl1; vl1.x = l2; vl1.y = l3;
    ((bf162*)hi)[i * 2] = vh0; ((bf162*)hi)[i * 2 + 1] = vh1;
    ((bf162*)lo)[i * 2] = vl0; ((bf162*)lo)[i * 2 + 1] = vl1;
}

static void split(const float* x, bf16* hi, bf16* lo, size_t n)
{
    size_t n4 = n / 4;
    split_kernel<<<(unsigned)((n4 + 255) / 256), 256>>>(x, hi, lo, n4);
}

__global__ void transpose_split_kernel(const float* __restrict__ B, bf16* __restrict__ Th,
                                       bf16* __restrict__ Tl, int K, int N)
{
    __shared__ float tile[32][33];
    int k0 = blockIdx.y * 32, n0 = blockIdx.x * 32;
    int tx = threadIdx.x, ty = threadIdx.y;  // 32 x 8
#pragma unroll
    for (int i = 0; i < 32; i += 8) {
        int k = k0 + ty + i, n = n0 + tx;
        tile[ty + i][tx] = (k < K && n < N) ? B[(size_t)k * N + n] : 0.f;
    }
    __syncthreads();
#pragma unroll
    for (int i = 0; i < 32; i += 8) {
        int n = n0 + ty + i, k = k0 + tx;
        if (n < N && k < K) {
            float f = tile[tx][ty + i];
            bf16 h, l; split1(f, h, l);
            Th[(size_t)n * K + k] = h;
            Tl[(size_t)n * K + k] = l;
        }
    }
}

// ---------------- fast activations ----------------
__device__ __forceinline__ float fsig(float x)
{
    return __fdividef(1.f, 1.f + __expf(-x));
}
__device__ __forceinline__ float ftanh(float x)
{
    x = fminf(fmaxf(x, -15.f), 15.f);
    float e = __expf(-2.f * x);
    return __fdividef(1.f - e, 1.f + e);
}

// ---------------- length-compaction permutation ----------------
// Deterministic: stable order within each len bucket, buckets by descending len.
__global__ void build_perm_kernel(const int* __restrict__ lens)
{
    __shared__ int slens[Mlstm];
    __shared__ int bins[Lq + 1];
    __shared__ int offs[Lq + 1];
    int tid = threadIdx.x;
    if (tid <= Lq) bins[tid] = 0;
    __syncthreads();
    for (int i = tid; i < Mlstm; i += blockDim.x) {
        int l = lens[i];
        slens[i] = l;
        atomicAdd(&bins[l], 1);
    }
    __syncthreads();
    if (tid == 0) {
        int off = 0;
        for (int l = Lq; l >= 0; l--) { offs[l] = off; off += bins[l]; }
        int c = 0;
        for (int t = Lq - 1; t >= 0; t--) { c += bins[t + 1]; g_cnt[t] = c; }
        // stable serial assignment
        int cur[Lq + 1];
        for (int l = 0; l <= Lq; l++) cur[l] = offs[l];
        for (int i = 0; i < Mlstm; i++) {
            int l = slens[i];
            g_perm[cur[l]++] = i;
        }
    }
}

// ---------------- small custom kernels ----------------
__global__ void build_enc_kernel(const float* __restrict__ eo, const int* __restrict__ etype,
                                 const int* __restrict__ eid, const float* __restrict__ temb,
                                 const float* __restrict__ iemb, float* __restrict__ enc)
{
    int bs = blockIdx.x;
    const float* src = eo + (long)bs * HBq;
    float* dst = enc + (long)bs * D0q;
    int ty = etype[bs], idv = eid[bs];
    for (int j = threadIdx.x; j < D0q; j += blockDim.x) {
        float v;
        if (j < HBq)            v = src[j];
        else if (j < HBq + DTq) v = temb[ty * DTq + (j - HBq)];
        else                    v = iemb[idv * DIq + (j - HBq - DTq)];
        dst[j] = v;
    }
}

__global__ void softmax256_kernel(float* __restrict__ x)
{
    int row = blockIdx.x;
    int tid = threadIdx.x;
    float v = x[(long)row * 256 + tid];
    __shared__ float red[8];
    int lane = tid & 31, warp = tid >> 5;
    float m = v;
#pragma unroll
    for (int o = 16; o > 0; o >>= 1) m = fmaxf(m, __shfl_xor_sync(0xffffffffu, m, o));
    if (lane == 0) red[warp] = m;
    __syncthreads();
    if (tid == 0) {
        float mm = red[0];
        for (int w = 1; w < 8; w++) mm = fmaxf(mm, red[w]);
        red[0] = mm;
    }
    __syncthreads();
    float mx = red[0];
    float e = expf(v - mx);
    float s = e;
#pragma unroll
    for (int o = 16; o > 0; o >>= 1) s += __shfl_xor_sync(0xffffffffu, s, o);
    __shared__ float red2[8];
    if (lane == 0) red2[warp] = s;
    __syncthreads();
    if (tid == 0) {
        float ss = 0.f;
        for (int w = 0; w < 8; w++) ss += red2[w];
        red2[0] = ss;
    }
    __syncthreads();
    x[(long)row * 256 + tid] = e / red2[0];
}

// layer-0 ih gather (t = 1..3 only; compacted rows): ih[t*Mlstm+i] = proj[b*Nq + node(perm[i],t)]
__global__ void gather_ih_l0_kernel(const float* __restrict__ proj, const int* __restrict__ nodes,
                                    float* __restrict__ ih)
{
    int r = blockIdx.x;                   // 0..3*Mlstm-1
    int t = 1 + r / Mlstm, i = r % Mlstm;
    if (i >= g_cnt[t]) return;
    int orig = g_perm[i];
    int b = orig / (Pq * Kq);
    int node = nodes[orig * Lq + t];
    const float4* src = (const float4*)(proj + ((size_t)(b * Nq + node)) * BANK4q);
    float4* dst = (float4*)(ih + ((size_t)t * Mlstm + i) * BANK4q);
    for (int j = threadIdx.x; j < BANK4q / 4; j += blockDim.x) dst[j] = src[j];
}

// 6304-wide gather via node0 (compacted rows, count-limited): dst[i] = src[b*Nq + node(perm[i],0)]
__global__ void gather_w64_kernel(const float* __restrict__ src, const int* __restrict__ nodes,
                                  float* __restrict__ dst, int cslot)
{
    int i = blockIdx.x;
    if (i >= g_cnt[cslot]) return;
    int orig = g_perm[i];
    int b = orig / (Pq * Kq);
    int node = nodes[orig * Lq];
    const float4* s = (const float4*)(src + ((size_t)(b * Nq + node)) * BANK4q);
    float4* d = (float4*)(dst + (size_t)i * BANK4q);
    for (int j = threadIdx.x; j < BANK4q / 4; j += blockDim.x) d[j] = s[j];
}

// t=0 candidate cell: 1024 rows, c=0
__global__ void cand_cell_kernel(const float* __restrict__ proj, float* __restrict__ ccand,
                                 bf16* __restrict__ hch, bf16* __restrict__ hcl)
{
    int i = blockIdx.y;
    int j = blockIdx.x * blockDim.x + threadIdx.x;
    if (j >= BANKq) return;
    const float* g = proj + (size_t)i * BANK4q;
    float gi = g[j], gg = g[2 * BANKq + j], go = g[3 * BANKq + j];
    float cn = fsig(gi) * ftanh(gg);
    float hn = fsig(go) * ftanh(cn);
    ccand[(size_t)i * BANKq + j] = cn;
    bf16 h, l; split1(hn, h, l);
    hch[(size_t)i * BANKq + j] = h;
    hcl[(size_t)i * BANKq + j] = l;
}

// distribute candidates to compacted rows: running h/c + seq/hs t=0 slice
__global__ void gather0_kernel(const bf16* __restrict__ hch, const bf16* __restrict__ hcl,
                               const float* __restrict__ ccand, const int* __restrict__ nodes,
                               bf16* __restrict__ sh, bf16* __restrict__ sl,
                               float* __restrict__ c,
                               bf16* __restrict__ seq_hi, bf16* __restrict__ seq_lo,
                               float* __restrict__ hs)
{
    int i = blockIdx.x;                   // compacted slot
    int orig = g_perm[i];
    int b = orig / (Pq * Kq);
    size_t idx = ((size_t)(b * Nq + nodes[orig * Lq])) * BANKq;
    size_t dst = (size_t)i * BANKq;
    for (int j = threadIdx.x; j < BANKq; j += blockDim.x) {
        bf16 h = hch[idx + j], l = hcl[idx + j];
        sh[dst + j] = h;
        sl[dst + j] = l;
        c[dst + j] = ccand[idx + j];
        if (seq_hi) { seq_hi[dst + j] = h; seq_lo[dst + j] = l; }
        if (hs) hs[dst + j] = __bfloat162float(h) + __bfloat162float(l);
    }
}

// LSTM cell for t >= 1 (t-major, compacted, count-limited)
__global__ void lstm_cell_kernel(const float* __restrict__ ih, const float* __restrict__ hh,
                                 bf16* __restrict__ h_hi, bf16* __restrict__ h_lo,
                                 bf16* __restrict__ seq_hi, bf16* __restrict__ seq_lo,
                                 float* __restrict__ c, float* __restrict__ hs, int t)
{
    int i = blockIdx.y;
    if (i >= g_cnt[t]) return;
    int j = blockIdx.x * blockDim.x + threadIdx.x;
    if (j >= BANKq) return;
    const float* g = ih + ((size_t)t * Mlstm + i) * BANK4q;
    const float* hr = hh + (size_t)i * BANK4q;
    float gi = g[j] + hr[j];
    float gf = g[BANKq + j] + hr[BANKq + j];
    float gg = g[2 * BANKq + j] + hr[2 * BANKq + j];
    float go = g[3 * BANKq + j] + hr[3 * BANKq + j];
    float cp = c[(size_t)i * BANKq + j];
    float cn = fsig(gf) * cp + fsig(gi) * ftanh(gg);
    float hn = fsig(go) * ftanh(cn);
    c[(size_t)i * BANKq + j] = cn;
    bf16 h, l; split1(hn, h, l);
    h_hi[(size_t)i * BANKq + j] = h;
    h_lo[(size_t)i * BANKq + j] = l;
    if (seq_hi) {
        seq_hi[((size_t)t * Mlstm + i) * BANKq + j] = h;
        seq_lo[((size_t)t * Mlstm + i) * BANKq + j] = l;
    }
    if (hs) hs[((size_t)t * Mlstm + i) * BANKq + j] = hn;
}

// masked max-pool over time (compacted t-major hs; scatter result to ORIGINAL row order)
__global__ void maxpool_split_kernel(const float* __restrict__ hs, const int* __restrict__ lens,
                                     bf16* __restrict__ hi, bf16* __restrict__ lo)
{
    int i = blockIdx.y;                   // compacted slot
    int j = blockIdx.x * blockDim.x + threadIdx.x;
    if (j >= BANKq) return;
    int orig = g_perm[i];
    int len = lens[orig];
    float m = -1e9f;
    const float* base = hs + (size_t)i * BANKq + j;
    for (int t = 0; t < Lq; t++)
        if (t < len) m = fmaxf(m, base[(size_t)t * Mlstm * BANKq]);
    float r = (len > 0) ? m : 0.f;
    bf16 h, l; split1(r, h, l);
    hi[(size_t)orig * BANKq + j] = h;
    lo[(size_t)orig * BANKq + j] = l;
}

__global__ void gather_ht_kernel(const float* __restrict__ feats, const int* __restrict__ htp,
                                 float* __restrict__ hf, float* __restrict__ tf,
                                 bf16* __restrict__ qh, bf16* __restrict__ ql)
{
    int bp = blockIdx.x;
    int b = bp / Pq;
    int h0 = htp[bp * 2 + 0], t0 = htp[bp * 2 + 1];
    h0 = (h0 == 0) ? 0 : h0 - 1;
    t0 = (t0 == 0) ? 0 : t0 - 1;
    const float* hsrc = feats + ((size_t)b * Nq + (Nq - Eq) + h0) * BANKq;
    const float* tsrc = feats + ((size_t)b * Nq + (Nq - Eq) + t0) * BANKq;
    for (int j = threadIdx.x; j < BANKq; j += blockDim.x) {
        float hv = hsrc[j], tv = tsrc[j];
        hf[(size_t)bp * BANKq + j] = hv;
        tf[(size_t)bp * BANKq + j] = tv;
        bf16 h, l; split1(hv - tv, h, l);
        qh[(size_t)bp * BANKq + j] = h;
        ql[(size_t)bp * BANKq + j] = l;
    }
}

__global__ void mha_attn_kernel(const float* __restrict__ q, const float* __restrict__ k,
                                const float* __restrict__ v, const int* __restrict__ plens,
                                const float* __restrict__ rmask,
                                bf16* __restrict__ ctx_hi, bf16* __restrict__ ctx_lo,
                                int* __restrict__ validany)
{
    int bp = blockIdx.x;
    int tid = threadIdx.x;
    int warp = tid >> 5, lane = tid & 31;
    __shared__ float sc[NHq][Kq];
    __shared__ float aw[NHq][Kq];
    __shared__ int vm[Kq];
    if (tid < Kq) vm[tid] = (rmask[bp] > 0.f && plens[bp * Kq + tid] > 0) ? 1 : 0;
    __syncthreads();
    {
        int h = warp / Kq, kk = warp % Kq;
        const float* qh = q + (size_t)bp * BANKq + h * DHq;
        const float* kh = k + ((size_t)bp * Kq + kk) * BANKq + h * DHq;
        float s = 0.f;
        for (int d = lane; d < DHq; d += 32) s += qh[d] * kh[d];
#pragma unroll
        for (int o = 16; o > 0; o >>= 1) s += __shfl_xor_sync(0xffffffffu, s, o);
        if (lane == 0) {
            s = s / sqrtf((float)DHq);
            sc[h][kk] = vm[kk] ? s : -1e9f;
        }
    }
    __syncthreads();
    if (tid < NHq) {
        int h = tid;
        float m = fmaxf(fmaxf(sc[h][0], sc[h][1]), sc[h][2]);
        float e0 = expf(sc[h][0] - m), e1 = expf(sc[h][1] - m), e2 = expf(sc[h][2] - m);
        float s = e0 + e1 + e2;
        aw[h][0] = e0 / s; aw[h][1] = e1 / s; aw[h][2] = e2 / s;
    }
    if (tid == 0) validany[bp] = (vm[0] | vm[1] | vm[2]);
    __syncthreads();
    for (int j = tid; j < BANKq; j += blockDim.x) {
        int h = j / DHq;
        const float* vb = v + (size_t)bp * Kq * BANKq + j;
        float r = aw[h][0] * vb[0] + aw[h][1] * vb[BANKq] + aw[h][2] * vb[2 * BANKq];
        bf16 hh2, ll2; split1(r, hh2, ll2);
        ctx_hi[(size_t)bp * BANKq + j] = hh2;
        ctx_lo[(size_t)bp * BANKq + j] = ll2;
    }
}

__global__ void build_of_split_kernel(const float* __restrict__ hf, const float* __restrict__ tf,
                                      const float* __restrict__ pinfo, const int* __restrict__ validany,
                                      bf16* __restrict__ oh, bf16* __restrict__ ol)
{
    int bp = blockIdx.x;
    int va = validany[bp];
    const float* hr = hf + (size_t)bp * BANKq;
    const float* tr = tf + (size_t)bp * BANKq;
    const float* pr = pinfo + (size_t)bp * BANKq;
    size_t base = (size_t)bp * BANK5q;
    for (int j = threadIdx.x; j < BANK5q; j += blockDim.x) {
        int seg = j / BANKq, jj = j - seg * BANKq;
        float v;
        if (seg == 0)      v = hr[jj];
        else if (seg == 1) v = tr[jj];
        else if (seg == 2) v = fabsf(hr[jj] - tr[jj]);
        else if (seg == 3) v = hr[jj] * tr[jj];
        else               v = va ? pr[jj] : 0.f;
        bf16 h, l; split1(v, h, l);
        oh[base + j] = h;
        ol[base + j] = l;
    }
}

__global__ void __launch_bounds__(256)
head_kernel(const float* __restrict__ hid, const float* __restrict__ mW,
            const float* __restrict__ mb, const float* __restrict__ bW,
            const float* __restrict__ bb, float* __restrict__ out)
{
    int m = blockIdx.x;
    __shared__ float srow[BANK5q];
    __shared__ float part[2][Rq + 2];
    const float* hr = hid + (size_t)m * BANK5q;
    for (int j = threadIdx.x; j < BANK5q; j += 256) srow[j] = hr[j];
    __syncthreads();
    int t = threadIdx.x;
    const int NT = Rq + 2;  // 99
    if (t < 2 * NT) {
        int ks = t / NT, n = t - ks * NT;
        int k0 = ks * (BANK5q / 2), k1 = k0 + BANK5q / 2;
        float acc = 0.f;
        if (n < Rq) {
#pragma unroll 8
            for (int k = k0; k < k1; k++) acc += srow[k] * mW[(size_t)k * Rq + n];
        } else {
            int nb = n - Rq;
#pragma unroll 8
            for (int k = k0; k < k1; k++) acc += srow[k] * bW[(size_t)k * 2 + nb];
        }
        part[ks][n] = acc;
    }
    __syncthreads();
    if (t < NT) {
        float v = part[0][t] + part[1][t];
        if (t < Rq) out[(size_t)m * Rq + t] = v + mb[t];
        else        out[(size_t)BPq * Rq + (size_t)m * 2 + (t - Rq)] = v + bb[t - Rq];
    }
}

// ---------------- orchestration ----------------
extern "C" void kernel_launch(void* const* d_in, const int* in_sizes, int n_in,
                              void* d_out, int out_size)
{
    const float* encoder_outputs = (const float*)d_in[0];
    const int*   entity_type     = (const int*)  d_in[1];
    const int*   entity_id       = (const int*)  d_in[2];
    const float* sub2words       = (const float*)d_in[3];
    const float* adj             = (const float*)d_in[4];
    const int*   h_t_pairs       = (const int*)  d_in[5];
    const float* rel_mask        = (const float*)d_in[6];
    const int*   path_nodes      = (const int*)  d_in[7];
    const int*   path_lens       = (const int*)  d_in[8];
    const float* type_emb        = (const float*)d_in[9];
    const float* id_emb          = (const float*)d_in[10];
    const float* gcn0_W          = (const float*)d_in[11];
    const float* gcn0_b          = (const float*)d_in[12];
    const float* gcn_W           = (const float*)d_in[13];
    const float* gcn_b           = (const float*)d_in[14];
    const float* attn_Wq         = (const float*)d_in[15];
    const float* attn_Wk         = (const float*)d_in[16];
    const float* attn_Wv         = (const float*)d_in[17];
    const float* lstm_Wih        = (const float*)d_in[18];
    const float* lstm_Whh        = (const float*)d_in[19];
    const float* lstm_b          = (const float*)d_in[20];
    const float* mha_inW         = (const float*)d_in[21];
    const float* mha_inb         = (const float*)d_in[22];
    const float* mha_outW        = (const float*)d_in[23];
    const float* mha_outb        = (const float*)d_in[24];
    const float* pred_W          = (const float*)d_in[25];
    const float* pred_b          = (const float*)d_in[26];
    const float* mW              = (const float*)d_in[27];
    const float* mb              = (const float*)d_in[28];
    const float* bW              = (const float*)d_in[29];
    const float* bb              = (const float*)d_in[30];
    float* out = (float*)d_out;

    void* p;
#define SYMF(var, sym) cudaGetSymbolAddress(&p, sym); float* var = (float*)p;
#define SYMB(var, sym) cudaGetSymbolAddress(&p, sym); bf16* var = (bf16*)p;
    SYMF(enc,   g_enc);    SYMF(feats, g_feats);  SYMF(tmp,   g_tmp);
    SYMF(x1,    g_x1);     SYMF(xq,    g_xq);     SYMF(xk,    g_xk);
    SYMF(xv,    g_xv);     SYMF(att,   g_att);
    SYMF(ih,    g_ih);     SYMF(hh,    g_hh);
    SYMF(cbuf,  g_c);      SYMF(hs1,   g_hs1);
    SYMF(hf,    g_hf);     SYMF(tf,    g_tf);
    SYMF(qb,    g_q);      SYMF(kb,    g_k);      SYMF(vb,    g_v);
    SYMF(pinfo, g_pinfo);  SYMF(hid,   g_hid);
    SYMB(ah,  g_ah);  SYMB(al,  g_al);
    SYMB(sh,  g_sh);  SYMB(sl,  g_sl);
    SYMB(hch, g_hch); SYMB(hcl, g_hcl);
    SYMB(w1h, g_w1h); SYMB(w1l, g_w1l);
    SYMB(w2h, g_w2h); SYMB(w2l, g_w2l);
    SYMB(wph, g_wph); SYMB(wpl, g_wpl);
    cudaGetSymbolAddress(&p, g_validany); int* validany = (int*)p;
    cudaGetSymbolAddress(&p, g_cnt);      int* cntdev = (int*)p;
#undef SYMF
#undef SYMB

    // permutation + counts (needed before LSTM; launch early)
    build_perm_kernel<<<1, 1024>>>(path_lens);

    // 1) enc
    build_enc_kernel<<<Bq * Sq, 256>>>(encoder_outputs, entity_type, entity_id, type_emb, id_emb, enc);

    // 2) x0 = sub2words @ enc
    gemm(false, sub2words, enc, nullptr, nullptr, feats,
         Nq, D0q, Sq, Sq, D0q, BANKq, 0,
         (long)Nq * Sq, (long)Sq * D0q, (long)Nq * BANKq, 0, Bq, 1.f, 0);

    // 3) tmp = adj @ x0
    gemm(false, adj, feats, nullptr, nullptr, tmp,
         Nq, D0q, Nq, Nq, BANKq, D0q, 0,
         (long)Nq * Nq, (long)Nq * BANKq, (long)Nq * D0q, 0, Bq, 1.f, 0);

    // 4) xg0
    gemm(false, tmp, gcn0_W, gcn0_b, nullptr, feats + 808,
         Nq, Gq, D0q, D0q, Gq, BANKq, 0,
         (long)Nq * D0q, 0, (long)Nq * BANKq, 0, Bq, 1.f, 0);

    // 5) GCN + graph-attention layers
    int xoff[NLq]   = {808, 1064};
    int outoff[NLq] = {1064, 1320};
    for (int l = 0; l < NLq; l++) {
        const float* x = feats + xoff[l];
        gemm(false, adj, x, nullptr, nullptr, tmp,
             Nq, Gq, Nq, Nq, BANKq, Gq, 0,
             (long)Nq * Nq, (long)Nq * BANKq, (long)Nq * Gq, 0, Bq, 1.f, 0);
        gemm(false, tmp, gcn_W + (long)l * Gq * Gq, gcn_b + l * Gq, nullptr, x1,
             Nq, Gq, Gq, Gq, Gq, Gq, 0,
             (long)Nq * Gq, 0, (long)Nq * Gq, 0, Bq, 1.f, 1);
        gemm(false, x, attn_Wq + (long)l * Gq * Gq, nullptr, nullptr, xq,
             Nq, Gq, Gq, BANKq, Gq, Gq, 0,
             (long)Nq * BANKq, 0, (long)Nq * Gq, 0, Bq, 1.f, 0);
        gemm(false, x1, attn_Wk + (long)l * Gq * Gq, nullptr, nullptr, xk,
             Nq, Gq, Gq, Gq, Gq, Gq, 0,
             (long)Nq * Gq, 0, (long)Nq * Gq, 0, Bq, 1.f, 0);
        gemm(false, x1, attn_Wv + (long)l * Gq * Gq, nullptr, nullptr, xv,
             Nq, Gq, Gq, Gq, Gq, Gq, 0,
             (long)Nq * Gq, 0, (long)Nq * Gq, 0, Bq, 1.f, 0);
        gemm(true, xq, xk, nullptr, nullptr, att,
             Nq, Nq, Gq, Gq, Gq, Nq, 0,
             (long)Nq * Gq, (long)Nq * Gq, (long)Nq * Nq, 0, Bq, 0.0625f, 0);
        softmax256_kernel<<<Bq * Nq, 256>>>(att);
        gemm(false, att, xv, nullptr, x1, feats + outoff[l],
             Nq, Gq, Nq, Nq, Gq, BANKq, Gq,
             (long)Nq * Nq, (long)Nq * Gq, (long)Nq * BANKq, (long)Nq * Gq, Bq, 1.f, 1);
    }

    // pred weight transpose-split
    {
        dim3 grid((BANK5q + 31) / 32, (BANK5q + 31) / 32);
        transpose_split_kernel<<<grid, dim3(32, 8)>>>(pred_W, wph, wpl, BANK5q, BANK5q);
    }

    const size_t W4 = (size_t)BANK4q * BANKq;
    dim3 cg((BANKq + 255) / 256, Mlstm);
    dim3 cg1((BANKq + 255) / 256, BPq);

    // ===== LSTM layer 0 (prefix dedup + length compaction) =====
    {
        const float* Wih0 = lstm_Wih;
        const float* Whh0 = lstm_Whh;
        const float* b0   = lstm_b;
        split(feats, sh, sl, (size_t)Bq * Nq * BANKq);
        split(Wih0, w1h, w1l, W4);
        split(Whh0, w2h, w2l, W4);
        // proj = feats @ Wih0^T + b0 (1024 x 6304) in hh buffer
        gemm_bf16(sh, sl, w1h, w1l, b0, hh, BPq, BANK4q, BANKq, 0);
        // ih slices t=1..3 (compacted, count-limited)
        gather_ih_l0_kernel<<<3 * Mlstm, 256>>>(hh, path_nodes, ih);
        // candidate t=0 states on 1024 distinct rows
        cand_cell_kernel<<<cg1, 256>>>(hh, qb /*ccand*/, hch, hcl);
        // distribute: running h/c + seq t=0 slice (compacted)
        gather0_kernel<<<Mlstm, 256>>>(hch, hcl, qb, path_nodes, sh, sl, cbuf, ah, al, nullptr);
        // t=1 hh via dedup
        gemm_bf16(hch, hcl, w2h, w2l, nullptr, hid, BPq, BANK4q, BANKq, 0);
        gather_w64_kernel<<<Mlstm, 256>>>(hid, path_nodes, hh, 1);
        for (int t = 1; t < Lq; t++) {
            if (t > 1)
                gemm_bf16(sh, sl, w2h, w2l, nullptr, hh, Mlstm, BANK4q, BANKq, 0, cntdev + t);
            lstm_cell_kernel<<<cg, 256>>>(ih, hh, sh, sl, ah, al, cbuf, nullptr, t);
        }
    }

    // ===== LSTM layer 1 (same dedup + compaction) =====
    {
        const float* Wih1 = lstm_Wih + W4;
        const float* Whh1 = lstm_Whh + W4;
        const float* b1   = lstm_b + BANK4q;
        split(Wih1, w1h, w1l, W4);
        split(Whh1, w2h, w2l, W4);
        // ihproj0 = hcand_L0 @ Wih1^T + b1 (1024 rows) -> hid  (t=0 goes via cand path; no gather needed)
        gemm_bf16(hch, hcl, w1h, w1l, b1, hid, BPq, BANK4q, BANKq, 0);
        // ih slices t=1..3 from layer-0 seq (compacted), count-limited per t
        for (int t = 1; t < Lq; t++)
            gemm_bf16(ah + (size_t)t * Mlstm * BANKq, al + (size_t)t * Mlstm * BANKq,
                      w1h, w1l, b1, ih + (size_t)t * Mlstm * BANK4q,
                      Mlstm, BANK4q, BANKq, 0, cntdev + t);
        // candidate layer-1 t=0 states (reads hid=ihproj0)
        cand_cell_kernel<<<cg1, 256>>>(hid, qb, hch, hcl);
        // distribute: running h/c + hs1 t=0 slice (compacted)
        gather0_kernel<<<Mlstm, 256>>>(hch, hcl, qb, path_nodes, sh, sl, cbuf,
                                       nullptr, nullptr, hs1);
        // t=1 hh via dedup
        gemm_bf16(hch, hcl, w2h, w2l, nullptr, hid, BPq, BANK4q, BANKq, 0);
        gather_w64_kernel<<<Mlstm, 256>>>(hid, path_nodes, hh, 1);
        for (int t = 1; t < Lq; t++) {
            if (t > 1)
                gemm_bf16(sh, sl, w2h, w2l, nullptr, hh, Mlstm, BANK4q, BANKq, 0, cntdev + t);
            lstm_cell_kernel<<<cg, 256>>>(ih, hh, sh, sl, nullptr, nullptr, cbuf, hs1, t);
        }
    }

    // 8) masked max-pool (compacted -> scatter to orig) -> split bf16 into ah/al
    maxpool_split_kernel<<<cg, 256>>>(hs1, path_lens, ah, al);

    // 9) h_f, t_f, query (split)
    gather_ht_kernel<<<BPq, 256>>>(feats, h_t_pairs, hf, tf, sh, sl);

    // 10-11) q/k/v projections
    split(mha_inW, w1h, w1l, (size_t)3 * BANKq * BANKq);
    gemm_bf16(sh, sl, w1h, w1l, mha_inb, qb, BPq, BANKq, BANKq, 0);
    gemm_bf16(ah, al, w1h + (size_t)BANKq * BANKq, w1l + (size_t)BANKq * BANKq,
              mha_inb + BANKq, kb, Mlstm, BANKq, BANKq, 0);
    gemm_bf16(ah, al, w1h + 2 * (size_t)BANKq * BANKq, w1l + 2 * (size_t)BANKq * BANKq,
              mha_inb + 2 * BANKq, vb, Mlstm, BANKq, BANKq, 0);

    // 12) tiny attention over K=3 paths (ctx split into sh/sl)
    mha_attn_kernel<<<BPq, 384>>>(qb, kb, vb, path_lens, rel_mask, sh, sl, validany);

    // 13) pinfo
    split(mha_outW, w2h, w2l, (size_t)BANKq * BANKq);
    gemm_bf16(sh, sl, w2h, w2l, mha_outb, pinfo, BPq, BANKq, BANKq, 0);

    // 14) of (split into ah/al)
    build_of_split_kernel<<<BPq, 256>>>(hf, tf, pinfo, validany, ah, al);

    // 15) hid = relu(of @ pred_W + pred_b)
    gemm_bf16(ah, al, wph, wpl, pred_b, hid, BPq, BANK5q, BANK5q, 1);

    // 16) fused output heads
    head_kernel<<<BPq, 256>>>(hid, mW, mb, bW, bb, out);
}

// round 12
// speedup vs baseline: 3.0028x; 1.0362x over previous
#include <cuda_runtime.h>
#include <cuda_bf16.h>
#include <math.h>
#include <stdio.h>

// ---------------- problem constants ----------------
#define Bq   4
#define Sq   512
#define Nq   256
#define Eq   42
#define Pq   256
#define Kq   3
#define Lq   4
#define HBq  768
#define DTq  20
#define DIq  20
#define Gq   256
#define NLq  2
#define Rq   97
#define NHq  4
#define D0q  808          // HB+DT+DI
#define BANKq 1576        // D0 + G*(NL+1)
#define BANK4q 6304       // 4*BANK
#define BANK5q 7880       // 5*BANK
#define DHq  394          // BANK/NH
#define Mlstm (Bq*Pq*Kq)        // 3072
#define MlstmT (Mlstm*Lq)       // 12288
#define BPq  (Bq*Pq)            // 1024

typedef __nv_bfloat16 bf16;
typedef __nv_bfloat162 bf162;

// ---------------- scratch (static device memory; no allocations allowed) ----------------
__device__ float g_enc   [Bq*Sq*D0q];
__device__ float g_feats [Bq*Nq*BANKq];
__device__ float g_tmp   [Bq*Nq*D0q];
__device__ float g_x1    [Bq*Nq*Gq];
__device__ float g_xq    [Bq*Nq*Gq];
__device__ float g_xk    [Bq*Nq*Gq];
__device__ float g_xv    [Bq*Nq*Gq];
__device__ float g_att   [Bq*Nq*Nq];
__device__ float g_ih    [(size_t)MlstmT*BANK4q];   // t-major
__device__ float g_hh    [(size_t)Mlstm*BANK4q];
__device__ float g_c     [Mlstm*BANKq];
__device__ float g_hs1   [MlstmT*BANKq];            // t-major, compacted rows
__device__ float g_hf    [BPq*BANKq];
__device__ float g_tf    [BPq*BANKq];
__device__ float g_q     [BPq*BANKq];               // qb / ccand scratch
__device__ float g_k     [Mlstm*BANKq];
__device__ float g_v     [Mlstm*BANKq];
__device__ float g_pinfo [BPq*BANKq];
__device__ int   g_validany[BPq];
__device__ float g_hid   [BPq*BANK5q];              // also proj scratch

// length-compaction state
__device__ int g_perm[Mlstm];                       // compacted slot -> orig row
__device__ int g_iperm[Mlstm];                      // orig row -> compacted slot
__device__ int g_cnt[4];                            // cnt[t] = #rows with len > t

// bf16 split scratch
__device__ bf16 g_ah  [(size_t)MlstmT*BANKq];       // layer-0 seq (t-major compacted); later pe (compacted)
__device__ bf16 g_al  [(size_t)MlstmT*BANKq];
__device__ bf16 g_sh  [(size_t)Mlstm*BANKq];
__device__ bf16 g_sl  [(size_t)Mlstm*BANKq];
__device__ bf16 g_hch [(size_t)BPq*BANKq];          // candidate h (1024 distinct rows)
__device__ bf16 g_hcl [(size_t)BPq*BANKq];
__device__ bf16 g_w1h [(size_t)BANK4q*BANKq];
__device__ bf16 g_w1l [(size_t)BANK4q*BANKq];
__device__ bf16 g_w2h [(size_t)BANK4q*BANKq];
__device__ bf16 g_w2l [(size_t)BANK4q*BANKq];
__device__ bf16 g_wph [(size_t)BANK5q*BANK5q];
__device__ bf16 g_wpl [(size_t)BANK5q*BANK5q];

// ================= fp32 tiled GEMM (small GCN ops + heads) =================
template <bool TRANSB>
__global__ void __launch_bounds__(256)
gemm32_kernel(const float* __restrict__ A, const float* __restrict__ B,
              const float* __restrict__ bias, const float* __restrict__ resid,
              float* __restrict__ C,
              int M, int N, int K,
              int lda, int ldb, int ldc, int ldr,
              long sA, long sB, long sC, long sR,
              float alpha, int act)
{
    int bz = blockIdx.z;
    A += bz * sA; B += bz * sB; C += bz * sC;
    if (resid) resid += bz * sR;

    int row0 = blockIdx.y * 32;
    int col0 = blockIdx.x * 32;

    __shared__ float As[32][33];
    __shared__ float Bs[32][33];

    int tid = threadIdx.x;
    int tx = tid & 15, ty = tid >> 4;

    float acc[2][2] = {{0.f, 0.f}, {0.f, 0.f}};

    for (int k0 = 0; k0 < K; k0 += 32) {
#pragma unroll
        for (int l = 0; l < 4; l++) {
            int idx = tid + l * 256;
            int m = idx >> 5, kk = idx & 31;
            int gr = row0 + m, gk = k0 + kk;
            As[kk][m] = (gr < M && gk < K) ? A[(long)gr * lda + gk] : 0.f;
        }
#pragma unroll
        for (int l = 0; l < 4; l++) {
            int idx = tid + l * 256;
            if (TRANSB) {
                int n = idx >> 5, kk = idx & 31;
                int gn = col0 + n, gk = k0 + kk;
                Bs[kk][n] = (gn < N && gk < K) ? B[(long)gn * ldb + gk] : 0.f;
            } else {
                int kk = idx >> 5, n = idx & 31;
                int gn = col0 + n, gk = k0 + kk;
                Bs[kk][n] = (gn < N && gk < K) ? B[(long)gk * ldb + gn] : 0.f;
            }
        }
        __syncthreads();
#pragma unroll
        for (int kk = 0; kk < 32; kk++) {
            float a0 = As[kk][ty], a1 = As[kk][ty + 16];
            float b0 = Bs[kk][tx], b1 = Bs[kk][tx + 16];
            acc[0][0] = fmaf(a0, b0, acc[0][0]);
            acc[0][1] = fmaf(a0, b1, acc[0][1]);
            acc[1][0] = fmaf(a1, b0, acc[1][0]);
            acc[1][1] = fmaf(a1, b1, acc[1][1]);
        }
        __syncthreads();
    }

#pragma unroll
    for (int i = 0; i < 2; i++) {
        int r = row0 + ty + 16 * i;
        if (r >= M) continue;
#pragma unroll
        for (int j = 0; j < 2; j++) {
            int cc = col0 + tx + 16 * j;
            if (cc >= N) continue;
            float v = acc[i][j] * alpha;
            if (bias) v += bias[cc];
            if (act == 1) v = fmaxf(v, 0.f);
            if (resid) v += resid[(long)r * ldr + cc];
            C[(long)r * ldc + cc] = v;
        }
    }
}

static void gemm(bool transB,
                 const float* A, const float* B, const float* bias, const float* resid, float* C,
                 int M, int N, int K, int lda, int ldb, int ldc, int ldr,
                 long sA, long sB, long sC, long sR, int batch, float alpha, int act)
{
    dim3 grid((N + 31) / 32, (M + 31) / 32, batch);
    if (transB)
        gemm32_kernel<true><<<grid, 256>>>(A, B, bias, resid, C, M, N, K, lda, ldb, ldc, ldr, sA, sB, sC, sR, alpha, act);
    else
        gemm32_kernel<false><<<grid, 256>>>(A, B, bias, resid, C, M, N, K, lda, ldb, ldc, ldr, sA, sB, sC, sR, alpha, act);
}

// ================= bf16 split-precision tensor-core GEMM (verified R6 loop + Mdev) =================
#define LDSB 40
#define GSTG 3
#define PLANE_E (128*LDSB)
#define PLANE_B (PLANE_E*2)
#define STAGE_B (4*PLANE_B)

#define MMA_BF16(d, a, b) asm volatile( \
    "mma.sync.aligned.m16n8k16.row.col.f32.bf16.bf16.f32 " \
    "{%0,%1,%2,%3}, {%4,%5,%6,%7}, {%8,%9}, {%0,%1,%2,%3};" \
    : "+f"((d)[0]), "+f"((d)[1]), "+f"((d)[2]), "+f"((d)[3]) \
    : "r"((a)[0]), "r"((a)[1]), "r"((a)[2]), "r"((a)[3]), "r"((b)[0]), "r"((b)[1]))

#define LDSM4(r, addr) asm volatile( \
    "ldmatrix.sync.aligned.m8n8.x4.shared.b16 {%0,%1,%2,%3}, [%4];" \
    : "=r"((r)[0]), "=r"((r)[1]), "=r"((r)[2]), "=r"((r)[3]) : "r"(addr))

__device__ __forceinline__ void cpasync16(unsigned saddr, const void* g, int srcbytes)
{
    asm volatile("cp.async.cg.shared.global [%0], [%1], 16, %2;\n"
                 :: "r"(saddr), "l"(g), "r"(srcbytes));
}

__device__ __forceinline__ void gbf_prefetch(
    const bf16* __restrict__ Ah, const bf16* __restrict__ Al,
    const bf16* __restrict__ Bh, const bf16* __restrict__ Bl,
    long row0, long col0, int M, int N, int K,
    int kt, int T, unsigned sbase, int stg, int tid)
{
    if (kt >= T) return;
    long k0 = (long)kt * 32;
    unsigned sst = sbase + (unsigned)stg * STAGE_B;
#pragma unroll
    for (int i = 0; i < 2; i++) {
        int c = tid + i * 256;
        int r = c >> 2;
        int ko = (c & 3) * 8;
        long gk = k0 + ko;
        bool kok = gk < K;
        long gkc = kok ? gk : 0;
        unsigned soff = (unsigned)((r * LDSB + ko) * 2);
        {
            long gr = row0 + r;
            bool ok = kok && (gr < M);
            long grc = ok ? gr : 0;
            int nb = ok ? 16 : 0;
            cpasync16(sst + soff,            Ah + grc * K + gkc, nb);
            cpasync16(sst + PLANE_B + soff,  Al + grc * K + gkc, nb);
        }
        {
            long gn = col0 + r;
            bool ok = kok && (gn < N);
            long gnc = ok ? gn : 0;
            int nb = ok ? 16 : 0;
            cpasync16(sst + 2 * PLANE_B + soff, Bh + gnc * K + gkc, nb);
            cpasync16(sst + 3 * PLANE_B + soff, Bl + gnc * K + gkc, nb);
        }
    }
}

__global__ void __launch_bounds__(256)
gemm_bf16_kernel(const bf16* __restrict__ Ah, const bf16* __restrict__ Al,
                 const bf16* __restrict__ Bh, const bf16* __restrict__ Bl,
                 const float* __restrict__ bias, float* __restrict__ C,
                 int M, int N, int K, int act, const int* __restrict__ Mdev)
{
    if (Mdev) {
        M = min(M, *Mdev);
        if ((long)blockIdx.y * 128 >= (long)M) return;   // uniform early exit
    }
    extern __shared__ __align__(16) bf16 dsm[];
    unsigned sbase = (unsigned)__cvta_generic_to_shared(dsm);

    int tid = threadIdx.x;
    int warp = tid >> 5, lane = tid & 31;
    int wm = (warp & 1) * 64;
    int wn = (warp >> 1) * 32;
    long row0 = (long)blockIdx.y * 128;
    long col0 = (long)blockIdx.x * 128;

    float acc[4][4][4];
#pragma unroll
    for (int a = 0; a < 4; a++)
#pragma unroll
        for (int b = 0; b < 4; b++)
#pragma unroll
            for (int c = 0; c < 4; c++) acc[a][b][c] = 0.f;

    int am_r = (lane & 7) + ((lane >> 3) & 1) * 8;
    int a_c8 = ((lane >> 4) & 1) * 8;
    int b_r  = (lane & 7) + ((lane >> 4) & 1) * 8;
    int b_c8 = ((lane >> 3) & 1) * 8;

    int T = (K + 31) / 32;

#pragma unroll
    for (int kt = 0; kt < GSTG; kt++) {
        gbf_prefetch(Ah, Al, Bh, Bl, row0, col0, M, N, K, kt, T, sbase, kt, tid);
        asm volatile("cp.async.commit_group;\n");
    }

    for (int kt = 0; kt < T; kt++) {
        asm volatile("cp.async.wait_group %0;\n" :: "n"(GSTG - 1));
        __syncthreads();

        int stg = kt % GSTG;
        unsigned sst = sbase + (unsigned)stg * STAGE_B;
        unsigned aB = sst;
        unsigned bB = sst + 2 * PLANE_B;

#pragma unroll
        for (int ks = 0; ks < 2; ks++) {
            int kb = ks * 16;
            unsigned bh[2][4], bl[2][4];
#pragma unroll
            for (int pp = 0; pp < 2; pp++) {
                unsigned addr = bB + (unsigned)(((wn + pp * 16 + b_r) * LDSB + kb + b_c8) * 2);
                LDSM4(bh[pp], addr);
                LDSM4(bl[pp], addr + PLANE_B);
            }
            unsigned ahf[4][4], alf[4][4];
#pragma unroll
            for (int mi = 0; mi < 4; mi++) {
                unsigned addr = aB + (unsigned)(((wm + mi * 16 + am_r) * LDSB + kb + a_c8) * 2);
                LDSM4(ahf[mi], addr);
                LDSM4(alf[mi], addr + PLANE_B);
            }
#pragma unroll
            for (int mi = 0; mi < 4; mi++)
#pragma unroll
                for (int ni = 0; ni < 4; ni++)
                    MMA_BF16(acc[mi][ni], ahf[mi], (&bh[ni >> 1][(ni & 1) * 2]));
#pragma unroll
            for (int mi = 0; mi < 4; mi++)
#pragma unroll
                for (int ni = 0; ni < 4; ni++)
                    MMA_BF16(acc[mi][ni], ahf[mi], (&bl[ni >> 1][(ni & 1) * 2]));
#pragma unroll
            for (int mi = 0; mi < 4; mi++)
#pragma unroll
                for (int ni = 0; ni < 4; ni++)
                    MMA_BF16(acc[mi][ni], alf[mi], (&bh[ni >> 1][(ni & 1) * 2]));
        }
        __syncthreads();
        gbf_prefetch(Ah, Al, Bh, Bl, row0, col0, M, N, K, kt + GSTG, T, sbase, stg, tid);
        asm volatile("cp.async.commit_group;\n");
    }

#pragma unroll
    for (int mi = 0; mi < 4; mi++) {
#pragma unroll
        for (int ni = 0; ni < 4; ni++) {
            long r = row0 + wm + mi * 16 + (lane >> 2);
            long c = col0 + wn + ni * 8 + (lane & 3) * 2;
#pragma unroll
            for (int half = 0; half < 2; half++) {
                long rr = r + half * 8;
                if (rr >= M) continue;
#pragma unroll
                for (int e = 0; e < 2; e++) {
                    long cc = c + e;
                    if (cc >= N) continue;
                    float v = acc[mi][ni][half * 2 + e];
                    if (bias) v += bias[cc];
                    if (act == 1) v = fmaxf(v, 0.f);
                    C[(size_t)rr * N + cc] = v;
                }
            }
        }
    }
}

static void gemm_bf16(const bf16* Ah, const bf16* Al, const bf16* Bh, const bf16* Bl,
                      const float* bias, float* C, int M, int N, int K, int act,
                      const int* Mdev = nullptr)
{
    static int attr_done = 0;
    if (!attr_done) {
        cudaFuncSetAttribute(gemm_bf16_kernel,
                             cudaFuncAttributeMaxDynamicSharedMemorySize, GSTG * STAGE_B);
        attr_done = 1;
    }
    dim3 grid((N + 127) / 128, (M + 127) / 128);
    gemm_bf16_kernel<<<grid, 256, GSTG * STAGE_B>>>(Ah, Al, Bh, Bl, bias, C, M, N, K, act, Mdev);
}

// ================= conversion kernels =================
__device__ __forceinline__ void split1(float f, bf16& h, bf16& l)
{
    h = __float2bfloat16(f);
    l = __float2bfloat16(f - __bfloat162float(h));
}

__global__ void split_kernel(const float* __restrict__ x, bf16* __restrict__ hi,
                             bf16* __restrict__ lo, size_t n4)
{
    size_t i = (size_t)blockIdx.x * blockDim.x + threadIdx.x;
    if (i >= n4) return;
    float4 f = ((const float4*)x)[i];
    bf16 h0, l0, h1, l1, h2, l2, h3, l3;
    split1(f.x, h0, l0); split1(f.y, h1, l1); split1(f.z, h2, l2); split1(f.w, h3, l3);
    bf162 vh0; vh0.x = h0; vh0.y = h1;
    bf162 vh1; vh1.x = h2; vh1.y = h3;
    bf162 vl0; vl0.x = l0; vl0.y = l1;
    bf162 vl1; vl1.x = l2; vl1.y = l3;
    ((bf162*)hi)[i * 2] = vh0; ((bf162*)hi)[i * 2 + 1] = vh1;
    ((bf162*)lo)[i * 2] = vl0; ((bf162*)lo)[i * 2 + 1] = vl1;
}

static void split(const float* x, bf16* hi, bf16* lo, size_t n)
{
    size_t n4 = n / 4;
    split_kernel<<<(unsigned)((n4 + 255) / 256), 256>>>(x, hi, lo, n4);
}

__global__ void transpose_split_kernel(const float* __restrict__ B, bf16* __restrict__ Th,
                                       bf16* __restrict__ Tl, int K, int N)
{
    __shared__ float tile[32][33];
    int k0 = blockIdx.y * 32, n0 = blockIdx.x * 32;
    int tx = threadIdx.x, ty = threadIdx.y;  // 32 x 8
#pragma unroll
    for (int i = 0; i < 32; i += 8) {
        int k = k0 + ty + i, n = n0 + tx;
        tile[ty + i][tx] = (k < K && n < N) ? B[(size_t)k * N + n] : 0.f;
    }
    __syncthreads();
#pragma unroll
    for (int i = 0; i < 32; i += 8) {
        int n = n0 + ty + i, k = k0 + tx;
        if (n < N && k < K) {
            float f = tile[tx][ty + i];
            bf16 h, l; split1(f, h, l);
            Th[(size_t)n * K + k] = h;
            Tl[(size_t)n * K + k] = l;
        }
    }
}

// ---------------- fast activations ----------------
__device__ __forceinline__ float fsig(float x)
{
    return __fdividef(1.f, 1.f + __expf(-x));
}
__device__ __forceinline__ float ftanh(float x)
{
    x = fminf(fmaxf(x, -15.f), 15.f);
    float e = __expf(-2.f * x);
    return __fdividef(1.f - e, 1.f + e);
}

// ---------------- length-compaction permutation ----------------
__global__ void build_perm_kernel(const int* __restrict__ lens)
{
    __shared__ int slens[Mlstm];
    __shared__ int bins[Lq + 1];
    __shared__ int offs[Lq + 1];
    int tid = threadIdx.x;
    if (tid <= Lq) bins[tid] = 0;
    __syncthreads();
    for (int i = tid; i < Mlstm; i += blockDim.x) {
        int l = lens[i];
        slens[i] = l;
        atomicAdd(&bins[l], 1);
    }
    __syncthreads();
    if (tid == 0) {
        int off = 0;
        for (int l = Lq; l >= 0; l--) { offs[l] = off; off += bins[l]; }
        int c = 0;
        for (int t = Lq - 1; t >= 0; t--) { c += bins[t + 1]; g_cnt[t] = c; }
        int cur[Lq + 1];
        for (int l = 0; l <= Lq; l++) cur[l] = offs[l];
        for (int i = 0; i < Mlstm; i++) {
            int l = slens[i];
            g_perm[cur[l]++] = i;
        }
        for (int i = 0; i < Mlstm; i++) g_iperm[g_perm[i]] = i;
    }
}

// ---------------- small custom kernels ----------------
__global__ void build_enc_kernel(const float* __restrict__ eo, const int* __restrict__ etype,
                                 const int* __restrict__ eid, const float* __restrict__ temb,
                                 const float* __restrict__ iemb, float* __restrict__ enc)
{
    int bs = blockIdx.x;
    const float* src = eo + (long)bs * HBq;
    float* dst = enc + (long)bs * D0q;
    int ty = etype[bs], idv = eid[bs];
    for (int j = threadIdx.x; j < D0q; j += blockDim.x) {
        float v;
        if (j < HBq)            v = src[j];
        else if (j < HBq + DTq) v = temb[ty * DTq + (j - HBq)];
        else                    v = iemb[idv * DIq + (j - HBq - DTq)];
        dst[j] = v;
    }
}

__global__ void softmax256_kernel(float* __restrict__ x)
{
    int row = blockIdx.x;
    int tid = threadIdx.x;
    float v = x[(long)row * 256 + tid];
    __shared__ float red[8];
    int lane = tid & 31, warp = tid >> 5;
    float m = v;
#pragma unroll
    for (int o = 16; o > 0; o >>= 1) m = fmaxf(m, __shfl_xor_sync(0xffffffffu, m, o));
    if (lane == 0) red[warp] = m;
    __syncthreads();
    if (tid == 0) {
        float mm = red[0];
        for (int w = 1; w < 8; w++) mm = fmaxf(mm, red[w]);
        red[0] = mm;
    }
    __syncthreads();
    float mx = red[0];
    float e = expf(v - mx);
    float s = e;
#pragma unroll
    for (int o = 16; o > 0; o >>= 1) s += __shfl_xor_sync(0xffffffffu, s, o);
    __shared__ float red2[8];
    if (lane == 0) red2[warp] = s;
    __syncthreads();
    if (tid == 0) {
        float ss = 0.f;
        for (int w = 0; w < 8; w++) ss += red2[w];
        red2[0] = ss;
    }
    __syncthreads();
    x[(long)row * 256 + tid] = e / red2[0];
}

// layer-0 ih gather (t = 1..3 only; compacted rows)
__global__ void gather_ih_l0_kernel(const float* __restrict__ proj, const int* __restrict__ nodes,
                                    float* __restrict__ ih)
{
    int r = blockIdx.x;
    int t = 1 + r / Mlstm, i = r % Mlstm;
    if (i >= g_cnt[t]) return;
    int orig = g_perm[i];
    int b = orig / (Pq * Kq);
    int node = nodes[orig * Lq + t];
    const float4* src = (const float4*)(proj + ((size_t)(b * Nq + node)) * BANK4q);
    float4* dst = (float4*)(ih + ((size_t)t * Mlstm + i) * BANK4q);
    for (int j = threadIdx.x; j < BANK4q / 4; j += blockDim.x) dst[j] = src[j];
}

__global__ void gather_w64_kernel(const float* __restrict__ src, const int* __restrict__ nodes,
                                  float* __restrict__ dst, int cslot)
{
    int i = blockIdx.x;
    if (i >= g_cnt[cslot]) return;
    int orig = g_perm[i];
    int b = orig / (Pq * Kq);
    int node = nodes[orig * Lq];
    const float4* s = (const float4*)(src + ((size_t)(b * Nq + node)) * BANK4q);
    float4* d = (float4*)(dst + (size_t)i * BANK4q);
    for (int j = threadIdx.x; j < BANK4q / 4; j += blockDim.x) d[j] = s[j];
}

__global__ void cand_cell_kernel(const float* __restrict__ proj, float* __restrict__ ccand,
                                 bf16* __restrict__ hch, bf16* __restrict__ hcl)
{
    int i = blockIdx.y;
    int j = blockIdx.x * blockDim.x + threadIdx.x;
    if (j >= BANKq) return;
    const float* g = proj + (size_t)i * BANK4q;
    float gi = g[j], gg = g[2 * BANKq + j], go = g[3 * BANKq + j];
    float cn = fsig(gi) * ftanh(gg);
    float hn = fsig(go) * ftanh(cn);
    ccand[(size_t)i * BANKq + j] = cn;
    bf16 h, l; split1(hn, h, l);
    hch[(size_t)i * BANKq + j] = h;
    hcl[(size_t)i * BANKq + j] = l;
}

__global__ void gather0_kernel(const bf16* __restrict__ hch, const bf16* __restrict__ hcl,
                               const float* __restrict__ ccand, const int* __restrict__ nodes,
                               bf16* __restrict__ sh, bf16* __restrict__ sl,
                               float* __restrict__ c,
                               bf16* __restrict__ seq_hi, bf16* __restrict__ seq_lo,
                               float* __restrict__ hs)
{
    int i = blockIdx.x;
    int orig = g_perm[i];
    int b = orig / (Pq * Kq);
    size_t idx = ((size_t)(b * Nq + nodes[orig * Lq])) * BANKq;
    size_t dst = (size_t)i * BANKq;
    for (int j = threadIdx.x; j < BANKq; j += blockDim.x) {
        bf16 h = hch[idx + j], l = hcl[idx + j];
        sh[dst + j] = h;
        sl[dst + j] = l;
        c[dst + j] = ccand[idx + j];
        if (seq_hi) { seq_hi[dst + j] = h; seq_lo[dst + j] = l; }
        if (hs) hs[dst + j] = __bfloat162float(h) + __bfloat162float(l);
    }
}

__global__ void lstm_cell_kernel(const float* __restrict__ ih, const float* __restrict__ hh,
                                 bf16* __restrict__ h_hi, bf16* __restrict__ h_lo,
                                 bf16* __restrict__ seq_hi, bf16* __restrict__ seq_lo,
                                 float* __restrict__ c, float* __restrict__ hs, int t)
{
    int i = blockIdx.y;
    if (i >= g_cnt[t]) return;
    int j = blockIdx.x * blockDim.x + threadIdx.x;
    if (j >= BANKq) return;
    const float* g = ih + ((size_t)t * Mlstm + i) * BANK4q;
    const float* hr = hh + (size_t)i * BANK4q;
    float gi = g[j] + hr[j];
    float gf = g[BANKq + j] + hr[BANKq + j];
    float gg = g[2 * BANKq + j] + hr[2 * BANKq + j];
    float go = g[3 * BANKq + j] + hr[3 * BANKq + j];
    float cp = c[(size_t)i * BANKq + j];
    float cn = fsig(gf) * cp + fsig(gi) * ftanh(gg);
    float hn = fsig(go) * ftanh(cn);
    c[(size_t)i * BANKq + j] = cn;
    bf16 h, l; split1(hn, h, l);
    h_hi[(size_t)i * BANKq + j] = h;
    h_lo[(size_t)i * BANKq + j] = l;
    if (seq_hi) {
        seq_hi[((size_t)t * Mlstm + i) * BANKq + j] = h;
        seq_lo[((size_t)t * Mlstm + i) * BANKq + j] = l;
    }
    if (hs) hs[((size_t)t * Mlstm + i) * BANKq + j] = hn;
}

// masked max-pool (compacted t-major hs) -> pe in COMPACTED order (split bf16)
__global__ void maxpool_split_kernel(const float* __restrict__ hs, const int* __restrict__ lens,
                                     bf16* __restrict__ hi, bf16* __restrict__ lo)
{
    int i = blockIdx.y;                   // compacted slot
    int j = blockIdx.x * blockDim.x + threadIdx.x;
    if (j >= BANKq) return;
    int orig = g_perm[i];
    int len = lens[orig];
    float m = -1e9f;
    const float* base = hs + (size_t)i * BANKq + j;
    for (int t = 0; t < Lq; t++)
        if (t < len) m = fmaxf(m, base[(size_t)t * Mlstm * BANKq]);
    float r = (len > 0) ? m : 0.f;
    bf16 h, l; split1(r, h, l);
    hi[(size_t)i * BANKq + j] = h;
    lo[(size_t)i * BANKq + j] = l;
}

// zero the skipped (len==0) tail rows of kb/vb so reads are deterministic
__global__ void zero_kv_tail_kernel(float* __restrict__ kb, float* __restrict__ vb)
{
    int i = blockIdx.x;
    if (i < g_cnt[0]) return;
    float4* k4 = (float4*)(kb + (size_t)i * BANKq);
    float4* v4 = (float4*)(vb + (size_t)i * BANKq);
    float4 z = {0.f, 0.f, 0.f, 0.f};
    for (int j = threadIdx.x; j < BANKq / 4; j += blockDim.x) { k4[j] = z; v4[j] = z; }
}

__global__ void gather_ht_kernel(const float* __restrict__ feats, const int* __restrict__ htp,
                                 float* __restrict__ hf, float* __restrict__ tf,
                                 bf16* __restrict__ qh, bf16* __restrict__ ql)
{
    int bp = blockIdx.x;
    int b = bp / Pq;
    int h0 = htp[bp * 2 + 0], t0 = htp[bp * 2 + 1];
    h0 = (h0 == 0) ? 0 : h0 - 1;
    t0 = (t0 == 0) ? 0 : t0 - 1;
    const float* hsrc = feats + ((size_t)b * Nq + (Nq - Eq) + h0) * BANKq;
    const float* tsrc = feats + ((size_t)b * Nq + (Nq - Eq) + t0) * BANKq;
    for (int j = threadIdx.x; j < BANKq; j += blockDim.x) {
        float hv = hsrc[j], tv = tsrc[j];
        hf[(size_t)bp * BANKq + j] = hv;
        tf[(size_t)bp * BANKq + j] = tv;
        bf16 h, l; split1(hv - tv, h, l);
        qh[(size_t)bp * BANKq + j] = h;
        ql[(size_t)bp * BANKq + j] = l;
    }
}

// k/v stored in COMPACTED order; index via g_iperm
__global__ void mha_attn_kernel(const float* __restrict__ q, const float* __restrict__ k,
                                const float* __restrict__ v, const int* __restrict__ plens,
                                const float* __restrict__ rmask,
                                bf16* __restrict__ ctx_hi, bf16* __restrict__ ctx_lo,
                                int* __restrict__ validany)
{
    int bp = blockIdx.x;
    int tid = threadIdx.x;
    int warp = tid >> 5, lane = tid & 31;
    __shared__ float sc[NHq][Kq];
    __shared__ float aw[NHq][Kq];
    __shared__ int vm[Kq];
    __shared__ int slot[Kq];
    if (tid < Kq) {
        vm[tid] = (rmask[bp] > 0.f && plens[bp * Kq + tid] > 0) ? 1 : 0;
        slot[tid] = g_iperm[bp * Kq + tid];
    }
    __syncthreads();
    {
        int h = warp / Kq, kk = warp % Kq;
        const float* qh = q + (size_t)bp * BANKq + h * DHq;
        const float* kh = k + (size_t)slot[kk] * BANKq + h * DHq;
        float s = 0.f;
        for (int d = lane; d < DHq; d += 32) s += qh[d] * kh[d];
#pragma unroll
        for (int o = 16; o > 0; o >>= 1) s += __shfl_xor_sync(0xffffffffu, s, o);
        if (lane == 0) {
            s = s / sqrtf((float)DHq);
            sc[h][kk] = vm[kk] ? s : -1e9f;
        }
    }
    __syncthreads();
    if (tid < NHq) {
        int h = tid;
        float m = fmaxf(fmaxf(sc[h][0], sc[h][1]), sc[h][2]);
        float e0 = expf(sc[h][0] - m), e1 = expf(sc[h][1] - m), e2 = expf(sc[h][2] - m);
        float s = e0 + e1 + e2;
        aw[h][0] = e0 / s; aw[h][1] = e1 / s; aw[h][2] = e2 / s;
    }
    if (tid == 0) validany[bp] = (vm[0] | vm[1] | vm[2]);
    __syncthreads();
    const float* v0 = v + (size_t)slot[0] * BANKq;
    const float* v1 = v + (size_t)slot[1] * BANKq;
    const float* v2 = v + (size_t)slot[2] * BANKq;
    for (int j = tid; j < BANKq; j += blockDim.x) {
        int h = j / DHq;
        float r = aw[h][0] * v0[j] + aw[h][1] * v1[j] + aw[h][2] * v2[j];
        bf16 hh2, ll2; split1(r, hh2, ll2);
        ctx_hi[(size_t)bp * BANKq + j] = hh2;
        ctx_lo[(size_t)bp * BANKq + j] = ll2;
    }
}

__global__ void build_of_split_kernel(const float* __restrict__ hf, const float* __restrict__ tf,
                                      const float* __restrict__ pinfo, const int* __restrict__ validany,
                                      bf16* __restrict__ oh, bf16* __restrict__ ol)
{
    int bp = blockIdx.x;
    int va = validany[bp];
    const float* hr = hf + (size_t)bp * BANKq;
    const float* tr = tf + (size_t)bp * BANKq;
    const float* pr = pinfo + (size_t)bp * BANKq;
    size_t base = (size_t)bp * BANK5q;
    for (int j = threadIdx.x; j < BANK5q; j += blockDim.x) {
        int seg = j / BANKq, jj = j - seg * BANKq;
        float v;
        if (seg == 0)      v = hr[jj];
        else if (seg == 1) v = tr[jj];
        else if (seg == 2) v = fabsf(hr[jj] - tr[jj]);
        else if (seg == 3) v = hr[jj] * tr[jj];
        else               v = va ? pr[jj] : 0.f;
        bf16 h, l; split1(v, h, l);
        oh[base + j] = h;
        ol[base + j] = l;
    }
}

// small head for the N=2 output
__global__ void __launch_bounds__(256)
head2_kernel(const float* __restrict__ hid, const float* __restrict__ bW,
             const float* __restrict__ bb, float* __restrict__ out2)
{
    int m = blockIdx.x;
    int tid = threadIdx.x, lane = tid & 31, warp = tid >> 5;
    const float* hr = hid + (size_t)m * BANK5q;
    float a0 = 0.f, a1 = 0.f;
    for (int k = tid; k < BANK5q; k += 256) {
        float h = hr[k];
        a0 = fmaf(h, bW[(size_t)k * 2], a0);
        a1 = fmaf(h, bW[(size_t)k * 2 + 1], a1);
    }
#pragma unroll
    for (int o = 16; o > 0; o >>= 1) {
        a0 += __shfl_xor_sync(0xffffffffu, a0, o);
        a1 += __shfl_xor_sync(0xffffffffu, a1, o);
    }
    __shared__ float r0[8], r1[8];
    if (lane == 0) { r0[warp] = a0; r1[warp] = a1; }
    __syncthreads();
    if (tid == 0) {
        float s0 = 0.f, s1 = 0.f;
        for (int w = 0; w < 8; w++) { s0 += r0[w]; s1 += r1[w]; }
        out2[(size_t)m * 2 + 0] = s0 + bb[0];
        out2[(size_t)m * 2 + 1] = s1 + bb[1];
    }
}

// ---------------- orchestration ----------------
extern "C" void kernel_launch(void* const* d_in, const int* in_sizes, int n_in,
                              void* d_out, int out_size)
{
    const float* encoder_outputs = (const float*)d_in[0];
    const int*   entity_type     = (const int*)  d_in[1];
    const int*   entity_id       = (const int*)  d_in[2];
    const float* sub2words       = (const float*)d_in[3];
    const float* adj             = (const float*)d_in[4];
    const int*   h_t_pairs       = (const int*)  d_in[5];
    const float* rel_mask        = (const float*)d_in[6];
    const int*   path_nodes      = (const int*)  d_in[7];
    const int*   path_lens       = (const int*)  d_in[8];
    const float* type_emb        = (const float*)d_in[9];
    const float* id_emb          = (const float*)d_in[10];
    const float* gcn0_W          = (const float*)d_in[11];
    const float* gcn0_b          = (const float*)d_in[12];
    const float* gcn_W           = (const float*)d_in[13];
    const float* gcn_b           = (const float*)d_in[14];
    const float* attn_Wq         = (const float*)d_in[15];
    const float* attn_Wk         = (const float*)d_in[16];
    const float* attn_Wv         = (const float*)d_in[17];
    const float* lstm_Wih        = (const float*)d_in[18];
    const float* lstm_Whh        = (const float*)d_in[19];
    const float* lstm_b          = (const float*)d_in[20];
    const float* mha_inW         = (const float*)d_in[21];
    const float* mha_inb         = (const float*)d_in[22];
    const float* mha_outW        = (const float*)d_in[23];
    const float* mha_outb        = (const float*)d_in[24];
    const float* pred_W          = (const float*)d_in[25];
    const float* pred_b          = (const float*)d_in[26];
    const float* mW              = (const float*)d_in[27];
    const float* mb              = (const float*)d_in[28];
    const float* bW              = (const float*)d_in[29];
    const float* bb              = (const float*)d_in[30];
    float* out = (float*)d_out;

    void* p;
#define SYMF(var, sym) cudaGetSymbolAddress(&p, sym); float* var = (float*)p;
#define SYMB(var, sym) cudaGetSymbolAddress(&p, sym); bf16* var = (bf16*)p;
    SYMF(enc,   g_enc);    SYMF(feats, g_feats);  SYMF(tmp,   g_tmp);
    SYMF(x1,    g_x1);     SYMF(xq,    g_xq);     SYMF(xk,    g_xk);
    SYMF(xv,    g_xv);     SYMF(att,   g_att);
    SYMF(ih,    g_ih);     SYMF(hh,    g_hh);
    SYMF(cbuf,  g_c);      SYMF(hs1,   g_hs1);
    SYMF(hf,    g_hf);     SYMF(tf,    g_tf);
    SYMF(qb,    g_q);      SYMF(kb,    g_k);      SYMF(vb,    g_v);
    SYMF(pinfo, g_pinfo);  SYMF(hid,   g_hid);
    SYMB(ah,  g_ah);  SYMB(al,  g_al);
    SYMB(sh,  g_sh);  SYMB(sl,  g_sl);
    SYMB(hch, g_hch); SYMB(hcl, g_hcl);
    SYMB(w1h, g_w1h); SYMB(w1l, g_w1l);
    SYMB(w2h, g_w2h); SYMB(w2l, g_w2l);
    SYMB(wph, g_wph); SYMB(wpl, g_wpl);
    cudaGetSymbolAddress(&p, g_validany); int* validany = (int*)p;
    cudaGetSymbolAddress(&p, g_cnt);      int* cntdev = (int*)p;
#undef SYMF
#undef SYMB

    // permutation + counts
    build_perm_kernel<<<1, 1024>>>(path_lens);

    // 1) enc
    build_enc_kernel<<<Bq * Sq, 256>>>(encoder_outputs, entity_type, entity_id, type_emb, id_emb, enc);

    // 2) x0 = sub2words @ enc
    gemm(false, sub2words, enc, nullptr, nullptr, feats,
         Nq, D0q, Sq, Sq, D0q, BANKq, 0,
         (long)Nq * Sq, (long)Sq * D0q, (long)Nq * BANKq, 0, Bq, 1.f, 0);

    // 3) tmp = adj @ x0
    gemm(false, adj, feats, nullptr, nullptr, tmp,
         Nq, D0q, Nq, Nq, BANKq, D0q, 0,
         (long)Nq * Nq, (long)Nq * BANKq, (long)Nq * D0q, 0, Bq, 1.f, 0);

    // 4) xg0
    gemm(false, tmp, gcn0_W, gcn0_b, nullptr, feats + 808,
         Nq, Gq, D0q, D0q, Gq, BANKq, 0,
         (long)Nq * D0q, 0, (long)Nq * BANKq, 0, Bq, 1.f, 0);

    // 5) GCN + graph-attention layers
    int xoff[NLq]   = {808, 1064};
    int outoff[NLq] = {1064, 1320};
    for (int l = 0; l < NLq; l++) {
        const float* x = feats + xoff[l];
        gemm(false, adj, x, nullptr, nullptr, tmp,
             Nq, Gq, Nq, Nq, BANKq, Gq, 0,
             (long)Nq * Nq, (long)Nq * BANKq, (long)Nq * Gq, 0, Bq, 1.f, 0);
        gemm(false, tmp, gcn_W + (long)l * Gq * Gq, gcn_b + l * Gq, nullptr, x1,
             Nq, Gq, Gq, Gq, Gq, Gq, 0,
             (long)Nq * Gq, 0, (long)Nq * Gq, 0, Bq, 1.f, 1);
        gemm(false, x, attn_Wq + (long)l * Gq * Gq, nullptr, nullptr, xq,
             Nq, Gq, Gq, BANKq, Gq, Gq, 0,
             (long)Nq * BANKq, 0, (long)Nq * Gq, 0, Bq, 1.f, 0);
        gemm(false, x1, attn_Wk + (long)l * Gq * Gq, nullptr, nullptr, xk,
             Nq, Gq, Gq, Gq, Gq, Gq, 0,
             (long)Nq * Gq, 0, (long)Nq * Gq, 0, Bq, 1.f, 0);
        gemm(false, x1, attn_Wv + (long)l * Gq * Gq, nullptr, nullptr, xv,
             Nq, Gq, Gq, Gq, Gq, Gq, 0,
             (long)Nq * Gq, 0, (long)Nq * Gq, 0, Bq, 1.f, 0);
        gemm(true, xq, xk, nullptr, nullptr, att,
             Nq, Nq, Gq, Gq, Gq, Nq, 0,
             (long)Nq * Gq, (long)Nq * Gq, (long)Nq * Nq, 0, Bq, 0.0625f, 0);
        softmax256_kernel<<<Bq * Nq, 256>>>(att);
        gemm(false, att, xv, nullptr, x1, feats + outoff[l],
             Nq, Gq, Nq, Nq, Gq, BANKq, Gq,
             (long)Nq * Nq, (long)Nq * Gq, (long)Nq * BANKq, (long)Nq * Gq, Bq, 1.f, 1);
    }

    // pred weight transpose-split
    {
        dim3 grid((BANK5q + 31) / 32, (BANK5q + 31) / 32);
        transpose_split_kernel<<<grid, dim3(32, 8)>>>(pred_W, wph, wpl, BANK5q, BANK5q);
    }

    const size_t W4 = (size_t)BANK4q * BANKq;
    dim3 cg((BANKq + 255) / 256, Mlstm);
    dim3 cg1((BANKq + 255) / 256, BPq);

    // ===== LSTM layer 0 (prefix dedup + length compaction) =====
    {
        const float* Wih0 = lstm_Wih;
        const float* Whh0 = lstm_Whh;
        const float* b0   = lstm_b;
        split(feats, sh, sl, (size_t)Bq * Nq * BANKq);
        split(Wih0, w1h, w1l, W4);
        split(Whh0, w2h, w2l, W4);
        gemm_bf16(sh, sl, w1h, w1l, b0, hh, BPq, BANK4q, BANKq, 0);
        gather_ih_l0_kernel<<<3 * Mlstm, 256>>>(hh, path_nodes, ih);
        cand_cell_kernel<<<cg1, 256>>>(hh, qb, hch, hcl);
        gather0_kernel<<<Mlstm, 256>>>(hch, hcl, qb, path_nodes, sh, sl, cbuf, ah, al, nullptr);
        gemm_bf16(hch, hcl, w2h, w2l, nullptr, hid, BPq, BANK4q, BANKq, 0);
        gather_w64_kernel<<<Mlstm, 256>>>(hid, path_nodes, hh, 1);
        for (int t = 1; t < Lq; t++) {
            if (t > 1)
                gemm_bf16(sh, sl, w2h, w2l, nullptr, hh, Mlstm, BANK4q, BANKq, 0, cntdev + t);
            lstm_cell_kernel<<<cg, 256>>>(ih, hh, sh, sl, ah, al, cbuf, nullptr, t);
        }
    }

    // ===== LSTM layer 1 (same dedup + compaction) =====
    {
        const float* Wih1 = lstm_Wih + W4;
        const float* Whh1 = lstm_Whh + W4;
        const float* b1   = lstm_b + BANK4q;
        split(Wih1, w1h, w1l, W4);
        split(Whh1, w2h, w2l, W4);
        gemm_bf16(hch, hcl, w1h, w1l, b1, hid, BPq, BANK4q, BANKq, 0);
        for (int t = 1; t < Lq; t++)
            gemm_bf16(ah + (size_t)t * Mlstm * BANKq, al + (size_t)t * Mlstm * BANKq,
                      w1h, w1l, b1, ih + (size_t)t * Mlstm * BANK4q,
                      Mlstm, BANK4q, BANKq, 0, cntdev + t);
        cand_cell_kernel<<<cg1, 256>>>(hid, qb, hch, hcl);
        gather0_kernel<<<Mlstm, 256>>>(hch, hcl, qb, path_nodes, sh, sl, cbuf,
                                       nullptr, nullptr, hs1);
        gemm_bf16(hch, hcl, w2h, w2l, nullptr, hid, BPq, BANK4q, BANKq, 0);
        gather_w64_kernel<<<Mlstm, 256>>>(hid, path_nodes, hh, 1);
        for (int t = 1; t < Lq; t++) {
            if (t > 1)
                gemm_bf16(sh, sl, w2h, w2l, nullptr, hh, Mlstm, BANK4q, BANKq, 0, cntdev + t);
            lstm_cell_kernel<<<cg, 256>>>(ih, hh, sh, sl, nullptr, nullptr, cbuf, hs1, t);
        }
    }

    // 8) masked max-pool -> pe in COMPACTED order (split bf16 into ah/al)
    maxpool_split_kernel<<<cg, 256>>>(hs1, path_lens, ah, al);

    // 9) h_f, t_f, query (split)
    gather_ht_kernel<<<BPq, 256>>>(feats, h_t_pairs, hf, tf, sh, sl);

    // 10-11) q/k/v projections (k/v compacted + count-limited; tail rows zeroed)
    split(mha_inW, w1h, w1l, (size_t)3 * BANKq * BANKq);
    gemm_bf16(sh, sl, w1h, w1l, mha_inb, qb, BPq, BANKq, BANKq, 0);
    gemm_bf16(ah, al, w1h + (size_t)BANKq * BANKq, w1l + (size_t)BANKq * BANKq,
              mha_inb + BANKq, kb, Mlstm, BANKq, BANKq, 0, cntdev + 0);
    gemm_bf16(ah, al, w1h + 2 * (size_t)BANKq * BANKq, w1l + 2 * (size_t)BANKq * BANKq,
              mha_inb + 2 * BANKq, vb, Mlstm, BANKq, BANKq, 0, cntdev + 0);
    zero_kv_tail_kernel<<<Mlstm, 256>>>(kb, vb);

    // 12) tiny attention over K=3 paths (compacted k/v via iperm; ctx split into sh/sl)
    mha_attn_kernel<<<BPq, 384>>>(qb, kb, vb, path_lens, rel_mask, sh, sl, validany);

    // 13) pinfo
    split(mha_outW, w2h, w2l, (size_t)BANKq * BANKq);
    gemm_bf16(sh, sl, w2h, w2l, mha_outb, pinfo, BPq, BANKq, BANKq, 0);

    // 14) of (split into ah/al)
    build_of_split_kernel<<<BPq, 256>>>(hf, tf, pinfo, validany, ah, al);

    // 15) hid = relu(of @ pred_W + pred_b)
    gemm_bf16(ah, al, wph, wpl, pred_b, hid, BPq, BANK5q, BANK5q, 1);

    // 16) output heads: mW via fp32 GEMM (L2-friendly), bW via lean kernel
    gemm(false, hid, mW, mb, nullptr, out,
         BPq, Rq, BANK5q, BANK5q, Rq, Rq, 0, 0, 0, 0, 0, 1, 1.f, 0);
    head2_kernel<<<BPq, 256>>>(hid, bW, bb, out + (size_t)BPq * Rq);
}

// round 13
// speedup vs baseline: 3.2611x; 1.0860x over previous
#include <cuda_runtime.h>
#include <cuda_bf16.h>
#include <math.h>
#include <stdio.h>

// ---------------- problem constants ----------------
#define Bq   4
#define Sq   512
#define Nq   256
#define Eq   42
#define Pq   256
#define Kq   3
#define Lq   4
#define HBq  768
#define DTq  20
#define DIq  20
#define Gq   256
#define NLq  2
#define Rq   97
#define NHq  4
#define D0q  808          // HB+DT+DI
#define BANKq 1576        // D0 + G*(NL+1)
#define BANK3q 4728       // 3*BANK (abs|prod|pinfo)
#define BANK4q 6304       // 4*BANK
#define BANK5q 7880       // 5*BANK
#define DHq  394          // BANK/NH
#define Mlstm (Bq*Pq*Kq)        // 3072
#define MlstmT (Mlstm*Lq)       // 12288
#define BPq  (Bq*Pq)            // 1024
#define NBANKROWS (Bq*Eq)       // 168 distinct entity-bank rows

typedef __nv_bfloat16 bf16;
typedef __nv_bfloat162 bf162;

// ---------------- scratch (static device memory; no allocations allowed) ----------------
__device__ float g_enc   [Bq*Sq*D0q];
__device__ float g_feats [Bq*Nq*BANKq];
__device__ float g_tmp   [Bq*Nq*D0q];
__device__ float g_x1    [Bq*Nq*Gq];
__device__ float g_xq    [Bq*Nq*Gq];
__device__ float g_xk    [Bq*Nq*Gq];
__device__ float g_xv    [Bq*Nq*Gq];
__device__ float g_att   [Bq*Nq*Nq];
__device__ float g_ih    [(size_t)MlstmT*BANK4q];   // t-major
__device__ float g_hh    [(size_t)Mlstm*BANK4q];
__device__ float g_c     [Mlstm*BANKq];
__device__ float g_hs1   [MlstmT*BANKq];            // t-major, compacted rows
__device__ float g_hf    [BPq*BANKq];
__device__ float g_tf    [BPq*BANKq];
__device__ float g_q     [BPq*BANKq];               // qb / ccand scratch
__device__ float g_k     [Mlstm*BANKq];             // kb; later pred partials p1/p2
__device__ float g_v     [Mlstm*BANKq];
__device__ float g_pinfo [BPq*BANKq];
__device__ int   g_validany[BPq];
__device__ float g_hid   [BPq*BANK5q];              // also proj scratch

// length-compaction state
__device__ int g_perm[Mlstm];
__device__ int g_iperm[Mlstm];
__device__ int g_cnt[4];

// bf16 split scratch
__device__ bf16 g_ah  [(size_t)MlstmT*BANKq];       // layer-0 seq; later pe; later of_rest
__device__ bf16 g_al  [(size_t)MlstmT*BANKq];
__device__ bf16 g_sh  [(size_t)Mlstm*BANKq];
__device__ bf16 g_sl  [(size_t)Mlstm*BANKq];
__device__ bf16 g_hch [(size_t)BPq*BANKq];          // candidate h; later bank split
__device__ bf16 g_hcl [(size_t)BPq*BANKq];
__device__ bf16 g_w1h [(size_t)BANK4q*BANKq];
__device__ bf16 g_w1l [(size_t)BANK4q*BANKq];
__device__ bf16 g_w2h [(size_t)BANK4q*BANKq];
__device__ bf16 g_w2l [(size_t)BANK4q*BANKq];
__device__ bf16 g_wph [(size_t)BANK5q*BANK5q];
__device__ bf16 g_wpl [(size_t)BANK5q*BANK5q];

// ================= fp32 tiled GEMM (small GCN ops + head) =================
template <bool TRANSB>
__global__ void __launch_bounds__(256)
gemm32_kernel(const float* __restrict__ A, const float* __restrict__ B,
              const float* __restrict__ bias, const float* __restrict__ resid,
              float* __restrict__ C,
              int M, int N, int K,
              int lda, int ldb, int ldc, int ldr,
              long sA, long sB, long sC, long sR,
              float alpha, int act)
{
    int bz = blockIdx.z;
    A += bz * sA; B += bz * sB; C += bz * sC;
    if (resid) resid += bz * sR;

    int row0 = blockIdx.y * 32;
    int col0 = blockIdx.x * 32;

    __shared__ float As[32][33];
    __shared__ float Bs[32][33];

    int tid = threadIdx.x;
    int tx = tid & 15, ty = tid >> 4;

    float acc[2][2] = {{0.f, 0.f}, {0.f, 0.f}};

    for (int k0 = 0; k0 < K; k0 += 32) {
#pragma unroll
        for (int l = 0; l < 4; l++) {
            int idx = tid + l * 256;
            int m = idx >> 5, kk = idx & 31;
            int gr = row0 + m, gk = k0 + kk;
            As[kk][m] = (gr < M && gk < K) ? A[(long)gr * lda + gk] : 0.f;
        }
#pragma unroll
        for (int l = 0; l < 4; l++) {
            int idx = tid + l * 256;
            if (TRANSB) {
                int n = idx >> 5, kk = idx & 31;
                int gn = col0 + n, gk = k0 + kk;
                Bs[kk][n] = (gn < N && gk < K) ? B[(long)gn * ldb + gk] : 0.f;
            } else {
                int kk = idx >> 5, n = idx & 31;
                int gn = col0 + n, gk = k0 + kk;
                Bs[kk][n] = (gn < N && gk < K) ? B[(long)gk * ldb + gn] : 0.f;
            }
        }
        __syncthreads();
#pragma unroll
        for (int kk = 0; kk < 32; kk++) {
            float a0 = As[kk][ty], a1 = As[kk][ty + 16];
            float b0 = Bs[kk][tx], b1 = Bs[kk][tx + 16];
            acc[0][0] = fmaf(a0, b0, acc[0][0]);
            acc[0][1] = fmaf(a0, b1, acc[0][1]);
            acc[1][0] = fmaf(a1, b0, acc[1][0]);
            acc[1][1] = fmaf(a1, b1, acc[1][1]);
        }
        __syncthreads();
    }

#pragma unroll
    for (int i = 0; i < 2; i++) {
        int r = row0 + ty + 16 * i;
        if (r >= M) continue;
#pragma unroll
        for (int j = 0; j < 2; j++) {
            int cc = col0 + tx + 16 * j;
            if (cc >= N) continue;
            float v = acc[i][j] * alpha;
            if (bias) v += bias[cc];
            if (act == 1) v = fmaxf(v, 0.f);
            if (resid) v += resid[(long)r * ldr + cc];
            C[(long)r * ldc + cc] = v;
        }
    }
}

static void gemm(bool transB,
                 const float* A, const float* B, const float* bias, const float* resid, float* C,
                 int M, int N, int K, int lda, int ldb, int ldc, int ldr,
                 long sA, long sB, long sC, long sR, int batch, float alpha, int act)
{
    dim3 grid((N + 31) / 32, (M + 31) / 32, batch);
    if (transB)
        gemm32_kernel<true><<<grid, 256>>>(A, B, bias, resid, C, M, N, K, lda, ldb, ldc, ldr, sA, sB, sC, sR, alpha, act);
    else
        gemm32_kernel<false><<<grid, 256>>>(A, B, bias, resid, C, M, N, K, lda, ldb, ldc, ldr, sA, sB, sC, sR, alpha, act);
}

// ================= bf16 split-precision tensor-core GEMM (R6 loop + Mdev + ld) =================
#define LDSB 40
#define GSTG 3
#define PLANE_E (128*LDSB)
#define PLANE_B (PLANE_E*2)
#define STAGE_B (4*PLANE_B)

#define MMA_BF16(d, a, b) asm volatile( \
    "mma.sync.aligned.m16n8k16.row.col.f32.bf16.bf16.f32 " \
    "{%0,%1,%2,%3}, {%4,%5,%6,%7}, {%8,%9}, {%0,%1,%2,%3};" \
    : "+f"((d)[0]), "+f"((d)[1]), "+f"((d)[2]), "+f"((d)[3]) \
    : "r"((a)[0]), "r"((a)[1]), "r"((a)[2]), "r"((a)[3]), "r"((b)[0]), "r"((b)[1]))

#define LDSM4(r, addr) asm volatile( \
    "ldmatrix.sync.aligned.m8n8.x4.shared.b16 {%0,%1,%2,%3}, [%4];" \
    : "=r"((r)[0]), "=r"((r)[1]), "=r"((r)[2]), "=r"((r)[3]) : "r"(addr))

__device__ __forceinline__ void cpasync16(unsigned saddr, const void* g, int srcbytes)
{
    asm volatile("cp.async.cg.shared.global [%0], [%1], 16, %2;\n"
                 :: "r"(saddr), "l"(g), "r"(srcbytes));
}

__device__ __forceinline__ void gbf_prefetch(
    const bf16* __restrict__ Ah, const bf16* __restrict__ Al,
    const bf16* __restrict__ Bh, const bf16* __restrict__ Bl,
    long row0, long col0, int M, int N, int K, int ldA, int ldB,
    int kt, int T, unsigned sbase, int stg, int tid)
{
    if (kt >= T) return;
    long k0 = (long)kt * 32;
    unsigned sst = sbase + (unsigned)stg * STAGE_B;
#pragma unroll
    for (int i = 0; i < 2; i++) {
        int c = tid + i * 256;
        int r = c >> 2;
        int ko = (c & 3) * 8;
        long gk = k0 + ko;
        bool kok = gk < K;
        long gkc = kok ? gk : 0;
        unsigned soff = (unsigned)((r * LDSB + ko) * 2);
        {
            long gr = row0 + r;
            bool ok = kok && (gr < M);
            long grc = ok ? gr : 0;
            int nb = ok ? 16 : 0;
            cpasync16(sst + soff,            Ah + grc * ldA + gkc, nb);
            cpasync16(sst + PLANE_B + soff,  Al + grc * ldA + gkc, nb);
        }
        {
            long gn = col0 + r;
            bool ok = kok && (gn < N);
            long gnc = ok ? gn : 0;
            int nb = ok ? 16 : 0;
            cpasync16(sst + 2 * PLANE_B + soff, Bh + gnc * ldB + gkc, nb);
            cpasync16(sst + 3 * PLANE_B + soff, Bl + gnc * ldB + gkc, nb);
        }
    }
}

__global__ void __launch_bounds__(256)
gemm_bf16_kernel(const bf16* __restrict__ Ah, const bf16* __restrict__ Al,
                 const bf16* __restrict__ Bh, const bf16* __restrict__ Bl,
                 const float* __restrict__ bias, float* __restrict__ C,
                 int M, int N, int K, int act, const int* __restrict__ Mdev,
                 int ldA, int ldB)
{
    if (Mdev) {
        M = min(M, *Mdev);
        if ((long)blockIdx.y * 128 >= (long)M) return;
    }
    extern __shared__ __align__(16) bf16 dsm[];
    unsigned sbase = (unsigned)__cvta_generic_to_shared(dsm);

    int tid = threadIdx.x;
    int warp = tid >> 5, lane = tid & 31;
    int wm = (warp & 1) * 64;
    int wn = (warp >> 1) * 32;
    long row0 = (long)blockIdx.y * 128;
    long col0 = (long)blockIdx.x * 128;

    float acc[4][4][4];
#pragma unroll
    for (int a = 0; a < 4; a++)
#pragma unroll
        for (int b = 0; b < 4; b++)
#pragma unroll
            for (int c = 0; c < 4; c++) acc[a][b][c] = 0.f;

    int am_r = (lane & 7) + ((lane >> 3) & 1) * 8;
    int a_c8 = ((lane >> 4) & 1) * 8;
    int b_r  = (lane & 7) + ((lane >> 4) & 1) * 8;
    int b_c8 = ((lane >> 3) & 1) * 8;

    int T = (K + 31) / 32;

#pragma unroll
    for (int kt = 0; kt < GSTG; kt++) {
        gbf_prefetch(Ah, Al, Bh, Bl, row0, col0, M, N, K, ldA, ldB, kt, T, sbase, kt, tid);
        asm volatile("cp.async.commit_group;\n");
    }

    for (int kt = 0; kt < T; kt++) {
        asm volatile("cp.async.wait_group %0;\n" :: "n"(GSTG - 1));
        __syncthreads();

        int stg = kt % GSTG;
        unsigned sst = sbase + (unsigned)stg * STAGE_B;
        unsigned aB = sst;
        unsigned bB = sst + 2 * PLANE_B;

#pragma unroll
        for (int ks = 0; ks < 2; ks++) {
            int kb = ks * 16;
            unsigned bh[2][4], bl[2][4];
#pragma unroll
            for (int pp = 0; pp < 2; pp++) {
                unsigned addr = bB + (unsigned)(((wn + pp * 16 + b_r) * LDSB + kb + b_c8) * 2);
                LDSM4(bh[pp], addr);
                LDSM4(bl[pp], addr + PLANE_B);
            }
            unsigned ahf[4][4], alf[4][4];
#pragma unroll
            for (int mi = 0; mi < 4; mi++) {
                unsigned addr = aB + (unsigned)(((wm + mi * 16 + am_r) * LDSB + kb + a_c8) * 2);
                LDSM4(ahf[mi], addr);
                LDSM4(alf[mi], addr + PLANE_B);
            }
#pragma unroll
            for (int mi = 0; mi < 4; mi++)
#pragma unroll
                for (int ni = 0; ni < 4; ni++)
                    MMA_BF16(acc[mi][ni], ahf[mi], (&bh[ni >> 1][(ni & 1) * 2]));
#pragma unroll
            for (int mi = 0; mi < 4; mi++)
#pragma unroll
                for (int ni = 0; ni < 4; ni++)
                    MMA_BF16(acc[mi][ni], ahf[mi], (&bl[ni >> 1][(ni & 1) * 2]));
#pragma unroll
            for (int mi = 0; mi < 4; mi++)
#pragma unroll
                for (int ni = 0; ni < 4; ni++)
                    MMA_BF16(acc[mi][ni], alf[mi], (&bh[ni >> 1][(ni & 1) * 2]));
        }
        __syncthreads();
        gbf_prefetch(Ah, Al, Bh, Bl, row0, col0, M, N, K, ldA, ldB, kt + GSTG, T, sbase, stg, tid);
        asm volatile("cp.async.commit_group;\n");
    }

#pragma unroll
    for (int mi = 0; mi < 4; mi++) {
#pragma unroll
        for (int ni = 0; ni < 4; ni++) {
            long r = row0 + wm + mi * 16 + (lane >> 2);
            long c = col0 + wn + ni * 8 + (lane & 3) * 2;
#pragma unroll
            for (int half = 0; half < 2; half++) {
                long rr = r + half * 8;
                if (rr >= M) continue;
#pragma unroll
                for (int e = 0; e < 2; e++) {
                    long cc = c + e;
                    if (cc >= N) continue;
                    float v = acc[mi][ni][half * 2 + e];
                    if (bias) v += bias[cc];
                    if (act == 1) v = fmaxf(v, 0.f);
                    C[(size_t)rr * N + cc] = v;
                }
            }
        }
    }
}

static void gemm_bf16(const bf16* Ah, const bf16* Al, const bf16* Bh, const bf16* Bl,
                      const float* bias, float* C, int M, int N, int K, int act,
                      const int* Mdev = nullptr, int ldA = 0, int ldB = 0)
{
    static int attr_done = 0;
    if (!attr_done) {
        cudaFuncSetAttribute(gemm_bf16_kernel,
                             cudaFuncAttributeMaxDynamicSharedMemorySize, GSTG * STAGE_B);
        attr_done = 1;
    }
    if (ldA == 0) ldA = K;
    if (ldB == 0) ldB = K;
    dim3 grid((N + 127) / 128, (M + 127) / 128);
    gemm_bf16_kernel<<<grid, 256, GSTG * STAGE_B>>>(Ah, Al, Bh, Bl, bias, C, M, N, K, act, Mdev, ldA, ldB);
}

// ================= conversion kernels =================
__device__ __forceinline__ void split1(float f, bf16& h, bf16& l)
{
    h = __float2bfloat16(f);
    l = __float2bfloat16(f - __bfloat162float(h));
}

__global__ void split_kernel(const float* __restrict__ x, bf16* __restrict__ hi,
                             bf16* __restrict__ lo, size_t n4)
{
    size_t i = (size_t)blockIdx.x * blockDim.x + threadIdx.x;
    if (i >= n4) return;
    float4 f = ((const float4*)x)[i];
    bf16 h0, l0, h1, l1, h2, l2, h3, l3;
    split1(f.x, h0, l0); split1(f.y, h1, l1); split1(f.z, h2, l2); split1(f.w, h3, l3);
    bf162 vh0; vh0.x = h0; vh0.y = h1;
    bf162 vh1; vh1.x = h2; vh1.y = h3;
    bf162 vl0; vl0.x = l0; vl0.y = l1;
    bf162 vl1; vl1.x = l2; vl1.y = l3;
    ((bf162*)hi)[i * 2] = vh0; ((bf162*)hi)[i * 2 + 1] = vh1;
    ((bf162*)lo)[i * 2] = vl0; ((bf162*)lo)[i * 2 + 1] = vl1;
}

static void split(const float* x, bf16* hi, bf16* lo, size_t n)
{
    size_t n4 = n / 4;
    split_kernel<<<(unsigned)((n4 + 255) / 256), 256>>>(x, hi, lo, n4);
}

__global__ void transpose_split_kernel(const float* __restrict__ B, bf16* __restrict__ Th,
                                       bf16* __restrict__ Tl, int K, int N)
{
    __shared__ float tile[32][33];
    int k0 = blockIdx.y * 32, n0 = blockIdx.x * 32;
    int tx = threadIdx.x, ty = threadIdx.y;  // 32 x 8
#pragma unroll
    for (int i = 0; i < 32; i += 8) {
        int k = k0 + ty + i, n = n0 + tx;
        tile[ty + i][tx] = (k < K && n < N) ? B[(size_t)k * N + n] : 0.f;
    }
    __syncthreads();
#pragma unroll
    for (int i = 0; i < 32; i += 8) {
        int n = n0 + ty + i, k = k0 + tx;
        if (n < N && k < K) {
            float f = tile[tx][ty + i];
            bf16 h, l; split1(f, h, l);
            Th[(size_t)n * K + k] = h;
            Tl[(size_t)n * K + k] = l;
        }
    }
}

// ---------------- fast activations ----------------
__device__ __forceinline__ float fsig(float x)
{
    return __fdividef(1.f, 1.f + __expf(-x));
}
__device__ __forceinline__ float ftanh(float x)
{
    x = fminf(fmaxf(x, -15.f), 15.f);
    float e = __expf(-2.f * x);
    return __fdividef(1.f - e, 1.f + e);
}

// ---------------- length-compaction permutation ----------------
__global__ void build_perm_kernel(const int* __restrict__ lens)
{
    __shared__ int slens[Mlstm];
    __shared__ int bins[Lq + 1];
    __shared__ int offs[Lq + 1];
    int tid = threadIdx.x;
    if (tid <= Lq) bins[tid] = 0;
    __syncthreads();
    for (int i = tid; i < Mlstm; i += blockDim.x) {
        int l = lens[i];
        slens[i] = l;
        atomicAdd(&bins[l], 1);
    }
    __syncthreads();
    if (tid == 0) {
        int off = 0;
        for (int l = Lq; l >= 0; l--) { offs[l] = off; off += bins[l]; }
        int c = 0;
        for (int t = Lq - 1; t >= 0; t--) { c += bins[t + 1]; g_cnt[t] = c; }
        int cur[Lq + 1];
        for (int l = 0; l <= Lq; l++) cur[l] = offs[l];
        for (int i = 0; i < Mlstm; i++) {
            int l = slens[i];
            g_perm[cur[l]++] = i;
        }
        for (int i = 0; i < Mlstm; i++) g_iperm[g_perm[i]] = i;
    }
}

// ---------------- small custom kernels ----------------
__global__ void build_enc_kernel(const float* __restrict__ eo, const int* __restrict__ etype,
                                 const int* __restrict__ eid, const float* __restrict__ temb,
                                 const float* __restrict__ iemb, float* __restrict__ enc)
{
    int bs = blockIdx.x;
    const float* src = eo + (long)bs * HBq;
    float* dst = enc + (long)bs * D0q;
    int ty = etype[bs], idv = eid[bs];
    for (int j = threadIdx.x; j < D0q; j += blockDim.x) {
        float v;
        if (j < HBq)            v = src[j];
        else if (j < HBq + DTq) v = temb[ty * DTq + (j - HBq)];
        else                    v = iemb[idv * DIq + (j - HBq - DTq)];
        dst[j] = v;
    }
}

__global__ void softmax256_kernel(float* __restrict__ x)
{
    int row = blockIdx.x;
    int tid = threadIdx.x;
    float v = x[(long)row * 256 + tid];
    __shared__ float red[8];
    int lane = tid & 31, warp = tid >> 5;
    float m = v;
#pragma unroll
    for (int o = 16; o > 0; o >>= 1) m = fmaxf(m, __shfl_xor_sync(0xffffffffu, m, o));
    if (lane == 0) red[warp] = m;
    __syncthreads();
    if (tid == 0) {
        float mm = red[0];
        for (int w = 1; w < 8; w++) mm = fmaxf(mm, red[w]);
        red[0] = mm;
    }
    __syncthreads();
    float mx = red[0];
    float e = expf(v - mx);
    float s = e;
#pragma unroll
    for (int o = 16; o > 0; o >>= 1) s += __shfl_xor_sync(0xffffffffu, s, o);
    __shared__ float red2[8];
    if (lane == 0) red2[warp] = s;
    __syncthreads();
    if (tid == 0) {
        float ss = 0.f;
        for (int w = 0; w < 8; w++) ss += red2[w];
        red2[0] = ss;
    }
    __syncthreads();
    x[(long)row * 256 + tid] = e / red2[0];
}

__global__ void gather_ih_l0_kernel(const float* __restrict__ proj, const int* __restrict__ nodes,
                                    float* __restrict__ ih)
{
    int r = blockIdx.x;
    int t = 1 + r / Mlstm, i = r % Mlstm;
    if (i >= g_cnt[t]) return;
    int orig = g_perm[i];
    int b = orig / (Pq * Kq);
    int node = nodes[orig * Lq + t];
    const float4* src = (const float4*)(proj + ((size_t)(b * Nq + node)) * BANK4q);
    float4* dst = (float4*)(ih + ((size_t)t * Mlstm + i) * BANK4q);
    for (int j = threadIdx.x; j < BANK4q / 4; j += blockDim.x) dst[j] = src[j];
}

__global__ void gather_w64_kernel(const float* __restrict__ src, const int* __restrict__ nodes,
                                  float* __restrict__ dst, int cslot)
{
    int i = blockIdx.x;
    if (i >= g_cnt[cslot]) return;
    int orig = g_perm[i];
    int b = orig / (Pq * Kq);
    int node = nodes[orig * Lq];
    const float4* s = (const float4*)(src + ((size_t)(b * Nq + node)) * BANK4q);
    float4* d = (float4*)(dst + (size_t)i * BANK4q);
    for (int j = threadIdx.x; j < BANK4q / 4; j += blockDim.x) d[j] = s[j];
}

__global__ void cand_cell_kernel(const float* __restrict__ proj, float* __restrict__ ccand,
                                 bf16* __restrict__ hch, bf16* __restrict__ hcl)
{
    int i = blockIdx.y;
    int j = blockIdx.x * blockDim.x + threadIdx.x;
    if (j >= BANKq) return;
    const float* g = proj + (size_t)i * BANK4q;
    float gi = g[j], gg = g[2 * BANKq + j], go = g[3 * BANKq + j];
    float cn = fsig(gi) * ftanh(gg);
    float hn = fsig(go) * ftanh(cn);
    ccand[(size_t)i * BANKq + j] = cn;
    bf16 h, l; split1(hn, h, l);
    hch[(size_t)i * BANKq + j] = h;
    hcl[(size_t)i * BANKq + j] = l;
}

__global__ void gather0_kernel(const bf16* __restrict__ hch, const bf16* __restrict__ hcl,
                               const float* __restrict__ ccand, const int* __restrict__ nodes,
                               bf16* __restrict__ sh, bf16* __restrict__ sl,
                               float* __restrict__ c,
                               bf16* __restrict__ seq_hi, bf16* __restrict__ seq_lo,
                               float* __restrict__ hs)
{
    int i = blockIdx.x;
    int orig = g_perm[i];
    int b = orig / (Pq * Kq);
    size_t idx = ((size_t)(b * Nq + nodes[orig * Lq])) * BANKq;
    size_t dst = (size_t)i * BANKq;
    for (int j = threadIdx.x; j < BANKq; j += blockDim.x) {
        bf16 h = hch[idx + j], l = hcl[idx + j];
        sh[dst + j] = h;
        sl[dst + j] = l;
        c[dst + j] = ccand[idx + j];
        if (seq_hi) { seq_hi[dst + j] = h; seq_lo[dst + j] = l; }
        if (hs) hs[dst + j] = __bfloat162float(h) + __bfloat162float(l);
    }
}

__global__ void lstm_cell_kernel(const float* __restrict__ ih, const float* __restrict__ hh,
                                 bf16* __restrict__ h_hi, bf16* __restrict__ h_lo,
                                 bf16* __restrict__ seq_hi, bf16* __restrict__ seq_lo,
                                 float* __restrict__ c, float* __restrict__ hs, int t)
{
    int i = blockIdx.y;
    if (i >= g_cnt[t]) return;
    int j = blockIdx.x * blockDim.x + threadIdx.x;
    if (j >= BANKq) return;
    const float* g = ih + ((size_t)t * Mlstm + i) * BANK4q;
    const float* hr = hh + (size_t)i * BANK4q;
    float gi = g[j] + hr[j];
    float gf = g[BANKq + j] + hr[BANKq + j];
    float gg = g[2 * BANKq + j] + hr[2 * BANKq + j];
    float go = g[3 * BANKq + j] + hr[3 * BANKq + j];
    float cp = c[(size_t)i * BANKq + j];
    float cn = fsig(gf) * cp + fsig(gi) * ftanh(gg);
    float hn = fsig(go) * ftanh(cn);
    c[(size_t)i * BANKq + j] = cn;
    bf16 h, l; split1(hn, h, l);
    h_hi[(size_t)i * BANKq + j] = h;
    h_lo[(size_t)i * BANKq + j] = l;
    if (seq_hi) {
        seq_hi[((size_t)t * Mlstm + i) * BANKq + j] = h;
        seq_lo[((size_t)t * Mlstm + i) * BANKq + j] = l;
    }
    if (hs) hs[((size_t)t * Mlstm + i) * BANKq + j] = hn;
}

__global__ void maxpool_split_kernel(const float* __restrict__ hs, const int* __restrict__ lens,
                                     bf16* __restrict__ hi, bf16* __restrict__ lo)
{
    int i = blockIdx.y;
    int j = blockIdx.x * blockDim.x + threadIdx.x;
    if (j >= BANKq) return;
    int orig = g_perm[i];
    int len = lens[orig];
    float m = -1e9f;
    const float* base = hs + (size_t)i * BANKq + j;
    for (int t = 0; t < Lq; t++)
        if (t < len) m = fmaxf(m, base[(size_t)t * Mlstm * BANKq]);
    float r = (len > 0) ? m : 0.f;
    bf16 h, l; split1(r, h, l);
    hi[(size_t)i * BANKq + j] = h;
    lo[(size_t)i * BANKq + j] = l;
}

__global__ void zero_kv_tail_kernel(float* __restrict__ kb, float* __restrict__ vb)
{
    int i = blockIdx.x;
    if (i < g_cnt[0]) return;
    float4* k4 = (float4*)(kb + (size_t)i * BANKq);
    float4* v4 = (float4*)(vb + (size_t)i * BANKq);
    float4 z = {0.f, 0.f, 0.f, 0.f};
    for (int j = threadIdx.x; j < BANKq / 4; j += blockDim.x) { k4[j] = z; v4[j] = z; }
}

__global__ void gather_ht_kernel(const float* __restrict__ feats, const int* __restrict__ htp,
                                 float* __restrict__ hf, float* __restrict__ tf,
                                 bf16* __restrict__ qh, bf16* __restrict__ ql)
{
    int bp = blockIdx.x;
    int b = bp / Pq;
    int h0 = htp[bp * 2 + 0], t0 = htp[bp * 2 + 1];
    h0 = (h0 == 0) ? 0 : h0 - 1;
    t0 = (t0 == 0) ? 0 : t0 - 1;
    const float* hsrc = feats + ((size_t)b * Nq + (Nq - Eq) + h0) * BANKq;
    const float* tsrc = feats + ((size_t)b * Nq + (Nq - Eq) + t0) * BANKq;
    for (int j = threadIdx.x; j < BANKq; j += blockDim.x) {
        float hv = hsrc[j], tv = tsrc[j];
        hf[(size_t)bp * BANKq + j] = hv;
        tf[(size_t)bp * BANKq + j] = tv;
        bf16 h, l; split1(hv - tv, h, l);
        qh[(size_t)bp * BANKq + j] = h;
        ql[(size_t)bp * BANKq + j] = l;
    }
}

__global__ void mha_attn_kernel(const float* __restrict__ q, const float* __restrict__ k,
                                const float* __restrict__ v, const int* __restrict__ plens,
                                const float* __restrict__ rmask,
                                bf16* __restrict__ ctx_hi, bf16* __restrict__ ctx_lo,
                                int* __restrict__ validany)
{
    int bp = blockIdx.x;
    int tid = threadIdx.x;
    int warp = tid >> 5, lane = tid & 31;
    __shared__ float sc[NHq][Kq];
    __shared__ float aw[NHq][Kq];
    __shared__ int vm[Kq];
    __shared__ int slot[Kq];
    if (tid < Kq) {
        vm[tid] = (rmask[bp] > 0.f && plens[bp * Kq + tid] > 0) ? 1 : 0;
        slot[tid] = g_iperm[bp * Kq + tid];
    }
    __syncthreads();
    {
        int h = warp / Kq, kk = warp % Kq;
        const float* qh = q + (size_t)bp * BANKq + h * DHq;
        const float* kh = k + (size_t)slot[kk] * BANKq + h * DHq;
        float s = 0.f;
        for (int d = lane; d < DHq; d += 32) s += qh[d] * kh[d];
#pragma unroll
        for (int o = 16; o > 0; o >>= 1) s += __shfl_xor_sync(0xffffffffu, s, o);
        if (lane == 0) {
            s = s / sqrtf((float)DHq);
            sc[h][kk] = vm[kk] ? s : -1e9f;
        }
    }
    __syncthreads();
    if (tid < NHq) {
        int h = tid;
        float m = fmaxf(fmaxf(sc[h][0], sc[h][1]), sc[h][2]);
        float e0 = expf(sc[h][0] - m), e1 = expf(sc[h][1] - m), e2 = expf(sc[h][2] - m);
        float s = e0 + e1 + e2;
        aw[h][0] = e0 / s; aw[h][1] = e1 / s; aw[h][2] = e2 / s;
    }
    if (tid == 0) validany[bp] = (vm[0] | vm[1] | vm[2]);
    __syncthreads();
    const float* v0 = v + (size_t)slot[0] * BANKq;
    const float* v1 = v + (size_t)slot[1] * BANKq;
    const float* v2 = v + (size_t)slot[2] * BANKq;
    for (int j = tid; j < BANKq; j += blockDim.x) {
        int h = j / DHq;
        float r = aw[h][0] * v0[j] + aw[h][1] * v1[j] + aw[h][2] * v2[j];
        bf16 hh2, ll2; split1(r, hh2, ll2);
        ctx_hi[(size_t)bp * BANKq + j] = hh2;
        ctx_lo[(size_t)bp * BANKq + j] = ll2;
    }
}

// bank rows -> split bf16 (168 rows)
__global__ void bank_split_kernel(const float* __restrict__ feats,
                                  bf16* __restrict__ bh, bf16* __restrict__ bl)
{
    int i = blockIdx.x;               // 0..167
    int b = i / Eq, e = i % Eq;
    const float* src = feats + ((size_t)b * Nq + (Nq - Eq) + e) * BANKq;
    size_t dst = (size_t)i * BANKq;
    for (int j = threadIdx.x; j < BANKq; j += blockDim.x) {
        bf16 h, l; split1(src[j], h, l);
        bh[dst + j] = h;
        bl[dst + j] = l;
    }
}

// of_rest = [abs, prod, pinfo] (1024 x 4728) split bf16
__global__ void build_of_rest_kernel(const float* __restrict__ hf, const float* __restrict__ tf,
                                     const float* __restrict__ pinfo, const int* __restrict__ validany,
                                     bf16* __restrict__ oh, bf16* __restrict__ ol)
{
    int bp = blockIdx.x;
    int va = validany[bp];
    const float* hr = hf + (size_t)bp * BANKq;
    const float* tr = tf + (size_t)bp * BANKq;
    const float* pr = pinfo + (size_t)bp * BANKq;
    size_t base = (size_t)bp * BANK3q;
    for (int j = threadIdx.x; j < BANK3q; j += blockDim.x) {
        int seg = j / BANKq, jj = j - seg * BANKq;
        float v;
        if (seg == 0)      v = fabsf(hr[jj] - tr[jj]);
        else if (seg == 1) v = hr[jj] * tr[jj];
        else               v = va ? pr[jj] : 0.f;
        bf16 h, l; split1(v, h, l);
        oh[base + j] = h;
        ol[base + j] = l;
    }
}

// hid[r] = relu(hid[r] + p1[bank(h_r)] + p2[bank(t_r)])
__global__ void combine_pred_kernel(float* __restrict__ hid, const float* __restrict__ p1,
                                    const float* __restrict__ p2, const int* __restrict__ htp)
{
    int r = blockIdx.x;               // 0..1023
    int b = r / Pq;
    int h0 = htp[r * 2 + 0], t0 = htp[r * 2 + 1];
    h0 = (h0 == 0) ? 0 : h0 - 1;
    t0 = (t0 == 0) ? 0 : t0 - 1;
    const float* q1 = p1 + (size_t)(b * Eq + h0) * BANK5q;
    const float* q2 = p2 + (size_t)(b * Eq + t0) * BANK5q;
    float* hr = hid + (size_t)r * BANK5q;
    for (int j = threadIdx.x; j < BANK5q; j += blockDim.x)
        hr[j] = fmaxf(hr[j] + q1[j] + q2[j], 0.f);
}

// small head for the N=2 output
__global__ void __launch_bounds__(256)
head2_kernel(const float* __restrict__ hid, const float* __restrict__ bW,
             const float* __restrict__ bb, float* __restrict__ out2)
{
    int m = blockIdx.x;
    int tid = threadIdx.x, lane = tid & 31, warp = tid >> 5;
    const float* hr = hid + (size_t)m * BANK5q;
    float a0 = 0.f, a1 = 0.f;
    for (int k = tid; k < BANK5q; k += 256) {
        float h = hr[k];
        a0 = fmaf(h, bW[(size_t)k * 2], a0);
        a1 = fmaf(h, bW[(size_t)k * 2 + 1], a1);
    }
#pragma unroll
    for (int o = 16; o > 0; o >>= 1) {
        a0 += __shfl_xor_sync(0xffffffffu, a0, o);
        a1 += __shfl_xor_sync(0xffffffffu, a1, o);
    }
    __shared__ float r0[8], r1[8];
    if (lane == 0) { r0[warp] = a0; r1[warp] = a1; }
    __syncthreads();
    if (tid == 0) {
        float s0 = 0.f, s1 = 0.f;
        for (int w = 0; w < 8; w++) { s0 += r0[w]; s1 += r1[w]; }
        out2[(size_t)m * 2 + 0] = s0 + bb[0];
        out2[(size_t)m * 2 + 1] = s1 + bb[1];
    }
}

// ---------------- orchestration ----------------
extern "C" void kernel_launch(void* const* d_in, const int* in_sizes, int n_in,
                              void* d_out, int out_size)
{
    const float* encoder_outputs = (const float*)d_in[0];
    const int*   entity_type     = (const int*)  d_in[1];
    const int*   entity_id       = (const int*)  d_in[2];
    const float* sub2words       = (const float*)d_in[3];
    const float* adj             = (const float*)d_in[4];
    const int*   h_t_pairs       = (const int*)  d_in[5];
    const float* rel_mask        = (const float*)d_in[6];
    const int*   path_nodes      = (const int*)  d_in[7];
    const int*   path_lens       = (const int*)  d_in[8];
    const float* type_emb        = (const float*)d_in[9];
    const float* id_emb          = (const float*)d_in[10];
    const float* gcn0_W          = (const float*)d_in[11];
    const float* gcn0_b          = (const float*)d_in[12];
    const float* gcn_W           = (const float*)d_in[13];
    const float* gcn_b           = (const float*)d_in[14];
    const float* attn_Wq         = (const float*)d_in[15];
    const float* attn_Wk         = (const float*)d_in[16];
    const float* attn_Wv         = (const float*)d_in[17];
    const float* lstm_Wih        = (const float*)d_in[18];
    const float* lstm_Whh        = (const float*)d_in[19];
    const float* lstm_b          = (const float*)d_in[20];
    const float* mha_inW         = (const float*)d_in[21];
    const float* mha_inb         = (const float*)d_in[22];
    const float* mha_outW        = (const float*)d_in[23];
    const float* mha_outb        = (const float*)d_in[24];
    const float* pred_W          = (const float*)d_in[25];
    const float* pred_b          = (const float*)d_in[26];
    const float* mW              = (const float*)d_in[27];
    const float* mb              = (const float*)d_in[28];
    const float* bW              = (const float*)d_in[29];
    const float* bb              = (const float*)d_in[30];
    float* out = (float*)d_out;

    void* p;
#define SYMF(var, sym) cudaGetSymbolAddress(&p, sym); float* var = (float*)p;
#define SYMB(var, sym) cudaGetSymbolAddress(&p, sym); bf16* var = (bf16*)p;
    SYMF(enc,   g_enc);    SYMF(feats, g_feats);  SYMF(tmp,   g_tmp);
    SYMF(x1,    g_x1);     SYMF(xq,    g_xq);     SYMF(xk,    g_xk);
    SYMF(xv,    g_xv);     SYMF(att,   g_att);
    SYMF(ih,    g_ih);     SYMF(hh,    g_hh);
    SYMF(cbuf,  g_c);      SYMF(hs1,   g_hs1);
    SYMF(hf,    g_hf);     SYMF(tf,    g_tf);
    SYMF(qb,    g_q);      SYMF(kb,    g_k);      SYMF(vb,    g_v);
    SYMF(pinfo, g_pinfo);  SYMF(hid,   g_hid);
    SYMB(ah,  g_ah);  SYMB(al,  g_al);
    SYMB(sh,  g_sh);  SYMB(sl,  g_sl);
    SYMB(hch, g_hch); SYMB(hcl, g_hcl);
    SYMB(w1h, g_w1h); SYMB(w1l, g_w1l);
    SYMB(w2h, g_w2h); SYMB(w2l, g_w2l);
    SYMB(wph, g_wph); SYMB(wpl, g_wpl);
    cudaGetSymbolAddress(&p, g_validany); int* validany = (int*)p;
    cudaGetSymbolAddress(&p, g_cnt);      int* cntdev = (int*)p;
#undef SYMF
#undef SYMB

    // permutation + counts
    build_perm_kernel<<<1, 1024>>>(path_lens);

    // 1) enc
    build_enc_kernel<<<Bq * Sq, 256>>>(encoder_outputs, entity_type, entity_id, type_emb, id_emb, enc);

    // 2) x0 = sub2words @ enc
    gemm(false, sub2words, enc, nullptr, nullptr, feats,
         Nq, D0q, Sq, Sq, D0q, BANKq, 0,
         (long)Nq * Sq, (long)Sq * D0q, (long)Nq * BANKq, 0, Bq, 1.f, 0);

    // 3) tmp = adj @ x0
    gemm(false, adj, feats, nullptr, nullptr, tmp,
         Nq, D0q, Nq, Nq, BANKq, D0q, 0,
         (long)Nq * Nq, (long)Nq * BANKq, (long)Nq * D0q, 0, Bq, 1.f, 0);

    // 4) xg0
    gemm(false, tmp, gcn0_W, gcn0_b, nullptr, feats + 808,
         Nq, Gq, D0q, D0q, Gq, BANKq, 0,
         (long)Nq * D0q, 0, (long)Nq * BANKq, 0, Bq, 1.f, 0);

    // 5) GCN + graph-attention layers
    int xoff[NLq]   = {808, 1064};
    int outoff[NLq] = {1064, 1320};
    for (int l = 0; l < NLq; l++) {
        const float* x = feats + xoff[l];
        gemm(false, adj, x, nullptr, nullptr, tmp,
             Nq, Gq, Nq, Nq, BANKq, Gq, 0,
             (long)Nq * Nq, (long)Nq * BANKq, (long)Nq * Gq, 0, Bq, 1.f, 0);
        gemm(false, tmp, gcn_W + (long)l * Gq * Gq, gcn_b + l * Gq, nullptr, x1,
             Nq, Gq, Gq, Gq, Gq, Gq, 0,
             (long)Nq * Gq, 0, (long)Nq * Gq, 0, Bq, 1.f, 1);
        gemm(false, x, attn_Wq + (long)l * Gq * Gq, nullptr, nullptr, xq,
             Nq, Gq, Gq, BANKq, Gq, Gq, 0,
             (long)Nq * BANKq, 0, (long)Nq * Gq, 0, Bq, 1.f, 0);
        gemm(false, x1, attn_Wk + (long)l * Gq * Gq, nullptr, nullptr, xk,
             Nq, Gq, Gq, Gq, Gq, Gq, 0,
             (long)Nq * Gq, 0, (long)Nq * Gq, 0, Bq, 1.f, 0);
        gemm(false, x1, attn_Wv + (long)l * Gq * Gq, nullptr, nullptr, xv,
             Nq, Gq, Gq, Gq, Gq, Gq, 0,
             (long)Nq * Gq, 0, (long)Nq * Gq, 0, Bq, 1.f, 0);
        gemm(true, xq, xk, nullptr, nullptr, att,
             Nq, Nq, Gq, Gq, Gq, Nq, 0,
             (long)Nq * Gq, (long)Nq * Gq, (long)Nq * Nq, 0, Bq, 0.0625f, 0);
        softmax256_kernel<<<Bq * Nq, 256>>>(att);
        gemm(false, att, xv, nullptr, x1, feats + outoff[l],
             Nq, Gq, Nq, Nq, Gq, BANKq, Gq,
             (long)Nq * Nq, (long)Nq * Gq, (long)Nq * BANKq, (long)Nq * Gq, Bq, 1.f, 1);
    }

    // pred weight transpose-split
    {
        dim3 grid((BANK5q + 31) / 32, (BANK5q + 31) / 32);
        transpose_split_kernel<<<grid, dim3(32, 8)>>>(pred_W, wph, wpl, BANK5q, BANK5q);
    }

    const size_t W4 = (size_t)BANK4q * BANKq;
    dim3 cg((BANKq + 255) / 256, Mlstm);
    dim3 cg1((BANKq + 255) / 256, BPq);

    // ===== LSTM layer 0 (prefix dedup + length compaction) =====
    {
        const float* Wih0 = lstm_Wih;
        const float* Whh0 = lstm_Whh;
        const float* b0   = lstm_b;
        split(feats, sh, sl, (size_t)Bq * Nq * BANKq);
        split(Wih0, w1h, w1l, W4);
        split(Whh0, w2h, w2l, W4);
        gemm_bf16(sh, sl, w1h, w1l, b0, hh, BPq, BANK4q, BANKq, 0);
        gather_ih_l0_kernel<<<3 * Mlstm, 256>>>(hh, path_nodes, ih);
        cand_cell_kernel<<<cg1, 256>>>(hh, qb, hch, hcl);
        gather0_kernel<<<Mlstm, 256>>>(hch, hcl, qb, path_nodes, sh, sl, cbuf, ah, al, nullptr);
        gemm_bf16(hch, hcl, w2h, w2l, nullptr, hid, BPq, BANK4q, BANKq, 0);
        gather_w64_kernel<<<Mlstm, 256>>>(hid, path_nodes, hh, 1);
        for (int t = 1; t < Lq; t++) {
            if (t > 1)
                gemm_bf16(sh, sl, w2h, w2l, nullptr, hh, Mlstm, BANK4q, BANKq, 0, cntdev + t);
            lstm_cell_kernel<<<cg, 256>>>(ih, hh, sh, sl, ah, al, cbuf, nullptr, t);
        }
    }

    // ===== LSTM layer 1 (same dedup + compaction) =====
    {
        const float* Wih1 = lstm_Wih + W4;
        const float* Whh1 = lstm_Whh + W4;
        const float* b1   = lstm_b + BANK4q;
        split(Wih1, w1h, w1l, W4);
        split(Whh1, w2h, w2l, W4);
        gemm_bf16(hch, hcl, w1h, w1l, b1, hid, BPq, BANK4q, BANKq, 0);
        for (int t = 1; t < Lq; t++)
            gemm_bf16(ah + (size_t)t * Mlstm * BANKq, al + (size_t)t * Mlstm * BANKq,
                      w1h, w1l, b1, ih + (size_t)t * Mlstm * BANK4q,
                      Mlstm, BANK4q, BANKq, 0, cntdev + t);
        cand_cell_kernel<<<cg1, 256>>>(hid, qb, hch, hcl);
        gather0_kernel<<<Mlstm, 256>>>(hch, hcl, qb, path_nodes, sh, sl, cbuf,
                                       nullptr, nullptr, hs1);
        gemm_bf16(hch, hcl, w2h, w2l, nullptr, hid, BPq, BANK4q, BANKq, 0);
        gather_w64_kernel<<<Mlstm, 256>>>(hid, path_nodes, hh, 1);
        for (int t = 1; t < Lq; t++) {
            if (t > 1)
                gemm_bf16(sh, sl, w2h, w2l, nullptr, hh, Mlstm, BANK4q, BANKq, 0, cntdev + t);
            lstm_cell_kernel<<<cg, 256>>>(ih, hh, sh, sl, nullptr, nullptr, cbuf, hs1, t);
        }
    }

    // 8) masked max-pool -> pe in COMPACTED order (split bf16 into ah/al)
    maxpool_split_kernel<<<cg, 256>>>(hs1, path_lens, ah, al);

    // 9) h_f, t_f, query (split)
    gather_ht_kernel<<<BPq, 256>>>(feats, h_t_pairs, hf, tf, sh, sl);

    // 10-11) q/k/v projections (k/v compacted + count-limited; tail rows zeroed)
    split(mha_inW, w1h, w1l, (size_t)3 * BANKq * BANKq);
    gemm_bf16(sh, sl, w1h, w1l, mha_inb, qb, BPq, BANKq, BANKq, 0);
    gemm_bf16(ah, al, w1h + (size_t)BANKq * BANKq, w1l + (size_t)BANKq * BANKq,
              mha_inb + BANKq, kb, Mlstm, BANKq, BANKq, 0, cntdev + 0);
    gemm_bf16(ah, al, w1h + 2 * (size_t)BANKq * BANKq, w1l + 2 * (size_t)BANKq * BANKq,
              mha_inb + 2 * BANKq, vb, Mlstm, BANKq, BANKq, 0, cntdev + 0);
    zero_kv_tail_kernel<<<Mlstm, 256>>>(kb, vb);

    // 12) tiny attention over K=3 paths
    mha_attn_kernel<<<BPq, 384>>>(qb, kb, vb, path_lens, rel_mask, sh, sl, validany);

    // 13) pinfo
    split(mha_outW, w2h, w2l, (size_t)BANKq * BANKq);
    gemm_bf16(sh, sl, w2h, w2l, mha_outb, pinfo, BPq, BANKq, BANKq, 0);

    // ===== 14-15) pred GEMM with segment dedup =====
    // bank (168 rows) split -> hch/hcl (free after LSTM)
    bank_split_kernel<<<NBANKROWS, 256>>>(feats, hch, hcl);
    // of_rest = [abs, prod, pinfo] split -> ah/al (1024 x 4728)
    build_of_rest_kernel<<<BPq, 256>>>(hf, tf, pinfo, validany, ah, al);
    // partials: p1 = bank @ Wseg0, p2 = bank @ Wseg1  (weights: wph rows, k-offset into each row)
    float* p1 = kb;                                  // 168*7880 fp32
    float* p2 = kb + (size_t)NBANKROWS * BANK5q;
    gemm_bf16(hch, hcl, wph, wpl, nullptr, p1,
              NBANKROWS, BANK5q, BANKq, 0, nullptr, BANKq, BANK5q);
    gemm_bf16(hch, hcl, wph + BANKq, wpl + BANKq, nullptr, p2,
              NBANKROWS, BANK5q, BANKq, 0, nullptr, BANKq, BANK5q);
    // rest: hid = of_rest @ Wseg2..4 + pred_b (no relu yet)
    gemm_bf16(ah, al, wph + 2 * BANKq, wpl + 2 * BANKq, pred_b, hid,
              BPq, BANK5q, BANK3q, 0, nullptr, BANK3q, BANK5q);
    // combine + relu
    combine_pred_kernel<<<BPq, 256>>>(hid, p1, p2, h_t_pairs);

    // 16) output heads
    gemm(false, hid, mW, mb, nullptr, out,
         BPq, Rq, BANK5q, BANK5q, Rq, Rq, 0, 0, 0, 0, 0, 1, 1.f, 0);
    head2_kernel<<<BPq, 256>>>(hid, bW, bb, out + (size_t)BPq * Rq);
}

// round 14
// speedup vs baseline: 3.4537x; 1.0591x over previous
#include <cuda_runtime.h>
#include <cuda_bf16.h>
#include <math.h>
#include <stdio.h>

// ---------------- problem constants ----------------
#define Bq   4
#define Sq   512
#define Nq   256
#define Eq   42
#define Pq   256
#define Kq   3
#define Lq   4
#define HBq  768
#define DTq  20
#define DIq  20
#define Gq   256
#define NLq  2
#define Rq   97
#define NHq  4
#define D0q  808          // HB+DT+DI
#define BANKq 1576        // D0 + G*(NL+1)
#define BANK3q 4728       // 3*BANK (abs|prod|pinfo)
#define BANK4q 6304       // 4*BANK
#define BANK5q 7880       // 5*BANK
#define DHq  394          // BANK/NH
#define Mlstm (Bq*Pq*Kq)        // 3072
#define MlstmT (Mlstm*Lq)       // 12288
#define BPq  (Bq*Pq)            // 1024
#define NBANKROWS (Bq*Eq)       // 168 distinct entity-bank rows

typedef __nv_bfloat16 bf16;
typedef __nv_bfloat162 bf162;

// ---------------- scratch (static device memory; no allocations allowed) ----------------
__device__ float g_enc   [Bq*Sq*D0q];
__device__ float g_feats [Bq*Nq*BANKq];
__device__ float g_tmp   [Bq*Nq*D0q];
__device__ float g_x1    [Bq*Nq*Gq];
__device__ float g_xq    [Bq*Nq*Gq];
__device__ float g_xk    [Bq*Nq*Gq];
__device__ float g_xv    [Bq*Nq*Gq];
__device__ float g_att   [Bq*Nq*Nq];
__device__ float g_ih    [(size_t)MlstmT*BANK4q];   // t-major
__device__ float g_hh    [(size_t)Mlstm*BANK4q];
__device__ float g_c     [Mlstm*BANKq];
__device__ float g_hs1   [MlstmT*BANKq];            // t-major, compacted rows
__device__ float g_hf    [BPq*BANKq];
__device__ float g_tf    [BPq*BANKq];
__device__ float g_q     [BPq*BANKq];               // qb (side stream)
__device__ float g_ccand [BPq*BANKq];               // candidate c scratch
__device__ float g_k     [Mlstm*BANKq];
__device__ float g_v     [Mlstm*BANKq];
__device__ float g_pinfo [BPq*BANKq];
__device__ float g_pp    [2*(size_t)NBANKROWS*BANK5q]; // pred partials p1/p2
__device__ int   g_validany[BPq];
__device__ float g_hid   [BPq*BANK5q];              // also proj scratch

// length-compaction state
__device__ int g_perm[Mlstm];
__device__ int g_iperm[Mlstm];
__device__ int g_cnt[4];

// bf16 split scratch
__device__ bf16 g_ah  [(size_t)MlstmT*BANKq];       // layer-0 seq; later pe; later of_rest
__device__ bf16 g_al  [(size_t)MlstmT*BANKq];
__device__ bf16 g_sh  [(size_t)Mlstm*BANKq];
__device__ bf16 g_sl  [(size_t)Mlstm*BANKq];
__device__ bf16 g_hch [(size_t)BPq*BANKq];          // candidate h
__device__ bf16 g_hcl [(size_t)BPq*BANKq];
__device__ bf16 g_q2h [(size_t)BPq*BANKq];          // query split (side stream)
__device__ bf16 g_q2l [(size_t)BPq*BANKq];
__device__ bf16 g_bkh [(size_t)NBANKROWS*BANKq];    // bank split (side stream)
__device__ bf16 g_bkl [(size_t)NBANKROWS*BANKq];
__device__ bf16 g_w1h [(size_t)BANK4q*BANKq];       // Wih0
__device__ bf16 g_w1l [(size_t)BANK4q*BANKq];
__device__ bf16 g_w2h [(size_t)BANK4q*BANKq];       // Whh0
__device__ bf16 g_w2l [(size_t)BANK4q*BANKq];
__device__ bf16 g_w3h [(size_t)BANK4q*BANKq];       // Wih1
__device__ bf16 g_w3l [(size_t)BANK4q*BANKq];
__device__ bf16 g_w4h [(size_t)BANK4q*BANKq];       // Whh1
__device__ bf16 g_w4l [(size_t)BANK4q*BANKq];
__device__ bf16 g_mwh [3*(size_t)BANKq*BANKq];      // mha_inW
__device__ bf16 g_mwl [3*(size_t)BANKq*BANKq];
__device__ bf16 g_owh [(size_t)BANKq*BANKq];        // mha_outW
__device__ bf16 g_owl [(size_t)BANKq*BANKq];
__device__ bf16 g_wph [(size_t)BANK5q*BANK5q];
__device__ bf16 g_wpl [(size_t)BANK5q*BANK5q];

// ================= fp32 tiled GEMM (small GCN ops + head) =================
template <bool TRANSB>
__global__ void __launch_bounds__(256)
gemm32_kernel(const float* __restrict__ A, const float* __restrict__ B,
              const float* __restrict__ bias, const float* __restrict__ resid,
              float* __restrict__ C,
              int M, int N, int K,
              int lda, int ldb, int ldc, int ldr,
              long sA, long sB, long sC, long sR,
              float alpha, int act)
{
    int bz = blockIdx.z;
    A += bz * sA; B += bz * sB; C += bz * sC;
    if (resid) resid += bz * sR;

    int row0 = blockIdx.y * 32;
    int col0 = blockIdx.x * 32;

    __shared__ float As[32][33];
    __shared__ float Bs[32][33];

    int tid = threadIdx.x;
    int tx = tid & 15, ty = tid >> 4;

    float acc[2][2] = {{0.f, 0.f}, {0.f, 0.f}};

    for (int k0 = 0; k0 < K; k0 += 32) {
#pragma unroll
        for (int l = 0; l < 4; l++) {
            int idx = tid + l * 256;
            int m = idx >> 5, kk = idx & 31;
            int gr = row0 + m, gk = k0 + kk;
            As[kk][m] = (gr < M && gk < K) ? A[(long)gr * lda + gk] : 0.f;
        }
#pragma unroll
        for (int l = 0; l < 4; l++) {
            int idx = tid + l * 256;
            if (TRANSB) {
                int n = idx >> 5, kk = idx & 31;
                int gn = col0 + n, gk = k0 + kk;
                Bs[kk][n] = (gn < N && gk < K) ? B[(long)gn * ldb + gk] : 0.f;
            } else {
                int kk = idx >> 5, n = idx & 31;
                int gn = col0 + n, gk = k0 + kk;
                Bs[kk][n] = (gn < N && gk < K) ? B[(long)gk * ldb + gn] : 0.f;
            }
        }
        __syncthreads();
#pragma unroll
        for (int kk = 0; kk < 32; kk++) {
            float a0 = As[kk][ty], a1 = As[kk][ty + 16];
            float b0 = Bs[kk][tx], b1 = Bs[kk][tx + 16];
            acc[0][0] = fmaf(a0, b0, acc[0][0]);
            acc[0][1] = fmaf(a0, b1, acc[0][1]);
            acc[1][0] = fmaf(a1, b0, acc[1][0]);
            acc[1][1] = fmaf(a1, b1, acc[1][1]);
        }
        __syncthreads();
    }

#pragma unroll
    for (int i = 0; i < 2; i++) {
        int r = row0 + ty + 16 * i;
        if (r >= M) continue;
#pragma unroll
        for (int j = 0; j < 2; j++) {
            int cc = col0 + tx + 16 * j;
            if (cc >= N) continue;
            float v = acc[i][j] * alpha;
            if (bias) v += bias[cc];
            if (act == 1) v = fmaxf(v, 0.f);
            if (resid) v += resid[(long)r * ldr + cc];
            C[(long)r * ldc + cc] = v;
        }
    }
}

static void gemm(bool transB,
                 const float* A, const float* B, const float* bias, const float* resid, float* C,
                 int M, int N, int K, int lda, int ldb, int ldc, int ldr,
                 long sA, long sB, long sC, long sR, int batch, float alpha, int act,
                 cudaStream_t st = 0)
{
    dim3 grid((N + 31) / 32, (M + 31) / 32, batch);
    if (transB)
        gemm32_kernel<true><<<grid, 256, 0, st>>>(A, B, bias, resid, C, M, N, K, lda, ldb, ldc, ldr, sA, sB, sC, sR, alpha, act);
    else
        gemm32_kernel<false><<<grid, 256, 0, st>>>(A, B, bias, resid, C, M, N, K, lda, ldb, ldc, ldr, sA, sB, sC, sR, alpha, act);
}

// ================= bf16 split-precision tensor-core GEMM (R6 loop + Mdev + ld) =================
#define LDSB 40
#define GSTG 3
#define PLANE_E (128*LDSB)
#define PLANE_B (PLANE_E*2)
#define STAGE_B (4*PLANE_B)

#define MMA_BF16(d, a, b) asm volatile( \
    "mma.sync.aligned.m16n8k16.row.col.f32.bf16.bf16.f32 " \
    "{%0,%1,%2,%3}, {%4,%5,%6,%7}, {%8,%9}, {%0,%1,%2,%3};" \
    : "+f"((d)[0]), "+f"((d)[1]), "+f"((d)[2]), "+f"((d)[3]) \
    : "r"((a)[0]), "r"((a)[1]), "r"((a)[2]), "r"((a)[3]), "r"((b)[0]), "r"((b)[1]))

#define LDSM4(r, addr) asm volatile( \
    "ldmatrix.sync.aligned.m8n8.x4.shared.b16 {%0,%1,%2,%3}, [%4];" \
    : "=r"((r)[0]), "=r"((r)[1]), "=r"((r)[2]), "=r"((r)[3]) : "r"(addr))

__device__ __forceinline__ void cpasync16(unsigned saddr, const void* g, int srcbytes)
{
    asm volatile("cp.async.cg.shared.global [%0], [%1], 16, %2;\n"
                 :: "r"(saddr), "l"(g), "r"(srcbytes));
}

__device__ __forceinline__ void gbf_prefetch(
    const bf16* __restrict__ Ah, const bf16* __restrict__ Al,
    const bf16* __restrict__ Bh, const bf16* __restrict__ Bl,
    long row0, long col0, int M, int N, int K, int ldA, int ldB,
    int kt, int T, unsigned sbase, int stg, int tid)
{
    if (kt >= T) return;
    long k0 = (long)kt * 32;
    unsigned sst = sbase + (unsigned)stg * STAGE_B;
#pragma unroll
    for (int i = 0; i < 2; i++) {
        int c = tid + i * 256;
        int r = c >> 2;
        int ko = (c & 3) * 8;
        long gk = k0 + ko;
        bool kok = gk < K;
        long gkc = kok ? gk : 0;
        unsigned soff = (unsigned)((r * LDSB + ko) * 2);
        {
            long gr = row0 + r;
            bool ok = kok && (gr < M);
            long grc = ok ? gr : 0;
            int nb = ok ? 16 : 0;
            cpasync16(sst + soff,            Ah + grc * ldA + gkc, nb);
            cpasync16(sst + PLANE_B + soff,  Al + grc * ldA + gkc, nb);
        }
        {
            long gn = col0 + r;
            bool ok = kok && (gn < N);
            long gnc = ok ? gn : 0;
            int nb = ok ? 16 : 0;
            cpasync16(sst + 2 * PLANE_B + soff, Bh + gnc * ldB + gkc, nb);
            cpasync16(sst + 3 * PLANE_B + soff, Bl + gnc * ldB + gkc, nb);
        }
    }
}

__global__ void __launch_bounds__(256)
gemm_bf16_kernel(const bf16* __restrict__ Ah, const bf16* __restrict__ Al,
                 const bf16* __restrict__ Bh, const bf16* __restrict__ Bl,
                 const float* __restrict__ bias, float* __restrict__ C,
                 int M, int N, int K, int act, const int* __restrict__ Mdev,
                 int ldA, int ldB)
{
    if (Mdev) {
        M = min(M, *Mdev);
        if ((long)blockIdx.y * 128 >= (long)M) return;
    }
    extern __shared__ __align__(16) bf16 dsm[];
    unsigned sbase = (unsigned)__cvta_generic_to_shared(dsm);

    int tid = threadIdx.x;
    int warp = tid >> 5, lane = tid & 31;
    int wm = (warp & 1) * 64;
    int wn = (warp >> 1) * 32;
    long row0 = (long)blockIdx.y * 128;
    long col0 = (long)blockIdx.x * 128;

    float acc[4][4][4];
#pragma unroll
    for (int a = 0; a < 4; a++)
#pragma unroll
        for (int b = 0; b < 4; b++)
#pragma unroll
            for (int c = 0; c < 4; c++) acc[a][b][c] = 0.f;

    int am_r = (lane & 7) + ((lane >> 3) & 1) * 8;
    int a_c8 = ((lane >> 4) & 1) * 8;
    int b_r  = (lane & 7) + ((lane >> 4) & 1) * 8;
    int b_c8 = ((lane >> 3) & 1) * 8;

    int T = (K + 31) / 32;

#pragma unroll
    for (int kt = 0; kt < GSTG; kt++) {
        gbf_prefetch(Ah, Al, Bh, Bl, row0, col0, M, N, K, ldA, ldB, kt, T, sbase, kt, tid);
        asm volatile("cp.async.commit_group;\n");
    }

    for (int kt = 0; kt < T; kt++) {
        asm volatile("cp.async.wait_group %0;\n" :: "n"(GSTG - 1));
        __syncthreads();

        int stg = kt % GSTG;
        unsigned sst = sbase + (unsigned)stg * STAGE_B;
        unsigned aB = sst;
        unsigned bB = sst + 2 * PLANE_B;

#pragma unroll
        for (int ks = 0; ks < 2; ks++) {
            int kb = ks * 16;
            unsigned bh[2][4], bl[2][4];
#pragma unroll
            for (int pp = 0; pp < 2; pp++) {
                unsigned addr = bB + (unsigned)(((wn + pp * 16 + b_r) * LDSB + kb + b_c8) * 2);
                LDSM4(bh[pp], addr);
                LDSM4(bl[pp], addr + PLANE_B);
            }
            unsigned ahf[4][4], alf[4][4];
#pragma unroll
            for (int mi = 0; mi < 4; mi++) {
                unsigned addr = aB + (unsigned)(((wm + mi * 16 + am_r) * LDSB + kb + a_c8) * 2);
                LDSM4(ahf[mi], addr);
                LDSM4(alf[mi], addr + PLANE_B);
            }
#pragma unroll
            for (int mi = 0; mi < 4; mi++)
#pragma unroll
                for (int ni = 0; ni < 4; ni++)
                    MMA_BF16(acc[mi][ni], ahf[mi], (&bh[ni >> 1][(ni & 1) * 2]));
#pragma unroll
            for (int mi = 0; mi < 4; mi++)
#pragma unroll
                for (int ni = 0; ni < 4; ni++)
                    MMA_BF16(acc[mi][ni], ahf[mi], (&bl[ni >> 1][(ni & 1) * 2]));
#pragma unroll
            for (int mi = 0; mi < 4; mi++)
#pragma unroll
                for (int ni = 0; ni < 4; ni++)
                    MMA_BF16(acc[mi][ni], alf[mi], (&bh[ni >> 1][(ni & 1) * 2]));
        }
        __syncthreads();
        gbf_prefetch(Ah, Al, Bh, Bl, row0, col0, M, N, K, ldA, ldB, kt + GSTG, T, sbase, stg, tid);
        asm volatile("cp.async.commit_group;\n");
    }

#pragma unroll
    for (int mi = 0; mi < 4; mi++) {
#pragma unroll
        for (int ni = 0; ni < 4; ni++) {
            long r = row0 + wm + mi * 16 + (lane >> 2);
            long c = col0 + wn + ni * 8 + (lane & 3) * 2;
#pragma unroll
            for (int half = 0; half < 2; half++) {
                long rr = r + half * 8;
                if (rr >= M) continue;
#pragma unroll
                for (int e = 0; e < 2; e++) {
                    long cc = c + e;
                    if (cc >= N) continue;
                    float v = acc[mi][ni][half * 2 + e];
                    if (bias) v += bias[cc];
                    if (act == 1) v = fmaxf(v, 0.f);
                    C[(size_t)rr * N + cc] = v;
                }
            }
        }
    }
}

static void gemm_bf16(const bf16* Ah, const bf16* Al, const bf16* Bh, const bf16* Bl,
                      const float* bias, float* C, int M, int N, int K, int act,
                      const int* Mdev = nullptr, int ldA = 0, int ldB = 0,
                      cudaStream_t st = 0)
{
    static int attr_done = 0;
    if (!attr_done) {
        cudaFuncSetAttribute(gemm_bf16_kernel,
                             cudaFuncAttributeMaxDynamicSharedMemorySize, GSTG * STAGE_B);
        attr_done = 1;
    }
    if (ldA == 0) ldA = K;
    if (ldB == 0) ldB = K;
    dim3 grid((N + 127) / 128, (M + 127) / 128);
    gemm_bf16_kernel<<<grid, 256, GSTG * STAGE_B, st>>>(Ah, Al, Bh, Bl, bias, C, M, N, K, act, Mdev, ldA, ldB);
}

// ================= conversion kernels =================
__device__ __forceinline__ void split1(float f, bf16& h, bf16& l)
{
    h = __float2bfloat16(f);
    l = __float2bfloat16(f - __bfloat162float(h));
}

__global__ void split_kernel(const float* __restrict__ x, bf16* __restrict__ hi,
                             bf16* __restrict__ lo, size_t n4)
{
    size_t i = (size_t)blockIdx.x * blockDim.x + threadIdx.x;
    if (i >= n4) return;
    float4 f = ((const float4*)x)[i];
    bf16 h0, l0, h1, l1, h2, l2, h3, l3;
    split1(f.x, h0, l0); split1(f.y, h1, l1); split1(f.z, h2, l2); split1(f.w, h3, l3);
    bf162 vh0; vh0.x = h0; vh0.y = h1;
    bf162 vh1; vh1.x = h2; vh1.y = h3;
    bf162 vl0; vl0.x = l0; vl0.y = l1;
    bf162 vl1; vl1.x = l2; vl1.y = l3;
    ((bf162*)hi)[i * 2] = vh0; ((bf162*)hi)[i * 2 + 1] = vh1;
    ((bf162*)lo)[i * 2] = vl0; ((bf162*)lo)[i * 2 + 1] = vl1;
}

static void split(const float* x, bf16* hi, bf16* lo, size_t n, cudaStream_t st = 0)
{
    size_t n4 = n / 4;
    split_kernel<<<(unsigned)((n4 + 255) / 256), 256, 0, st>>>(x, hi, lo, n4);
}

__global__ void transpose_split_kernel(const float* __restrict__ B, bf16* __restrict__ Th,
                                       bf16* __restrict__ Tl, int K, int N)
{
    __shared__ float tile[32][33];
    int k0 = blockIdx.y * 32, n0 = blockIdx.x * 32;
    int tx = threadIdx.x, ty = threadIdx.y;  // 32 x 8
#pragma unroll
    for (int i = 0; i < 32; i += 8) {
        int k = k0 + ty + i, n = n0 + tx;
        tile[ty + i][tx] = (k < K && n < N) ? B[(size_t)k * N + n] : 0.f;
    }
    __syncthreads();
#pragma unroll
    for (int i = 0; i < 32; i += 8) {
        int n = n0 + ty + i, k = k0 + tx;
        if (n < N && k < K) {
            float f = tile[tx][ty + i];
            bf16 h, l; split1(f, h, l);
            Th[(size_t)n * K + k] = h;
            Tl[(size_t)n * K + k] = l;
        }
    }
}

// ---------------- fast activations ----------------
__device__ __forceinline__ float fsig(float x)
{
    return __fdividef(1.f, 1.f + __expf(-x));
}
__device__ __forceinline__ float ftanh(float x)
{
    x = fminf(fmaxf(x, -15.f), 15.f);
    float e = __expf(-2.f * x);
    return __fdividef(1.f - e, 1.f + e);
}

// ---------------- length-compaction permutation ----------------
__global__ void build_perm_kernel(const int* __restrict__ lens)
{
    __shared__ int slens[Mlstm];
    __shared__ int bins[Lq + 1];
    __shared__ int offs[Lq + 1];
    int tid = threadIdx.x;
    if (tid <= Lq) bins[tid] = 0;
    __syncthreads();
    for (int i = tid; i < Mlstm; i += blockDim.x) {
        int l = lens[i];
        slens[i] = l;
        atomicAdd(&bins[l], 1);
    }
    __syncthreads();
    if (tid == 0) {
        int off = 0;
        for (int l = Lq; l >= 0; l--) { offs[l] = off; off += bins[l]; }
        int c = 0;
        for (int t = Lq - 1; t >= 0; t--) { c += bins[t + 1]; g_cnt[t] = c; }
        int cur[Lq + 1];
        for (int l = 0; l <= Lq; l++) cur[l] = offs[l];
        for (int i = 0; i < Mlstm; i++) {
            int l = slens[i];
            g_perm[cur[l]++] = i;
        }
        for (int i = 0; i < Mlstm; i++) g_iperm[g_perm[i]] = i;
    }
}

// ---------------- small custom kernels ----------------
__global__ void build_enc_kernel(const float* __restrict__ eo, const int* __restrict__ etype,
                                 const int* __restrict__ eid, const float* __restrict__ temb,
                                 const float* __restrict__ iemb, float* __restrict__ enc)
{
    int bs = blockIdx.x;
    const float* src = eo + (long)bs * HBq;
    float* dst = enc + (long)bs * D0q;
    int ty = etype[bs], idv = eid[bs];
    for (int j = threadIdx.x; j < D0q; j += blockDim.x) {
        float v;
        if (j < HBq)            v = src[j];
        else if (j < HBq + DTq) v = temb[ty * DTq + (j - HBq)];
        else                    v = iemb[idv * DIq + (j - HBq - DTq)];
        dst[j] = v;
    }
}

__global__ void softmax256_kernel(float* __restrict__ x)
{
    int row = blockIdx.x;
    int tid = threadIdx.x;
    float v = x[(long)row * 256 + tid];
    __shared__ float red[8];
    int lane = tid & 31, warp = tid >> 5;
    float m = v;
#pragma unroll
    for (int o = 16; o > 0; o >>= 1) m = fmaxf(m, __shfl_xor_sync(0xffffffffu, m, o));
    if (lane == 0) red[warp] = m;
    __syncthreads();
    if (tid == 0) {
        float mm = red[0];
        for (int w = 1; w < 8; w++) mm = fmaxf(mm, red[w]);
        red[0] = mm;
    }
    __syncthreads();
    float mx = red[0];
    float e = expf(v - mx);
    float s = e;
#pragma unroll
    for (int o = 16; o > 0; o >>= 1) s += __shfl_xor_sync(0xffffffffu, s, o);
    __shared__ float red2[8];
    if (lane == 0) red2[warp] = s;
    __syncthreads();
    if (tid == 0) {
        float ss = 0.f;
        for (int w = 0; w < 8; w++) ss += red2[w];
        red2[0] = ss;
    }
    __syncthreads();
    x[(long)row * 256 + tid] = e / red2[0];
}

__global__ void gather_ih_l0_kernel(const float* __restrict__ proj, const int* __restrict__ nodes,
                                    float* __restrict__ ih)
{
    int r = blockIdx.x;
    int t = 1 + r / Mlstm, i = r % Mlstm;
    if (i >= g_cnt[t]) return;
    int orig = g_perm[i];
    int b = orig / (Pq * Kq);
    int node = nodes[orig * Lq + t];
    const float4* src = (const float4*)(proj + ((size_t)(b * Nq + node)) * BANK4q);
    float4* dst = (float4*)(ih + ((size_t)t * Mlstm + i) * BANK4q);
    for (int j = threadIdx.x; j < BANK4q / 4; j += blockDim.x) dst[j] = src[j];
}

__global__ void gather_w64_kernel(const float* __restrict__ src, const int* __restrict__ nodes,
                                  float* __restrict__ dst, int cslot)
{
    int i = blockIdx.x;
    if (i >= g_cnt[cslot]) return;
    int orig = g_perm[i];
    int b = orig / (Pq * Kq);
    int node = nodes[orig * Lq];
    const float4* s = (const float4*)(src + ((size_t)(b * Nq + node)) * BANK4q);
    float4* d = (float4*)(dst + (size_t)i * BANK4q);
    for (int j = threadIdx.x; j < BANK4q / 4; j += blockDim.x) d[j] = s[j];
}

__global__ void cand_cell_kernel(const float* __restrict__ proj, float* __restrict__ ccand,
                                 bf16* __restrict__ hch, bf16* __restrict__ hcl)
{
    int i = blockIdx.y;
    int j = blockIdx.x * blockDim.x + threadIdx.x;
    if (j >= BANKq) return;
    const float* g = proj + (size_t)i * BANK4q;
    float gi = g[j], gg = g[2 * BANKq + j], go = g[3 * BANKq + j];
    float cn = fsig(gi) * ftanh(gg);
    float hn = fsig(go) * ftanh(cn);
    ccand[(size_t)i * BANKq + j] = cn;
    bf16 h, l; split1(hn, h, l);
    hch[(size_t)i * BANKq + j] = h;
    hcl[(size_t)i * BANKq + j] = l;
}

__global__ void gather0_kernel(const bf16* __restrict__ hch, const bf16* __restrict__ hcl,
                               const float* __restrict__ ccand, const int* __restrict__ nodes,
                               bf16* __restrict__ sh, bf16* __restrict__ sl,
                               float* __restrict__ c,
                               bf16* __restrict__ seq_hi, bf16* __restrict__ seq_lo,
                               float* __restrict__ hs)
{
    int i = blockIdx.x;
    int orig = g_perm[i];
    int b = orig / (Pq * Kq);
    size_t idx = ((size_t)(b * Nq + nodes[orig * Lq])) * BANKq;
    size_t dst = (size_t)i * BANKq;
    for (int j = threadIdx.x; j < BANKq; j += blockDim.x) {
        bf16 h = hch[idx + j], l = hcl[idx + j];
        sh[dst + j] = h;
        sl[dst + j] = l;
        c[dst + j] = ccand[idx + j];
        if (seq_hi) { seq_hi[dst + j] = h; seq_lo[dst + j] = l; }
        if (hs) hs[dst + j] = __bfloat162float(h) + __bfloat162float(l);
    }
}

__global__ void lstm_cell_kernel(const float* __restrict__ ih, const float* __restrict__ hh,
                                 bf16* __restrict__ h_hi, bf16* __restrict__ h_lo,
                                 bf16* __restrict__ seq_hi, bf16* __restrict__ seq_lo,
                                 float* __restrict__ c, float* __restrict__ hs, int t)
{
    int i = blockIdx.y;
    if (i >= g_cnt[t]) return;
    int j = blockIdx.x * blockDim.x + threadIdx.x;
    if (j >= BANKq) return;
    const float* g = ih + ((size_t)t * Mlstm + i) * BANK4q;
    const float* hr = hh + (size_t)i * BANK4q;
    float gi = g[j] + hr[j];
    float gf = g[BANKq + j] + hr[BANKq + j];
    float gg = g[2 * BANKq + j] + hr[2 * BANKq + j];
    float go = g[3 * BANKq + j] + hr[3 * BANKq + j];
    float cp = c[(size_t)i * BANKq + j];
    float cn = fsig(gf) * cp + fsig(gi) * ftanh(gg);
    float hn = fsig(go) * ftanh(cn);
    c[(size_t)i * BANKq + j] = cn;
    bf16 h, l; split1(hn, h, l);
    h_hi[(size_t)i * BANKq + j] = h;
    h_lo[(size_t)i * BANKq + j] = l;
    if (seq_hi) {
        seq_hi[((size_t)t * Mlstm + i) * BANKq + j] = h;
        seq_lo[((size_t)t * Mlstm + i) * BANKq + j] = l;
    }
    if (hs) hs[((size_t)t * Mlstm + i) * BANKq + j] = hn;
}

__global__ void maxpool_split_kernel(const float* __restrict__ hs, const int* __restrict__ lens,
                                     bf16* __restrict__ hi, bf16* __restrict__ lo)
{
    int i = blockIdx.y;
    int j = blockIdx.x * blockDim.x + threadIdx.x;
    if (j >= BANKq) return;
    int orig = g_perm[i];
    int len = lens[orig];
    float m = -1e9f;
    const float* base = hs + (size_t)i * BANKq + j;
    for (int t = 0; t < Lq; t++)
        if (t < len) m = fmaxf(m, base[(size_t)t * Mlstm * BANKq]);
    float r = (len > 0) ? m : 0.f;
    bf16 h, l; split1(r, h, l);
    hi[(size_t)i * BANKq + j] = h;
    lo[(size_t)i * BANKq + j] = l;
}

__global__ void zero_kv_tail_kernel(float* __restrict__ kb, float* __restrict__ vb)
{
    int i = blockIdx.x;
    if (i < g_cnt[0]) return;
    float4* k4 = (float4*)(kb + (size_t)i * BANKq);
    float4* v4 = (float4*)(vb + (size_t)i * BANKq);
    float4 z = {0.f, 0.f, 0.f, 0.f};
    for (int j = threadIdx.x; j < BANKq / 4; j += blockDim.x) { k4[j] = z; v4[j] = z; }
}

__global__ void gather_ht_kernel(const float* __restrict__ feats, const int* __restrict__ htp,
                                 float* __restrict__ hf, float* __restrict__ tf,
                                 bf16* __restrict__ qh, bf16* __restrict__ ql)
{
    int bp = blockIdx.x;
    int b = bp / Pq;
    int h0 = htp[bp * 2 + 0], t0 = htp[bp * 2 + 1];
    h0 = (h0 == 0) ? 0 : h0 - 1;
    t0 = (t0 == 0) ? 0 : t0 - 1;
    const float* hsrc = feats + ((size_t)b * Nq + (Nq - Eq) + h0) * BANKq;
    const float* tsrc = feats + ((size_t)b * Nq + (Nq - Eq) + t0) * BANKq;
    for (int j = threadIdx.x; j < BANKq; j += blockDim.x) {
        float hv = hsrc[j], tv = tsrc[j];
        hf[(size_t)bp * BANKq + j] = hv;
        tf[(size_t)bp * BANKq + j] = tv;
        bf16 h, l; split1(hv - tv, h, l);
        qh[(size_t)bp * BANKq + j] = h;
        ql[(size_t)bp * BANKq + j] = l;
    }
}

__global__ void mha_attn_kernel(const float* __restrict__ q, const float* __restrict__ k,
                                const float* __restrict__ v, const int* __restrict__ plens,
                                const float* __restrict__ rmask,
                                bf16* __restrict__ ctx_hi, bf16* __restrict__ ctx_lo,
                                int* __restrict__ validany)
{
    int bp = blockIdx.x;
    int tid = threadIdx.x;
    int warp = tid >> 5, lane = tid & 31;
    __shared__ float sc[NHq][Kq];
    __shared__ float aw[NHq][Kq];
    __shared__ int vm[Kq];
    __shared__ int slot[Kq];
    if (tid < Kq) {
        vm[tid] = (rmask[bp] > 0.f && plens[bp * Kq + tid] > 0) ? 1 : 0;
        slot[tid] = g_iperm[bp * Kq + tid];
    }
    __syncthreads();
    {
        int h = warp / Kq, kk = warp % Kq;
        const float* qh = q + (size_t)bp * BANKq + h * DHq;
        const float* kh = k + (size_t)slot[kk] * BANKq + h * DHq;
        float s = 0.f;
        for (int d = lane; d < DHq; d += 32) s += qh[d] * kh[d];
#pragma unroll
        for (int o = 16; o > 0; o >>= 1) s += __shfl_xor_sync(0xffffffffu, s, o);
        if (lane == 0) {
            s = s / sqrtf((float)DHq);
            sc[h][kk] = vm[kk] ? s : -1e9f;
        }
    }
    __syncthreads();
    if (tid < NHq) {
        int h = tid;
        float m = fmaxf(fmaxf(sc[h][0], sc[h][1]), sc[h][2]);
        float e0 = expf(sc[h][0] - m), e1 = expf(sc[h][1] - m), e2 = expf(sc[h][2] - m);
        float s = e0 + e1 + e2;
        aw[h][0] = e0 / s; aw[h][1] = e1 / s; aw[h][2] = e2 / s;
    }
    if (tid == 0) validany[bp] = (vm[0] | vm[1] | vm[2]);
    __syncthreads();
    const float* v0 = v + (size_t)slot[0] * BANKq;
    const float* v1 = v + (size_t)slot[1] * BANKq;
    const float* v2 = v + (size_t)slot[2] * BANKq;
    for (int j = tid; j < BANKq; j += blockDim.x) {
        int h = j / DHq;
        float r = aw[h][0] * v0[j] + aw[h][1] * v1[j] + aw[h][2] * v2[j];
        bf16 hh2, ll2; split1(r, hh2, ll2);
        ctx_hi[(size_t)bp * BANKq + j] = hh2;
        ctx_lo[(size_t)bp * BANKq + j] = ll2;
    }
}

// bank rows -> split bf16 (168 rows)
__global__ void bank_split_kernel(const float* __restrict__ feats,
                                  bf16* __restrict__ bh, bf16* __restrict__ bl)
{
    int i = blockIdx.x;
    int b = i / Eq, e = i % Eq;
    const float* src = feats + ((size_t)b * Nq + (Nq - Eq) + e) * BANKq;
    size_t dst = (size_t)i * BANKq;
    for (int j = threadIdx.x; j < BANKq; j += blockDim.x) {
        bf16 h, l; split1(src[j], h, l);
        bh[dst + j] = h;
        bl[dst + j] = l;
    }
}

// of_rest = [abs, prod, pinfo] (1024 x 4728) split bf16
__global__ void build_of_rest_kernel(const float* __restrict__ hf, const float* __restrict__ tf,
                                     const float* __restrict__ pinfo, const int* __restrict__ validany,
                                     bf16* __restrict__ oh, bf16* __restrict__ ol)
{
    int bp = blockIdx.x;
    int va = validany[bp];
    const float* hr = hf + (size_t)bp * BANKq;
    const float* tr = tf + (size_t)bp * BANKq;
    const float* pr = pinfo + (size_t)bp * BANKq;
    size_t base = (size_t)bp * BANK3q;
    for (int j = threadIdx.x; j < BANK3q; j += blockDim.x) {
        int seg = j / BANKq, jj = j - seg * BANKq;
        float v;
        if (seg == 0)      v = fabsf(hr[jj] - tr[jj]);
        else if (seg == 1) v = hr[jj] * tr[jj];
        else               v = va ? pr[jj] : 0.f;
        bf16 h, l; split1(v, h, l);
        oh[base + j] = h;
        ol[base + j] = l;
    }
}

// hid[r] = relu(hid[r] + p1[bank(h_r)] + p2[bank(t_r)])
__global__ void combine_pred_kernel(float* __restrict__ hid, const float* __restrict__ p1,
                                    const float* __restrict__ p2, const int* __restrict__ htp)
{
    int r = blockIdx.x;
    int b = r / Pq;
    int h0 = htp[r * 2 + 0], t0 = htp[r * 2 + 1];
    h0 = (h0 == 0) ? 0 : h0 - 1;
    t0 = (t0 == 0) ? 0 : t0 - 1;
    const float* q1 = p1 + (size_t)(b * Eq + h0) * BANK5q;
    const float* q2 = p2 + (size_t)(b * Eq + t0) * BANK5q;
    float* hr = hid + (size_t)r * BANK5q;
    for (int j = threadIdx.x; j < BANK5q; j += blockDim.x)
        hr[j] = fmaxf(hr[j] + q1[j] + q2[j], 0.f);
}

// small head for the N=2 output
__global__ void __launch_bounds__(256)
head2_kernel(const float* __restrict__ hid, const float* __restrict__ bW,
             const float* __restrict__ bb, float* __restrict__ out2)
{
    int m = blockIdx.x;
    int tid = threadIdx.x, lane = tid & 31, warp = tid >> 5;
    const float* hr = hid + (size_t)m * BANK5q;
    float a0 = 0.f, a1 = 0.f;
    for (int k = tid; k < BANK5q; k += 256) {
        float h = hr[k];
        a0 = fmaf(h, bW[(size_t)k * 2], a0);
        a1 = fmaf(h, bW[(size_t)k * 2 + 1], a1);
    }
#pragma unroll
    for (int o = 16; o > 0; o >>= 1) {
        a0 += __shfl_xor_sync(0xffffffffu, a0, o);
        a1 += __shfl_xor_sync(0xffffffffu, a1, o);
    }
    __shared__ float r0[8], r1[8];
    if (lane == 0) { r0[warp] = a0; r1[warp] = a1; }
    __syncthreads();
    if (tid == 0) {
        float s0 = 0.f, s1 = 0.f;
        for (int w = 0; w < 8; w++) { s0 += r0[w]; s1 += r1[w]; }
        out2[(size_t)m * 2 + 0] = s0 + bb[0];
        out2[(size_t)m * 2 + 1] = s1 + bb[1];
    }
}

// ---------------- orchestration ----------------
extern "C" void kernel_launch(void* const* d_in, const int* in_sizes, int n_in,
                              void* d_out, int out_size)
{
    const float* encoder_outputs = (const float*)d_in[0];
    const int*   entity_type     = (const int*)  d_in[1];
    const int*   entity_id       = (const int*)  d_in[2];
    const float* sub2words       = (const float*)d_in[3];
    const float* adj             = (const float*)d_in[4];
    const int*   h_t_pairs       = (const int*)  d_in[5];
    const float* rel_mask        = (const float*)d_in[6];
    const int*   path_nodes      = (const int*)  d_in[7];
    const int*   path_lens       = (const int*)  d_in[8];
    const float* type_emb        = (const float*)d_in[9];
    const float* id_emb          = (const float*)d_in[10];
    const float* gcn0_W          = (const float*)d_in[11];
    const float* gcn0_b          = (const float*)d_in[12];
    const float* gcn_W           = (const float*)d_in[13];
    const float* gcn_b           = (const float*)d_in[14];
    const float* attn_Wq         = (const float*)d_in[15];
    const float* attn_Wk         = (const float*)d_in[16];
    const float* attn_Wv         = (const float*)d_in[17];
    const float* lstm_Wih        = (const float*)d_in[18];
    const float* lstm_Whh        = (const float*)d_in[19];
    const float* lstm_b          = (const float*)d_in[20];
    const float* mha_inW         = (const float*)d_in[21];
    const float* mha_inb         = (const float*)d_in[22];
    const float* mha_outW        = (const float*)d_in[23];
    const float* mha_outb        = (const float*)d_in[24];
    const float* pred_W          = (const float*)d_in[25];
    const float* pred_b          = (const float*)d_in[26];
    const float* mW              = (const float*)d_in[27];
    const float* mb              = (const float*)d_in[28];
    const float* bW              = (const float*)d_in[29];
    const float* bb              = (const float*)d_in[30];
    float* out = (float*)d_out;

    void* p;
#define SYMF(var, sym) cudaGetSymbolAddress(&p, sym); float* var = (float*)p;
#define SYMB(var, sym) cudaGetSymbolAddress(&p, sym); bf16* var = (bf16*)p;
    SYMF(enc,   g_enc);    SYMF(feats, g_feats);  SYMF(tmp,   g_tmp);
    SYMF(x1,    g_x1);     SYMF(xq,    g_xq);     SYMF(xk,    g_xk);
    SYMF(xv,    g_xv);     SYMF(att,   g_att);
    SYMF(ih,    g_ih);     SYMF(hh,    g_hh);
    SYMF(cbuf,  g_c);      SYMF(hs1,   g_hs1);
    SYMF(hf,    g_hf);     SYMF(tf,    g_tf);
    SYMF(qb,    g_q);      SYMF(ccand, g_ccand);
    SYMF(kb,    g_k);      SYMF(vb,    g_v);
    SYMF(pinfo, g_pinfo);  SYMF(pp,    g_pp);     SYMF(hid,   g_hid);
    SYMB(ah,  g_ah);  SYMB(al,  g_al);
    SYMB(sh,  g_sh);  SYMB(sl,  g_sl);
    SYMB(hch, g_hch); SYMB(hcl, g_hcl);
    SYMB(q2h, g_q2h); SYMB(q2l, g_q2l);
    SYMB(bkh, g_bkh); SYMB(bkl, g_bkl);
    SYMB(w1h, g_w1h); SYMB(w1l, g_w1l);
    SYMB(w2h, g_w2h); SYMB(w2l, g_w2l);
    SYMB(w3h, g_w3h); SYMB(w3l, g_w3l);
    SYMB(w4h, g_w4h); SYMB(w4l, g_w4l);
    SYMB(mwh, g_mwh); SYMB(mwl, g_mwl);
    SYMB(owh, g_owh); SYMB(owl, g_owl);
    SYMB(wph, g_wph); SYMB(wpl, g_wpl);
    cudaGetSymbolAddress(&p, g_validany); int* validany = (int*)p;
    cudaGetSymbolAddress(&p, g_cnt);      int* cntdev = (int*)p;
#undef SYMF
#undef SYMB

    // ---- persistent side stream + events (created once; deterministic) ----
    static cudaStream_t s2 = nullptr;
    static cudaEvent_t evFork = nullptr, evW0 = nullptr, evW1 = nullptr,
                       evFeats = nullptr, evSide = nullptr;
    if (!s2) {
        cudaStreamCreateWithFlags(&s2, cudaStreamNonBlocking);
        cudaEventCreateWithFlags(&evFork,  cudaEventDisableTiming);
        cudaEventCreateWithFlags(&evW0,    cudaEventDisableTiming);
        cudaEventCreateWithFlags(&evW1,    cudaEventDisableTiming);
        cudaEventCreateWithFlags(&evFeats, cudaEventDisableTiming);
        cudaEventCreateWithFlags(&evSide,  cudaEventDisableTiming);
    }

    const size_t W4 = (size_t)BANK4q * BANKq;

    // ======== FORK: side stream does all weight prep ========
    cudaEventRecord(evFork, 0);
    cudaStreamWaitEvent(s2, evFork, 0);

    split(lstm_Wih,      w1h, w1l, W4, s2);
    split(lstm_Whh,      w2h, w2l, W4, s2);
    cudaEventRecord(evW0, s2);
    split(lstm_Wih + W4, w3h, w3l, W4, s2);
    split(lstm_Whh + W4, w4h, w4l, W4, s2);
    cudaEventRecord(evW1, s2);
    split(mha_inW,  mwh, mwl, (size_t)3 * BANKq * BANKq, s2);
    split(mha_outW, owh, owl, (size_t)BANKq * BANKq, s2);
    {
        dim3 grid((BANK5q + 31) / 32, (BANK5q + 31) / 32);
        transpose_split_kernel<<<grid, dim3(32, 8), 0, s2>>>(pred_W, wph, wpl, BANK5q, BANK5q);
    }

    // ======== main stream: perm + enc + GCN ========
    build_perm_kernel<<<1, 1024>>>(path_lens);
    build_enc_kernel<<<Bq * Sq, 256>>>(encoder_outputs, entity_type, entity_id, type_emb, id_emb, enc);

    gemm(false, sub2words, enc, nullptr, nullptr, feats,
         Nq, D0q, Sq, Sq, D0q, BANKq, 0,
         (long)Nq * Sq, (long)Sq * D0q, (long)Nq * BANKq, 0, Bq, 1.f, 0);
    gemm(false, adj, feats, nullptr, nullptr, tmp,
         Nq, D0q, Nq, Nq, BANKq, D0q, 0,
         (long)Nq * Nq, (long)Nq * BANKq, (long)Nq * D0q, 0, Bq, 1.f, 0);
    gemm(false, tmp, gcn0_W, gcn0_b, nullptr, feats + 808,
         Nq, Gq, D0q, D0q, Gq, BANKq, 0,
         (long)Nq * D0q, 0, (long)Nq * BANKq, 0, Bq, 1.f, 0);

    int xoff[NLq]   = {808, 1064};
    int outoff[NLq] = {1064, 1320};
    for (int l = 0; l < NLq; l++) {
        const float* x = feats + xoff[l];
        gemm(false, adj, x, nullptr, nullptr, tmp,
             Nq, Gq, Nq, Nq, BANKq, Gq, 0,
             (long)Nq * Nq, (long)Nq * BANKq, (long)Nq * Gq, 0, Bq, 1.f, 0);
        gemm(false, tmp, gcn_W + (long)l * Gq * Gq, gcn_b + l * Gq, nullptr, x1,
             Nq, Gq, Gq, Gq, Gq, Gq, 0,
             (long)Nq * Gq, 0, (long)Nq * Gq, 0, Bq, 1.f, 1);
        gemm(false, x, attn_Wq + (long)l * Gq * Gq, nullptr, nullptr, xq,
             Nq, Gq, Gq, BANKq, Gq, Gq, 0,
             (long)Nq * BANKq, 0, (long)Nq * Gq, 0, Bq, 1.f, 0);
        gemm(false, x1, attn_Wk + (long)l * Gq * Gq, nullptr, nullptr, xk,
             Nq, Gq, Gq, Gq, Gq, Gq, 0,
             (long)Nq * Gq, 0, (long)Nq * Gq, 0, Bq, 1.f, 0);
        gemm(false, x1, attn_Wv + (long)l * Gq * Gq, nullptr, nullptr, xv,
             Nq, Gq, Gq, Gq, Gq, Gq, 0,
             (long)Nq * Gq, 0, (long)Nq * Gq, 0, Bq, 1.f, 0);
        gemm(true, xq, xk, nullptr, nullptr, att,
             Nq, Nq, Gq, Gq, Gq, Nq, 0,
             (long)Nq * Gq, (long)Nq * Gq, (long)Nq * Nq, 0, Bq, 0.0625f, 0);
        softmax256_kernel<<<Bq * Nq, 256>>>(att);
        gemm(false, att, xv, nullptr, x1, feats + outoff[l],
             Nq, Gq, Nq, Nq, Gq, BANKq, Gq,
             (long)Nq * Nq, (long)Nq * Gq, (long)Nq * BANKq, (long)Nq * Gq, Bq, 1.f, 1);
    }
    cudaEventRecord(evFeats, 0);

    // ======== side stream (after feats ready): q-branch + bank partials ========
    cudaStreamWaitEvent(s2, evFeats, 0);
    gather_ht_kernel<<<BPq, 256, 0, s2>>>(feats, h_t_pairs, hf, tf, q2h, q2l);
    gemm_bf16(q2h, q2l, mwh, mwl, mha_inb, qb, BPq, BANKq, BANKq, 0, nullptr, 0, 0, s2);
    bank_split_kernel<<<NBANKROWS, 256, 0, s2>>>(feats, bkh, bkl);
    float* p1 = pp;
    float* p2 = pp + (size_t)NBANKROWS * BANK5q;
    gemm_bf16(bkh, bkl, wph, wpl, nullptr, p1,
              NBANKROWS, BANK5q, BANKq, 0, nullptr, BANKq, BANK5q, s2);
    gemm_bf16(bkh, bkl, wph + BANKq, wpl + BANKq, nullptr, p2,
              NBANKROWS, BANK5q, BANKq, 0, nullptr, BANKq, BANK5q, s2);
    cudaEventRecord(evSide, s2);

    // ======== main stream: LSTM ========
    dim3 cg((BANKq + 255) / 256, Mlstm);
    dim3 cg1((BANKq + 255) / 256, BPq);

    cudaStreamWaitEvent(0, evW0, 0);
    // ----- layer 0 (prefix dedup + length compaction) -----
    {
        const float* b0 = lstm_b;
        split(feats, sh, sl, (size_t)Bq * Nq * BANKq);
        gemm_bf16(sh, sl, w1h, w1l, b0, hh, BPq, BANK4q, BANKq, 0);
        gather_ih_l0_kernel<<<3 * Mlstm, 256>>>(hh, path_nodes, ih);
        cand_cell_kernel<<<cg1, 256>>>(hh, ccand, hch, hcl);
        gather0_kernel<<<Mlstm, 256>>>(hch, hcl, ccand, path_nodes, sh, sl, cbuf, ah, al, nullptr);
        gemm_bf16(hch, hcl, w2h, w2l, nullptr, hid, BPq, BANK4q, BANKq, 0);
        gather_w64_kernel<<<Mlstm, 256>>>(hid, path_nodes, hh, 1);
        for (int t = 1; t < Lq; t++) {
            if (t > 1)
                gemm_bf16(sh, sl, w2h, w2l, nullptr, hh, Mlstm, BANK4q, BANKq, 0, cntdev + t);
            lstm_cell_kernel<<<cg, 256>>>(ih, hh, sh, sl, ah, al, cbuf, nullptr, t);
        }
    }

    cudaStreamWaitEvent(0, evW1, 0);
    // ----- layer 1 (same dedup + compaction) -----
    {
        const float* b1 = lstm_b + BANK4q;
        gemm_bf16(hch, hcl, w3h, w3l, b1, hid, BPq, BANK4q, BANKq, 0);
        for (int t = 1; t < Lq; t++)
            gemm_bf16(ah + (size_t)t * Mlstm * BANKq, al + (size_t)t * Mlstm * BANKq,
                      w3h, w3l, b1, ih + (size_t)t * Mlstm * BANK4q,
                      Mlstm, BANK4q, BANKq, 0, cntdev + t);
        cand_cell_kernel<<<cg1, 256>>>(hid, ccand, hch, hcl);
        gather0_kernel<<<Mlstm, 256>>>(hch, hcl, ccand, path_nodes, sh, sl, cbuf,
                                       nullptr, nullptr, hs1);
        gemm_bf16(hch, hcl, w4h, w4l, nullptr, hid, BPq, BANK4q, BANKq, 0);
        gather_w64_kernel<<<Mlstm, 256>>>(hid, path_nodes, hh, 1);
        for (int t = 1; t < Lq; t++) {
            if (t > 1)
                gemm_bf16(sh, sl, w4h, w4l, nullptr, hh, Mlstm, BANK4q, BANKq, 0, cntdev + t);
            lstm_cell_kernel<<<cg, 256>>>(ih, hh, sh, sl, nullptr, nullptr, cbuf, hs1, t);
        }
    }

    // 8) masked max-pool -> pe in COMPACTED order (split bf16 into ah/al)
    maxpool_split_kernel<<<cg, 256>>>(hs1, path_lens, ah, al);

    // ======== JOIN side stream ========
    cudaStreamWaitEvent(0, evSide, 0);

    // 10-11) k/v projections (compacted + count-limited; tail rows zeroed)
    gemm_bf16(ah, al, mwh + (size_t)BANKq * BANKq, mwl + (size_t)BANKq * BANKq,
              mha_inb + BANKq, kb, Mlstm, BANKq, BANKq, 0, cntdev + 0);
    gemm_bf16(ah, al, mwh + 2 * (size_t)BANKq * BANKq, mwl + 2 * (size_t)BANKq * BANKq,
              mha_inb + 2 * BANKq, vb, Mlstm, BANKq, BANKq, 0, cntdev + 0);
    zero_kv_tail_kernel<<<Mlstm, 256>>>(kb, vb);

    // 12) tiny attention over K=3 paths (ctx split into sh/sl)
    mha_attn_kernel<<<BPq, 384>>>(qb, kb, vb, path_lens, rel_mask, sh, sl, validany);

    // 13) pinfo
    gemm_bf16(sh, sl, owh, owl, mha_outb, pinfo, BPq, BANKq, BANKq, 0);

    // 14-15) pred GEMM with segment dedup (partials from side stream)
    build_of_rest_kernel<<<BPq, 256>>>(hf, tf, pinfo, validany, ah, al);
    gemm_bf16(ah, al, wph + 2 * BANKq, wpl + 2 * BANKq, pred_b, hid,
              BPq, BANK5q, BANK3q, 0, nullptr, BANK3q, BANK5q);
    combine_pred_kernel<<<BPq, 256>>>(hid, p1, p2, h_t_pairs);

    // 16) output heads
    gemm(false, hid, mW, mb, nullptr, out,
         BPq, Rq, BANK5q, BANK5q, Rq, Rq, 0, 0, 0, 0, 0, 1, 1.f, 0);
    head2_kernel<<<BPq, 256>>>(hid, bW, bb, out + (size_t)BPq * Rq);
}